// round 1
// baseline (speedup 1.0000x reference)
#include <cuda_runtime.h>
#include <cuda_bf16.h>
#include <math.h>

// ---------------------------------------------------------------------------
// Problem constants
// ---------------------------------------------------------------------------
#define BATCH   32
#define CIN     512
#define COUT    512
#define HEADS   8
#define DH      64          // head dim
#define IH      32
#define IW      32
#define S       1024        // IH*IW queries
#define NKV     320         // pooled kv length: 32 + 32 + 256
#define QKVC    1536        // 3*CIN

// Scratch (device globals: no allocation allowed)
__device__ float g_qkv[(size_t)BATCH * QKVC * S];        // [B,1536,1024]  192 MB
__device__ float g_k  [(size_t)BATCH * HEADS * DH * NKV]; // [B,8,64,320]   21 MB
__device__ float g_v  [(size_t)BATCH * HEADS * DH * NKV];
__device__ float g_att[(size_t)BATCH * CIN * S];          // [B,512,1024]   67 MB

// ---------------------------------------------------------------------------
// Batched SGEMM: C[b] = A @ B[b] (+bias).  A:[M,K] row-major (shared),
// B:[K,N] per batch, C:[M,N] per batch.  BM=BN=128, BK=16, 256 thr, 8x8 micro.
// M%128==0, N%128==0, K%16==0 guaranteed by problem sizes.
// ---------------------------------------------------------------------------
__global__ void __launch_bounds__(256) sgemm_kernel(
    const float* __restrict__ A, const float* __restrict__ B,
    float* __restrict__ C, const float* __restrict__ bias,
    int M, int N, int K)
{
    __shared__ float As[16][128];   // [k][m]
    __shared__ float Bs[16][128];   // [k][n]

    const int n0 = blockIdx.x * 128;
    const int m0 = blockIdx.y * 128;
    const size_t bo = (size_t)blockIdx.z * K * N;
    const size_t co = (size_t)blockIdx.z * M * N;

    const int tid = threadIdx.x;
    const int ty = tid >> 4;     // 0..15
    const int tx = tid & 15;     // 0..15

    // A-load mapping: row = tid>>1 (0..127), kc = (tid&1)*8
    const int ar  = tid >> 1;
    const int akc = (tid & 1) * 8;

    float acc[8][8];
#pragma unroll
    for (int i = 0; i < 8; i++)
#pragma unroll
        for (int j = 0; j < 8; j++) acc[i][j] = 0.f;

    for (int k0 = 0; k0 < K; k0 += 16) {
        // Load A tile (128x16) transposed into As
        const float* ap = &A[(size_t)(m0 + ar) * K + k0 + akc];
        float4 a0 = *(const float4*)(ap);
        float4 a1 = *(const float4*)(ap + 4);
        As[akc + 0][ar] = a0.x; As[akc + 1][ar] = a0.y;
        As[akc + 2][ar] = a0.z; As[akc + 3][ar] = a0.w;
        As[akc + 4][ar] = a1.x; As[akc + 5][ar] = a1.y;
        As[akc + 6][ar] = a1.z; As[akc + 7][ar] = a1.w;
        // Load B tile (16x128)
        const float* bp = &B[bo + (size_t)(k0 + ty) * N + n0 + tx * 8];
        *(float4*)&Bs[ty][tx * 8]     = *(const float4*)(bp);
        *(float4*)&Bs[ty][tx * 8 + 4] = *(const float4*)(bp + 4);
        __syncthreads();

#pragma unroll
        for (int kk = 0; kk < 16; kk++) {
            float a[8], bb[8];
            *(float4*)(a)     = *(const float4*)&As[kk][ty * 8];
            *(float4*)(a + 4) = *(const float4*)&As[kk][ty * 8 + 4];
            *(float4*)(bb)     = *(const float4*)&Bs[kk][tx * 8];
            *(float4*)(bb + 4) = *(const float4*)&Bs[kk][tx * 8 + 4];
#pragma unroll
            for (int i = 0; i < 8; i++)
#pragma unroll
                for (int j = 0; j < 8; j++)
                    acc[i][j] = fmaf(a[i], bb[j], acc[i][j]);
        }
        __syncthreads();
    }

#pragma unroll
    for (int i = 0; i < 8; i++) {
        const int m = m0 + ty * 8 + i;
        const float bv = bias ? bias[m] : 0.f;
        float* cp = &C[co + (size_t)m * N + n0 + tx * 8];
        float4 r0 = make_float4(acc[i][0] + bv, acc[i][1] + bv,
                                acc[i][2] + bv, acc[i][3] + bv);
        float4 r1 = make_float4(acc[i][4] + bv, acc[i][5] + bv,
                                acc[i][6] + bv, acc[i][7] + bv);
        *(float4*)(cp)     = r0;
        *(float4*)(cp + 4) = r1;
    }
}

// ---------------------------------------------------------------------------
// Pool + sigmoid gate.  For each (b, c) channel of k (or v) part of qkv:
//   n 0..31  : mean over width  (per h)
//   n 32..63 : mean over height (per w)
//   n 64..319: 2x2 average pool
// Output layout [B, HEADS, DH, NKV] (n contiguous).
// grid: (B*CIN, 2), 256 threads.
// ---------------------------------------------------------------------------
__device__ __forceinline__ float sigmoidf_(float x) {
    return 1.f / (1.f + __expf(-x));
}

__global__ void __launch_bounds__(256) pool_kernel(
    const float* __restrict__ qkv, float* __restrict__ kp, float* __restrict__ vp)
{
    const int bc = blockIdx.x;
    const int b = bc >> 9;        // /512
    const int c = bc & 511;
    const int part = blockIdx.y;  // 0 = k, 1 = v
    const float* src = qkv + ((size_t)b * QKVC + 512 + part * 512 + c) * S;
    float* dstbase = part ? vp : kp;
    float* dst = dstbase + ((size_t)(b * HEADS + (c >> 6)) * DH + (c & 63)) * NKV;

    __shared__ float ts[S];
    const int tid = threadIdx.x;
    ((float4*)ts)[tid] = ((const float4*)src)[tid];
    __syncthreads();

    if (tid < 32) {                 // mean over width: n = h
        float s = 0.f;
#pragma unroll
        for (int w = 0; w < 32; w++) s += ts[tid * 32 + w];
        dst[tid] = sigmoidf_(s * (1.f / 32.f));
    } else if (tid < 64) {          // mean over height: n = 32 + w
        const int w = tid - 32;
        float s = 0.f;
#pragma unroll
        for (int hh = 0; hh < 32; hh++) s += ts[hh * 32 + w];
        dst[tid] = sigmoidf_(s * (1.f / 32.f));
    }
    // 2x2 avg pool: n = 64 + tid  (256 values, all threads)
    {
        const int ph = tid >> 4, pw = tid & 15;
        const float s = ts[(2 * ph) * 32 + 2 * pw] + ts[(2 * ph) * 32 + 2 * pw + 1]
                      + ts[(2 * ph + 1) * 32 + 2 * pw] + ts[(2 * ph + 1) * 32 + 2 * pw + 1];
        dst[64 + tid] = sigmoidf_(s * 0.25f);
    }
}

// ---------------------------------------------------------------------------
// Fused attention: per CTA = (b, h, block of 64 queries).
// smem: q[64][65], kv[320][65] (k then reused for v), scores[64][321].
// dots = (q*scale) @ k^T + pos ; softmax over n ; out = attn @ v.
// Output written to g_att as [B, C, S] (c = h*64+dd).
// ---------------------------------------------------------------------------
#define TS 64
#define KST 65
#define SST 321
#define ATTN_SMEM ((TS*KST + NKV*KST + TS*SST) * 4)

__global__ void __launch_bounds__(256, 1) attn_kernel(
    const float* __restrict__ qkv,   // [B,1536,1024]
    const float* __restrict__ kp,    // [B,8,64,320]
    const float* __restrict__ vp,    // [B,8,64,320]
    const float* __restrict__ pos,   // [1024,320]
    float* __restrict__ outp)        // [B,512,1024]
{
    extern __shared__ float sm[];
    float* qs = sm;                     // 64*65
    float* kv = sm + TS * KST;          // 320*65
    float* sc = kv + NKV * KST;         // 64*321

    const int b = blockIdx.z, h = blockIdx.y;
    const int s0 = blockIdx.x * TS;
    const int tid = threadIdx.x;
    const float scale = 0.125f;         // d^-0.5, d=64

    // ---- load q (pre-scaled), transposed to qs[si][dd] ----
    const float* qg = qkv + ((size_t)b * QKVC + h * DH) * S + s0;
    for (int idx = tid; idx < TS * DH; idx += 256) {
        const int dd = idx >> 6, si = idx & 63;
        qs[si * KST + dd] = qg[(size_t)dd * S + si] * scale;
    }
    // ---- load k: global [dd][n] -> smem kv[n][dd] ----
    const float* kg = kp + (size_t)(b * HEADS + h) * DH * NKV;
    for (int i4 = tid; i4 < DH * NKV / 4; i4 += 256) {
        const float4 d = ((const float4*)kg)[i4];
        const int lin = i4 * 4;
        const int dd = lin / NKV;
        const int n  = lin - dd * NKV;   // NKV%4==0 -> 4 elems share dd
        kv[(n    ) * KST + dd] = d.x;
        kv[(n + 1) * KST + dd] = d.y;
        kv[(n + 2) * KST + dd] = d.z;
        kv[(n + 3) * KST + dd] = d.w;
    }
    __syncthreads();

    // ---- QK^T + pos -> scores ----
    {
        const int ng = tid & 31;        // n group (n = ng + 32j)
        const int sg = tid >> 5;        // si group (si = sg*8 + i)
        const int sbase = sg * 8;
        float acc[8][10];
#pragma unroll
        for (int i = 0; i < 8; i++)
#pragma unroll
            for (int j = 0; j < 10; j++) acc[i][j] = 0.f;

#pragma unroll 4
        for (int dd = 0; dd < DH; dd++) {
            float qv[8];
#pragma unroll
            for (int i = 0; i < 8; i++) qv[i] = qs[(sbase + i) * KST + dd];
#pragma unroll
            for (int j = 0; j < 10; j++) {
                const float kval = kv[(ng + 32 * j) * KST + dd];
#pragma unroll
                for (int i = 0; i < 8; i++)
                    acc[i][j] = fmaf(qv[i], kval, acc[i][j]);
            }
        }
        const float* pr = pos + (size_t)(s0 + sbase) * NKV + ng;
#pragma unroll
        for (int i = 0; i < 8; i++)
#pragma unroll
            for (int j = 0; j < 10; j++)
                sc[(sbase + i) * SST + ng + 32 * j] =
                    acc[i][j] + pr[(size_t)i * NKV + 32 * j];
    }
    __syncthreads();

    // ---- load v into kv buffer (k no longer needed) ----
    const float* vg = vp + (size_t)(b * HEADS + h) * DH * NKV;
    for (int i4 = tid; i4 < DH * NKV / 4; i4 += 256) {
        const float4 d = ((const float4*)vg)[i4];
        const int lin = i4 * 4;
        const int dd = lin / NKV;
        const int n  = lin - dd * NKV;
        kv[(n    ) * KST + dd] = d.x;
        kv[(n + 1) * KST + dd] = d.y;
        kv[(n + 2) * KST + dd] = d.z;
        kv[(n + 3) * KST + dd] = d.w;
    }

    // ---- softmax over n (4 threads per row) ----
    {
        const int r = tid >> 2, cq = tid & 3;
        float* row = sc + r * SST;
        float m = -1e30f;
        for (int k = cq; k < NKV; k += 4) m = fmaxf(m, row[k]);
        m = fmaxf(m, __shfl_xor_sync(0xffffffffu, m, 1));
        m = fmaxf(m, __shfl_xor_sync(0xffffffffu, m, 2));
        float ssum = 0.f;
        for (int k = cq; k < NKV; k += 4) {
            const float e = __expf(row[k] - m);
            row[k] = e;
            ssum += e;
        }
        ssum += __shfl_xor_sync(0xffffffffu, ssum, 1);
        ssum += __shfl_xor_sync(0xffffffffu, ssum, 2);
        const float inv = 1.f / ssum;
        for (int k = cq; k < NKV; k += 4) row[k] *= inv;
    }
    __syncthreads();

    // ---- AV: out[si][dd] = sum_n p[si][n] * v[n][dd] ----
    {
        const int ty = tid >> 4, tx = tid & 15;   // si = ty+16i, dd = tx+16j
        float acc[4][4];
#pragma unroll
        for (int i = 0; i < 4; i++)
#pragma unroll
            for (int j = 0; j < 4; j++) acc[i][j] = 0.f;

#pragma unroll 4
        for (int n = 0; n < NKV; n++) {
            float p[4], vv[4];
#pragma unroll
            for (int i = 0; i < 4; i++) p[i] = sc[(ty + 16 * i) * SST + n];
#pragma unroll
            for (int j = 0; j < 4; j++) vv[j] = kv[n * KST + tx + 16 * j];
#pragma unroll
            for (int i = 0; i < 4; i++)
#pragma unroll
                for (int j = 0; j < 4; j++)
                    acc[i][j] = fmaf(p[i], vv[j], acc[i][j]);
        }

        // stage transposed into qs region (free now): outT[dd][si]
#pragma unroll
        for (int i = 0; i < 4; i++)
#pragma unroll
            for (int j = 0; j < 4; j++)
                qs[(tx + 16 * j) * KST + (ty + 16 * i)] = acc[i][j];
    }
    __syncthreads();

    // ---- coalesced global write: g_att[b][h*64+dd][s0+si] ----
    float* og = outp + ((size_t)b * CIN + h * DH) * S + s0;
    for (int idx = tid; idx < DH * TS; idx += 256) {
        const int dd = idx >> 6, si = idx & 63;
        og[(size_t)dd * S + si] = qs[dd * KST + si];
    }
}

// ---------------------------------------------------------------------------
// Launch
// ---------------------------------------------------------------------------
extern "C" void kernel_launch(void* const* d_in, const int* in_sizes, int n_in,
                              void* d_out, int out_size)
{
    const float* x     = (const float*)d_in[0];   // [32,512,32,32]
    const float* Wqkv  = (const float*)d_in[1];   // [1536,512]
    const float* Wout  = (const float*)d_in[2];   // [512,512]
    const float* bout  = (const float*)d_in[3];   // [512]
    const float* pos   = (const float*)d_in[4];   // [1,1024,320]
    float* out = (float*)d_out;                   // [32,512,32,32]

    float *p_qkv, *p_k, *p_v, *p_att;
    cudaGetSymbolAddress((void**)&p_qkv, g_qkv);
    cudaGetSymbolAddress((void**)&p_k,   g_k);
    cudaGetSymbolAddress((void**)&p_v,   g_v);
    cudaGetSymbolAddress((void**)&p_att, g_att);

    // 1) qkv = Wqkv @ x   (per batch [1536,512]@[512,1024])
    dim3 g1(S / 128, QKVC / 128, BATCH);
    sgemm_kernel<<<g1, 256>>>(Wqkv, x, p_qkv, nullptr, QKVC, S, CIN);

    // 2) pool + sigmoid gates for k and v
    pool_kernel<<<dim3(BATCH * CIN, 2), 256>>>(p_qkv, p_k, p_v);

    // 3) fused attention
    cudaFuncSetAttribute(attn_kernel, cudaFuncAttributeMaxDynamicSharedMemorySize,
                         ATTN_SMEM);
    attn_kernel<<<dim3(S / TS, HEADS, BATCH), 256, ATTN_SMEM>>>(
        p_qkv, p_k, p_v, pos, p_att);

    // 4) out = Wout @ att + bout
    dim3 g2(S / 128, COUT / 128, BATCH);
    sgemm_kernel<<<g2, 256>>>(Wout, p_att, out, bout, COUT, S, CIN);
}

// round 3
// speedup vs baseline: 1.2985x; 1.2985x over previous
#include <cuda_runtime.h>
#include <cuda_bf16.h>
#include <math.h>
#include <stdint.h>

// ---------------------------------------------------------------------------
// Problem constants
// ---------------------------------------------------------------------------
#define BATCH   32
#define CIN     512
#define COUT    512
#define HEADS   8
#define DH      64
#define S       1024
#define NKV     320
#define QKVC    1536
#define KDIM    512

// ---------------------------------------------------------------------------
// Scratch (device globals)
// ---------------------------------------------------------------------------
__device__ float g_qkv[(size_t)BATCH * QKVC * S];                    // [B,1536,1024]
__device__ __align__(16) __nv_bfloat16 g_xh [(size_t)BATCH * S * KDIM];  // xT hi [B,1024,512]
__device__ __align__(16) __nv_bfloat16 g_xl [(size_t)BATCH * S * KDIM];
__device__ float g_k  [(size_t)BATCH * HEADS * DH * NKV];
__device__ float g_v  [(size_t)BATCH * HEADS * DH * NKV];
__device__ __align__(16) __nv_bfloat16 g_ath[(size_t)BATCH * S * CIN];   // att hi [B,1024,512]
__device__ __align__(16) __nv_bfloat16 g_atl[(size_t)BATCH * S * CIN];
__device__ __align__(16) __nv_bfloat16 g_wqh[(size_t)QKVC * KDIM];
__device__ __align__(16) __nv_bfloat16 g_wql[(size_t)QKVC * KDIM];
__device__ __align__(16) __nv_bfloat16 g_woh[(size_t)COUT * KDIM];
__device__ __align__(16) __nv_bfloat16 g_wol[(size_t)COUT * KDIM];

// ---------------------------------------------------------------------------
// PTX helpers (base compute_103-safe: mma.sync / ldmatrix / cp.async only)
// ---------------------------------------------------------------------------
__device__ __forceinline__ uint32_t smem_u32(const void* p) {
    uint32_t a;
    asm("{ .reg .u64 t; cvta.to.shared.u64 t, %1; cvt.u32.u64 %0, t; }"
        : "=r"(a) : "l"(p));
    return a;
}
__device__ __forceinline__ void cpasync16(uint32_t s, const void* g) {
    asm volatile("cp.async.cg.shared.global [%0], [%1], 16;" :: "r"(s), "l"(g));
}
#define CP_COMMIT() asm volatile("cp.async.commit_group;" ::: "memory")
#define CP_WAIT(N)  asm volatile("cp.async.wait_group %0;" :: "n"(N) : "memory")

#define LDSM_X4(r, addr) \
    asm volatile("ldmatrix.sync.aligned.m8n8.x4.shared.b16 {%0,%1,%2,%3}, [%4];" \
                 : "=r"((r)[0]), "=r"((r)[1]), "=r"((r)[2]), "=r"((r)[3]) : "r"(addr))

__device__ __forceinline__ void mma_bf16(float* d, const uint32_t* a,
                                         uint32_t b0, uint32_t b1) {
    asm volatile(
        "mma.sync.aligned.m16n8k16.row.col.f32.bf16.bf16.f32 "
        "{%0,%1,%2,%3}, {%4,%5,%6,%7}, {%8,%9}, {%0,%1,%2,%3};"
        : "+f"(d[0]), "+f"(d[1]), "+f"(d[2]), "+f"(d[3])
        : "r"(a[0]), "r"(a[1]), "r"(a[2]), "r"(a[3]), "r"(b0), "r"(b1));
}

// ---------------------------------------------------------------------------
// fp32 -> bf16 hi/lo split
// ---------------------------------------------------------------------------
__global__ void split_kernel(const float* __restrict__ a,
                             __nv_bfloat16* __restrict__ h,
                             __nv_bfloat16* __restrict__ l, int n)
{
    int i = blockIdx.x * 256 + threadIdx.x;
    if (i < n) {
        float v = a[i];
        __nv_bfloat16 hi = __float2bfloat16_rn(v);
        h[i] = hi;
        l[i] = __float2bfloat16_rn(v - __bfloat162float(hi));
    }
}

// Transpose + split: x[B,512,1024] -> xT hi/lo [B,1024,512] (bf16)
__global__ void __launch_bounds__(256) tsplit_kernel(
    const float* __restrict__ x,
    __nv_bfloat16* __restrict__ oh, __nv_bfloat16* __restrict__ ol)
{
    __shared__ float t[32][33];
    const int n0 = blockIdx.x * 32, k0 = blockIdx.y * 32, b = blockIdx.z;
    const int tx = threadIdx.x, ty = threadIdx.y;
    const float* src = x + ((size_t)b * KDIM + k0) * S + n0;
#pragma unroll
    for (int i = 0; i < 4; i++)
        t[ty + 8 * i][tx] = src[(size_t)(ty + 8 * i) * S + tx];
    __syncthreads();
    __nv_bfloat16* dh = oh + ((size_t)b * S + n0) * KDIM + k0;
    __nv_bfloat16* dl = ol + ((size_t)b * S + n0) * KDIM + k0;
#pragma unroll
    for (int i = 0; i < 4; i++) {
        float v = t[tx][ty + 8 * i];
        __nv_bfloat16 hi = __float2bfloat16_rn(v);
        dh[(size_t)(ty + 8 * i) * KDIM + tx] = hi;
        dl[(size_t)(ty + 8 * i) * KDIM + tx] =
            __float2bfloat16_rn(v - __bfloat162float(hi));
    }
}

// ---------------------------------------------------------------------------
// HMMA bf16 3x-split batched GEMM.
// C[b][M,Ntot] = A[M,512] @ B[b][Ntot,512]^T (+bias), fp32 accumulate.
// CTA tile 128x128, 8 warps (warp tile 32x64), K chunks of 16,
// 4-stage cp.async pipeline.  grid = (Ntot/128, M/128, BATCH).
// ---------------------------------------------------------------------------
#define NCH     32                 // 512/16 k-chunks
#define STG_SZ  24576              // per stage: 4 tiles x 128 rows x 48B
#define T_AL    6144
#define T_BH    12288
#define T_BL    18432
#define GSMEM   (4 * STG_SZ)       // 98304 B

__global__ void __launch_bounds__(256) gemm_mma_kernel(
    const __nv_bfloat16* __restrict__ Ah, const __nv_bfloat16* __restrict__ Al,
    const __nv_bfloat16* __restrict__ Bh, const __nv_bfloat16* __restrict__ Bl,
    float* __restrict__ C, const float* __restrict__ bias, int Ntot)
{
    extern __shared__ char smem[];
    const uint32_t sbase = smem_u32(smem);

    const int tid = threadIdx.x;
    const int n0 = blockIdx.x * 128;
    const int m0 = blockIdx.y * 128;
    const int M  = gridDim.y * 128;
    const size_t bo = (size_t)blockIdx.z * Ntot * KDIM;
    const size_t co = (size_t)blockIdx.z * M * Ntot;

    const __nv_bfloat16* Bhb = Bh + bo;
    const __nv_bfloat16* Blb = Bl + bo;

    // loader mapping: 256 threads, 128 rows x 2 halves of 16B
    const int lrow = tid >> 1, lhalf = tid & 1;
    const uint32_t lso = (uint32_t)(lrow * 48 + lhalf * 16);

    // warp mapping
    const int wid = tid >> 5, lane = tid & 31;
    const int wm = (wid & 3) * 32, wn = (wid >> 2) * 64;
    const uint32_t aoff = (uint32_t)((wm + (lane & 15)) * 48 + (lane >> 4) * 16);
    const uint32_t boff = (uint32_t)(T_BH + (wn + (lane & 15)) * 48 + (lane >> 4) * 16);

    float acc[2][8][4];
#pragma unroll
    for (int f = 0; f < 2; f++)
#pragma unroll
        for (int j = 0; j < 8; j++)
#pragma unroll
            for (int r = 0; r < 4; r++) acc[f][j][r] = 0.f;

    // ---- issue helper (macro to keep asm simple) ----
#define ISSUE(cc, st) do {                                                    \
        const size_t ga = (size_t)(m0 + lrow) * KDIM + (cc) * 16 + lhalf * 8; \
        const size_t gb = (size_t)(n0 + lrow) * KDIM + (cc) * 16 + lhalf * 8; \
        const uint32_t sb = sbase + (st) * STG_SZ + lso;                      \
        cpasync16(sb,         Ah  + ga);                                      \
        cpasync16(sb + T_AL,  Al  + ga);                                      \
        cpasync16(sb + T_BH,  Bhb + gb);                                      \
        cpasync16(sb + T_BL,  Blb + gb);                                      \
    } while (0)

    // prologue: stages 0..2
    ISSUE(0, 0); CP_COMMIT();
    ISSUE(1, 1); CP_COMMIT();
    ISSUE(2, 2); CP_COMMIT();

    for (int c = 0; c < NCH; c++) {
        if (c + 3 < NCH) ISSUE(c + 3, (c + 3) & 3);
        CP_COMMIT();          // empty group at tail keeps wait count uniform
        CP_WAIT(3);           // chunk c complete
        __syncthreads();

        const uint32_t sa = sbase + (uint32_t)((c & 3) * STG_SZ);
        uint32_t ah[2][4], al[2][4];
        LDSM_X4(ah[0], sa + aoff);
        LDSM_X4(ah[1], sa + aoff + 768);
        LDSM_X4(al[0], sa + aoff + T_AL);
        LDSM_X4(al[1], sa + aoff + T_AL + 768);
#pragma unroll
        for (int g = 0; g < 4; g++) {
            uint32_t bh[4], bl[4];
            LDSM_X4(bh, sa + boff + g * 768);
            LDSM_X4(bl, sa + boff + g * 768 + T_AL);   // BL = BH + 6144
#pragma unroll
            for (int f = 0; f < 2; f++) {
                mma_bf16(acc[f][2 * g],     ah[f], bh[0], bh[2]);
                mma_bf16(acc[f][2 * g],     al[f], bh[0], bh[2]);
                mma_bf16(acc[f][2 * g],     ah[f], bl[0], bl[2]);
                mma_bf16(acc[f][2 * g + 1], ah[f], bh[1], bh[3]);
                mma_bf16(acc[f][2 * g + 1], al[f], bh[1], bh[3]);
                mma_bf16(acc[f][2 * g + 1], ah[f], bl[1], bl[3]);
            }
        }
        __syncthreads();
    }
#undef ISSUE

    // ---- epilogue: direct fp32 stores ----
#pragma unroll
    for (int f = 0; f < 2; f++) {
        const int r0 = m0 + wm + f * 16 + (lane >> 2);
        const float bv0 = bias ? bias[r0] : 0.f;
        const float bv1 = bias ? bias[r0 + 8] : 0.f;
        float* cp0 = C + co + (size_t)r0 * Ntot;
        float* cp1 = cp0 + (size_t)8 * Ntot;
#pragma unroll
        for (int j = 0; j < 8; j++) {
            const int col = n0 + wn + j * 8 + (lane & 3) * 2;
            float2 v0 = make_float2(acc[f][j][0] + bv0, acc[f][j][1] + bv0);
            float2 v1 = make_float2(acc[f][j][2] + bv1, acc[f][j][3] + bv1);
            *(float2*)(cp0 + col) = v0;
            *(float2*)(cp1 + col) = v1;
        }
    }
}

// ---------------------------------------------------------------------------
// Pool + sigmoid gate (unchanged)
// ---------------------------------------------------------------------------
__device__ __forceinline__ float sigmoidf_(float x) {
    return 1.f / (1.f + __expf(-x));
}

__global__ void __launch_bounds__(256) pool_kernel(
    const float* __restrict__ qkv, float* __restrict__ kp, float* __restrict__ vp)
{
    const int bc = blockIdx.x;
    const int b = bc >> 9;
    const int c = bc & 511;
    const int part = blockIdx.y;
    const float* src = qkv + ((size_t)b * QKVC + 512 + part * 512 + c) * S;
    float* dstbase = part ? vp : kp;
    float* dst = dstbase + ((size_t)(b * HEADS + (c >> 6)) * DH + (c & 63)) * NKV;

    __shared__ float ts[S];
    const int tid = threadIdx.x;
    ((float4*)ts)[tid] = ((const float4*)src)[tid];
    __syncthreads();

    if (tid < 32) {
        float s = 0.f;
#pragma unroll
        for (int w = 0; w < 32; w++) s += ts[tid * 32 + w];
        dst[tid] = sigmoidf_(s * (1.f / 32.f));
    } else if (tid < 64) {
        const int w = tid - 32;
        float s = 0.f;
#pragma unroll
        for (int hh = 0; hh < 32; hh++) s += ts[hh * 32 + w];
        dst[tid] = sigmoidf_(s * (1.f / 32.f));
    }
    {
        const int ph = tid >> 4, pw = tid & 15;
        const float s = ts[(2 * ph) * 32 + 2 * pw] + ts[(2 * ph) * 32 + 2 * pw + 1]
                      + ts[(2 * ph + 1) * 32 + 2 * pw] + ts[(2 * ph + 1) * 32 + 2 * pw + 1];
        dst[64 + tid] = sigmoidf_(s * 0.25f);
    }
}

// ---------------------------------------------------------------------------
// Fused attention (FFMA, as R1); epilogue emits bf16 hi/lo in [B,S,C]
// ---------------------------------------------------------------------------
#define TS 64
#define KST 65
#define SST 321
#define ATTN_SMEM ((TS*KST + NKV*KST + TS*SST) * 4)

__global__ void __launch_bounds__(256, 1) attn_kernel(
    const float* __restrict__ qkv,
    const float* __restrict__ kp,
    const float* __restrict__ vp,
    const float* __restrict__ pos,
    __nv_bfloat16* __restrict__ atth, __nv_bfloat16* __restrict__ attl)
{
    extern __shared__ float sm[];
    float* qs = sm;
    float* kv = sm + TS * KST;
    float* sc = kv + NKV * KST;

    const int b = blockIdx.z, hd = blockIdx.y;
    const int s0 = blockIdx.x * TS;
    const int tid = threadIdx.x;
    const float scale = 0.125f;

    const float* qg = qkv + ((size_t)b * QKVC + hd * DH) * S + s0;
    for (int idx = tid; idx < TS * DH; idx += 256) {
        const int dd = idx >> 6, si = idx & 63;
        qs[si * KST + dd] = qg[(size_t)dd * S + si] * scale;
    }
    const float* kg = kp + (size_t)(b * HEADS + hd) * DH * NKV;
    for (int i4 = tid; i4 < DH * NKV / 4; i4 += 256) {
        const float4 d = ((const float4*)kg)[i4];
        const int lin = i4 * 4;
        const int dd = lin / NKV;
        const int n  = lin - dd * NKV;
        kv[(n    ) * KST + dd] = d.x;
        kv[(n + 1) * KST + dd] = d.y;
        kv[(n + 2) * KST + dd] = d.z;
        kv[(n + 3) * KST + dd] = d.w;
    }
    __syncthreads();

    {
        const int ng = tid & 31;
        const int sg = tid >> 5;
        const int sbs = sg * 8;
        float acc[8][10];
#pragma unroll
        for (int i = 0; i < 8; i++)
#pragma unroll
            for (int j = 0; j < 10; j++) acc[i][j] = 0.f;

#pragma unroll 4
        for (int dd = 0; dd < DH; dd++) {
            float qv[8];
#pragma unroll
            for (int i = 0; i < 8; i++) qv[i] = qs[(sbs + i) * KST + dd];
#pragma unroll
            for (int j = 0; j < 10; j++) {
                const float kval = kv[(ng + 32 * j) * KST + dd];
#pragma unroll
                for (int i = 0; i < 8; i++)
                    acc[i][j] = fmaf(qv[i], kval, acc[i][j]);
            }
        }
        const float* pr = pos + (size_t)(s0 + sbs) * NKV + ng;
#pragma unroll
        for (int i = 0; i < 8; i++)
#pragma unroll
            for (int j = 0; j < 10; j++)
                sc[(sbs + i) * SST + ng + 32 * j] =
                    acc[i][j] + pr[(size_t)i * NKV + 32 * j];
    }
    __syncthreads();

    const float* vg = vp + (size_t)(b * HEADS + hd) * DH * NKV;
    for (int i4 = tid; i4 < DH * NKV / 4; i4 += 256) {
        const float4 d = ((const float4*)vg)[i4];
        const int lin = i4 * 4;
        const int dd = lin / NKV;
        const int n  = lin - dd * NKV;
        kv[(n    ) * KST + dd] = d.x;
        kv[(n + 1) * KST + dd] = d.y;
        kv[(n + 2) * KST + dd] = d.z;
        kv[(n + 3) * KST + dd] = d.w;
    }

    {
        const int r = tid >> 2, cq = tid & 3;
        float* row = sc + r * SST;
        float m = -1e30f;
        for (int k = cq; k < NKV; k += 4) m = fmaxf(m, row[k]);
        m = fmaxf(m, __shfl_xor_sync(0xffffffffu, m, 1));
        m = fmaxf(m, __shfl_xor_sync(0xffffffffu, m, 2));
        float ssum = 0.f;
        for (int k = cq; k < NKV; k += 4) {
            const float e = __expf(row[k] - m);
            row[k] = e;
            ssum += e;
        }
        ssum += __shfl_xor_sync(0xffffffffu, ssum, 1);
        ssum += __shfl_xor_sync(0xffffffffu, ssum, 2);
        const float inv = 1.f / ssum;
        for (int k = cq; k < NKV; k += 4) row[k] *= inv;
    }
    __syncthreads();

    {
        const int ty = tid >> 4, tx = tid & 15;
        float acc[4][4];
#pragma unroll
        for (int i = 0; i < 4; i++)
#pragma unroll
            for (int j = 0; j < 4; j++) acc[i][j] = 0.f;

#pragma unroll 4
        for (int n = 0; n < NKV; n++) {
            float p[4], vv[4];
#pragma unroll
            for (int i = 0; i < 4; i++) p[i] = sc[(ty + 16 * i) * SST + n];
#pragma unroll
            for (int j = 0; j < 4; j++) vv[j] = kv[n * KST + tx + 16 * j];
#pragma unroll
            for (int i = 0; i < 4; i++)
#pragma unroll
                for (int j = 0; j < 4; j++)
                    acc[i][j] = fmaf(p[i], vv[j], acc[i][j]);
        }
#pragma unroll
        for (int i = 0; i < 4; i++)
#pragma unroll
            for (int j = 0; j < 4; j++)
                qs[(ty + 16 * i) * KST + (tx + 16 * j)] = acc[i][j];
    }
    __syncthreads();

    // write att hi/lo bf16, layout [B, S, C]
    for (int idx = tid; idx < TS * DH; idx += 256) {
        const int si = idx >> 6, dd = idx & 63;
        const float v = qs[si * KST + dd];
        const __nv_bfloat16 hi = __float2bfloat16_rn(v);
        const size_t off = ((size_t)b * S + s0 + si) * CIN + hd * DH + dd;
        atth[off] = hi;
        attl[off] = __float2bfloat16_rn(v - __bfloat162float(hi));
    }
}

// ---------------------------------------------------------------------------
// Launch
// ---------------------------------------------------------------------------
extern "C" void kernel_launch(void* const* d_in, const int* in_sizes, int n_in,
                              void* d_out, int out_size)
{
    const float* x     = (const float*)d_in[0];
    const float* Wqkv  = (const float*)d_in[1];
    const float* Wout  = (const float*)d_in[2];
    const float* bout  = (const float*)d_in[3];
    const float* pos   = (const float*)d_in[4];
    float* out = (float*)d_out;

    float *p_qkv, *p_k, *p_v;
    __nv_bfloat16 *p_xh, *p_xl, *p_ath, *p_atl, *p_wqh, *p_wql, *p_woh, *p_wol;
    cudaGetSymbolAddress((void**)&p_qkv, g_qkv);
    cudaGetSymbolAddress((void**)&p_xh,  g_xh);
    cudaGetSymbolAddress((void**)&p_xl,  g_xl);
    cudaGetSymbolAddress((void**)&p_k,   g_k);
    cudaGetSymbolAddress((void**)&p_v,   g_v);
    cudaGetSymbolAddress((void**)&p_ath, g_ath);
    cudaGetSymbolAddress((void**)&p_atl, g_atl);
    cudaGetSymbolAddress((void**)&p_wqh, g_wqh);
    cudaGetSymbolAddress((void**)&p_wql, g_wql);
    cudaGetSymbolAddress((void**)&p_woh, g_woh);
    cudaGetSymbolAddress((void**)&p_wol, g_wol);

    cudaFuncSetAttribute(gemm_mma_kernel,
                         cudaFuncAttributeMaxDynamicSharedMemorySize, GSMEM);
    cudaFuncSetAttribute(attn_kernel,
                         cudaFuncAttributeMaxDynamicSharedMemorySize, ATTN_SMEM);

    // 0) operand prep
    split_kernel<<<(QKVC * KDIM + 255) / 256, 256>>>(Wqkv, p_wqh, p_wql, QKVC * KDIM);
    split_kernel<<<(COUT * KDIM + 255) / 256, 256>>>(Wout, p_woh, p_wol, COUT * KDIM);
    tsplit_kernel<<<dim3(S / 32, KDIM / 32, BATCH), dim3(32, 8)>>>(x, p_xh, p_xl);

    // 1) qkv = Wqkv @ x^T   [B,1536,1024]
    gemm_mma_kernel<<<dim3(S / 128, QKVC / 128, BATCH), 256, GSMEM>>>(
        p_wqh, p_wql, p_xh, p_xl, p_qkv, nullptr, S);

    // 2) pool + sigmoid gates
    pool_kernel<<<dim3(BATCH * CIN, 2), 256>>>(p_qkv, p_k, p_v);

    // 3) fused attention -> att hi/lo bf16 [B,S,C]
    attn_kernel<<<dim3(S / TS, HEADS, BATCH), 256, ATTN_SMEM>>>(
        p_qkv, p_k, p_v, pos, p_ath, p_atl);

    // 4) out = Wout @ att^T + bout   [B,512,1024]
    gemm_mma_kernel<<<dim3(S / 128, COUT / 128, BATCH), 256, GSMEM>>>(
        p_woh, p_wol, p_ath, p_atl, out, bout, S);
}

// round 4
// speedup vs baseline: 2.1420x; 1.6496x over previous
#include <cuda_runtime.h>
#include <cuda_bf16.h>
#include <cuda_fp16.h>
#include <math.h>
#include <stdint.h>

// ---------------------------------------------------------------------------
// Problem constants
// ---------------------------------------------------------------------------
#define BATCH   32
#define CIN     512
#define COUT    512
#define HEADS   8
#define DH      64
#define S       1024
#define NKV     320
#define QKVC    1536
#define KDIM    512

// ---------------------------------------------------------------------------
// Scratch (device globals)
// ---------------------------------------------------------------------------
__device__ float g_qkv[(size_t)BATCH * QKVC * S];                        // [B,1536,1024]
__device__ __align__(16) __nv_bfloat16 g_xh [(size_t)BATCH * S * KDIM];
__device__ __align__(16) __nv_bfloat16 g_xl [(size_t)BATCH * S * KDIM];
__device__ __align__(16) __half g_kh[(size_t)BATCH * HEADS * NKV * DH];  // K hi [b,h,n,d]
__device__ __align__(16) __half g_kl[(size_t)BATCH * HEADS * NKV * DH];
__device__ __align__(16) __half g_vh[(size_t)BATCH * HEADS * DH * NKV];  // V hi [b,h,d,n]
__device__ __align__(16) __half g_vl[(size_t)BATCH * HEADS * DH * NKV];
__device__ __align__(16) __nv_bfloat16 g_ath[(size_t)BATCH * S * CIN];   // att hi [B,S,C]
__device__ __align__(16) __nv_bfloat16 g_atl[(size_t)BATCH * S * CIN];
__device__ __align__(16) __nv_bfloat16 g_wqh[(size_t)QKVC * KDIM];
__device__ __align__(16) __nv_bfloat16 g_wql[(size_t)QKVC * KDIM];
__device__ __align__(16) __nv_bfloat16 g_woh[(size_t)COUT * KDIM];
__device__ __align__(16) __nv_bfloat16 g_wol[(size_t)COUT * KDIM];

// ---------------------------------------------------------------------------
// PTX helpers
// ---------------------------------------------------------------------------
__device__ __forceinline__ uint32_t smem_u32(const void* p) {
    uint32_t a;
    asm("{ .reg .u64 t; cvta.to.shared.u64 t, %1; cvt.u32.u64 %0, t; }"
        : "=r"(a) : "l"(p));
    return a;
}
__device__ __forceinline__ void cpasync16(uint32_t s, const void* g) {
    asm volatile("cp.async.cg.shared.global [%0], [%1], 16;" :: "r"(s), "l"(g));
}
#define CP_COMMIT() asm volatile("cp.async.commit_group;" ::: "memory")
#define CP_WAIT(N)  asm volatile("cp.async.wait_group %0;" :: "n"(N) : "memory")

#define LDSM_X4(r, addr) \
    asm volatile("ldmatrix.sync.aligned.m8n8.x4.shared.b16 {%0,%1,%2,%3}, [%4];" \
                 : "=r"((r)[0]), "=r"((r)[1]), "=r"((r)[2]), "=r"((r)[3]) : "r"(addr))

__device__ __forceinline__ void mma_bf16(float* d, const uint32_t* a,
                                         uint32_t b0, uint32_t b1) {
    asm volatile(
        "mma.sync.aligned.m16n8k16.row.col.f32.bf16.bf16.f32 "
        "{%0,%1,%2,%3}, {%4,%5,%6,%7}, {%8,%9}, {%0,%1,%2,%3};"
        : "+f"(d[0]), "+f"(d[1]), "+f"(d[2]), "+f"(d[3])
        : "r"(a[0]), "r"(a[1]), "r"(a[2]), "r"(a[3]), "r"(b0), "r"(b1));
}
__device__ __forceinline__ void mma_f16(float* d, const uint32_t* a,
                                        uint32_t b0, uint32_t b1) {
    asm volatile(
        "mma.sync.aligned.m16n8k16.row.col.f32.f16.f16.f32 "
        "{%0,%1,%2,%3}, {%4,%5,%6,%7}, {%8,%9}, {%0,%1,%2,%3};"
        : "+f"(d[0]), "+f"(d[1]), "+f"(d[2]), "+f"(d[3])
        : "r"(a[0]), "r"(a[1]), "r"(a[2]), "r"(a[3]), "r"(b0), "r"(b1));
}

// ---------------------------------------------------------------------------
// fp32 -> bf16 hi/lo split (weights) ; transpose+split for x
// ---------------------------------------------------------------------------
__global__ void split_kernel(const float* __restrict__ a,
                             __nv_bfloat16* __restrict__ h,
                             __nv_bfloat16* __restrict__ l, int n)
{
    int i = blockIdx.x * 256 + threadIdx.x;
    if (i < n) {
        float v = a[i];
        __nv_bfloat16 hi = __float2bfloat16_rn(v);
        h[i] = hi;
        l[i] = __float2bfloat16_rn(v - __bfloat162float(hi));
    }
}

__global__ void __launch_bounds__(256) tsplit_kernel(
    const float* __restrict__ x,
    __nv_bfloat16* __restrict__ oh, __nv_bfloat16* __restrict__ ol)
{
    __shared__ float t[32][33];
    const int n0 = blockIdx.x * 32, k0 = blockIdx.y * 32, b = blockIdx.z;
    const int tx = threadIdx.x, ty = threadIdx.y;
    const float* src = x + ((size_t)b * KDIM + k0) * S + n0;
#pragma unroll
    for (int i = 0; i < 4; i++)
        t[ty + 8 * i][tx] = src[(size_t)(ty + 8 * i) * S + tx];
    __syncthreads();
    __nv_bfloat16* dh = oh + ((size_t)b * S + n0) * KDIM + k0;
    __nv_bfloat16* dl = ol + ((size_t)b * S + n0) * KDIM + k0;
#pragma unroll
    for (int i = 0; i < 4; i++) {
        float v = t[tx][ty + 8 * i];
        __nv_bfloat16 hi = __float2bfloat16_rn(v);
        dh[(size_t)(ty + 8 * i) * KDIM + tx] = hi;
        dl[(size_t)(ty + 8 * i) * KDIM + tx] =
            __float2bfloat16_rn(v - __bfloat162float(hi));
    }
}

// ---------------------------------------------------------------------------
// HMMA bf16 3x-split batched GEMM (unchanged from R3)
// ---------------------------------------------------------------------------
#define NCH     32
#define STG_SZ  24576
#define T_AL    6144
#define T_BH    12288
#define T_BL    18432
#define GSMEM   (4 * STG_SZ)

__global__ void __launch_bounds__(256) gemm_mma_kernel(
    const __nv_bfloat16* __restrict__ Ah, const __nv_bfloat16* __restrict__ Al,
    const __nv_bfloat16* __restrict__ Bh, const __nv_bfloat16* __restrict__ Bl,
    float* __restrict__ C, const float* __restrict__ bias, int Ntot)
{
    extern __shared__ char smem[];
    const uint32_t sbase = smem_u32(smem);

    const int tid = threadIdx.x;
    const int n0 = blockIdx.x * 128;
    const int m0 = blockIdx.y * 128;
    const int M  = gridDim.y * 128;
    const size_t bo = (size_t)blockIdx.z * Ntot * KDIM;
    const size_t co = (size_t)blockIdx.z * M * Ntot;

    const __nv_bfloat16* Bhb = Bh + bo;
    const __nv_bfloat16* Blb = Bl + bo;

    const int lrow = tid >> 1, lhalf = tid & 1;
    const uint32_t lso = (uint32_t)(lrow * 48 + lhalf * 16);

    const int wid = tid >> 5, lane = tid & 31;
    const int wm = (wid & 3) * 32, wn = (wid >> 2) * 64;
    const uint32_t aoff = (uint32_t)((wm + (lane & 15)) * 48 + (lane >> 4) * 16);
    const uint32_t boff = (uint32_t)(T_BH + (wn + (lane & 15)) * 48 + (lane >> 4) * 16);

    float acc[2][8][4];
#pragma unroll
    for (int f = 0; f < 2; f++)
#pragma unroll
        for (int j = 0; j < 8; j++)
#pragma unroll
            for (int r = 0; r < 4; r++) acc[f][j][r] = 0.f;

#define ISSUE(cc, st) do {                                                    \
        const size_t ga = (size_t)(m0 + lrow) * KDIM + (cc) * 16 + lhalf * 8; \
        const size_t gb = (size_t)(n0 + lrow) * KDIM + (cc) * 16 + lhalf * 8; \
        const uint32_t sb = sbase + (st) * STG_SZ + lso;                      \
        cpasync16(sb,         Ah  + ga);                                      \
        cpasync16(sb + T_AL,  Al  + ga);                                      \
        cpasync16(sb + T_BH,  Bhb + gb);                                      \
        cpasync16(sb + T_BL,  Blb + gb);                                      \
    } while (0)

    ISSUE(0, 0); CP_COMMIT();
    ISSUE(1, 1); CP_COMMIT();
    ISSUE(2, 2); CP_COMMIT();

    for (int c = 0; c < NCH; c++) {
        if (c + 3 < NCH) ISSUE(c + 3, (c + 3) & 3);
        CP_COMMIT();
        CP_WAIT(3);
        __syncthreads();

        const uint32_t sa = sbase + (uint32_t)((c & 3) * STG_SZ);
        uint32_t ah[2][4], al[2][4];
        LDSM_X4(ah[0], sa + aoff);
        LDSM_X4(ah[1], sa + aoff + 768);
        LDSM_X4(al[0], sa + aoff + T_AL);
        LDSM_X4(al[1], sa + aoff + T_AL + 768);
#pragma unroll
        for (int g = 0; g < 4; g++) {
            uint32_t bh[4], bl[4];
            LDSM_X4(bh, sa + boff + g * 768);
            LDSM_X4(bl, sa + boff + g * 768 + T_AL);
#pragma unroll
            for (int f = 0; f < 2; f++) {
                mma_bf16(acc[f][2 * g],     ah[f], bh[0], bh[2]);
                mma_bf16(acc[f][2 * g],     al[f], bh[0], bh[2]);
                mma_bf16(acc[f][2 * g],     ah[f], bl[0], bl[2]);
                mma_bf16(acc[f][2 * g + 1], ah[f], bh[1], bh[3]);
                mma_bf16(acc[f][2 * g + 1], al[f], bh[1], bh[3]);
                mma_bf16(acc[f][2 * g + 1], ah[f], bl[1], bl[3]);
            }
        }
        __syncthreads();
    }
#undef ISSUE

#pragma unroll
    for (int f = 0; f < 2; f++) {
        const int r0 = m0 + wm + f * 16 + (lane >> 2);
        const float bv0 = bias ? bias[r0] : 0.f;
        const float bv1 = bias ? bias[r0 + 8] : 0.f;
        float* cp0 = C + co + (size_t)r0 * Ntot;
        float* cp1 = cp0 + (size_t)8 * Ntot;
#pragma unroll
        for (int j = 0; j < 8; j++) {
            const int col = n0 + wn + j * 8 + (lane & 3) * 2;
            float2 v0 = make_float2(acc[f][j][0] + bv0, acc[f][j][1] + bv0);
            float2 v1 = make_float2(acc[f][j][2] + bv1, acc[f][j][3] + bv1);
            *(float2*)(cp0 + col) = v0;
            *(float2*)(cp1 + col) = v1;
        }
    }
}

// ---------------------------------------------------------------------------
// Pool + sigmoid gate -> fp16 hi/lo.  K: [b,h,n,d]  V: [b,h,d,n]
// ---------------------------------------------------------------------------
__global__ void __launch_bounds__(256) pool_kernel(
    const float* __restrict__ qkv,
    __half* __restrict__ khg, __half* __restrict__ klg,
    __half* __restrict__ vhg, __half* __restrict__ vlg)
{
    const int bc = blockIdx.x;
    const int b = bc >> 9;
    const int c = bc & 511;
    const int part = blockIdx.y;           // 0 = k, 1 = v
    const int bh = b * HEADS + (c >> 6);
    const int d  = c & 63;
    const float* src = qkv + ((size_t)b * QKVC + 512 + part * 512 + c) * S;

    __shared__ float ts[S];
    const int tid = threadIdx.x;
    ((float4*)ts)[tid] = ((const float4*)src)[tid];
    __syncthreads();

    auto store = [&](int n, float pooled) {
        const float sv = 1.f / (1.f + __expf(-pooled));
        const __half hi = __float2half_rn(sv);
        const __half lo = __float2half_rn(sv - __half2float(hi));
        if (part == 0) {
            const size_t idx = ((size_t)bh * NKV + n) * DH + d;
            khg[idx] = hi; klg[idx] = lo;
        } else {
            const size_t idx = ((size_t)bh * DH + d) * NKV + n;
            vhg[idx] = hi; vlg[idx] = lo;
        }
    };

    if (tid < 32) {
        float s = 0.f;
#pragma unroll
        for (int w = 0; w < 32; w++) s += ts[tid * 32 + w];
        store(tid, s * (1.f / 32.f));
    } else if (tid < 64) {
        const int w = tid - 32;
        float s = 0.f;
#pragma unroll
        for (int hh = 0; hh < 32; hh++) s += ts[hh * 32 + w];
        store(32 + (tid - 32), s * (1.f / 32.f));
    }
    {
        const int ph = tid >> 4, pw = tid & 15;
        const float s = ts[(2 * ph) * 32 + 2 * pw] + ts[(2 * ph) * 32 + 2 * pw + 1]
                      + ts[(2 * ph + 1) * 32 + 2 * pw] + ts[(2 * ph + 1) * 32 + 2 * pw + 1];
        store(64 + tid, s * 0.25f);
    }
}

// ---------------------------------------------------------------------------
// MMA attention.  CTA = (64 queries, head, batch).  fp16 tensor-core QK^T+AV.
// ---------------------------------------------------------------------------
#define TQ       64
#define Q_ROW    144
#define K_ROW    144
#define V_ROW    656
#define SC_ROWB  1296          // 324 floats
#define A_SA_Q   0
#define A_Q_LO   9216
#define A_SA_K   18432
#define A_K_LO   46080         // hi->lo offset
#define A_SA_V   18432         // overlays K (dead after QK^T)
#define A_V_LO   41984
#define A_SA_SC  110592
#define A_SA_INV 193536
#define ATTN2_SMEM 193792

__global__ void __launch_bounds__(256, 1) attn_mma_kernel(
    const float* __restrict__ qkv,
    const __half* __restrict__ khg, const __half* __restrict__ klg,
    const __half* __restrict__ vhg, const __half* __restrict__ vlg,
    const float* __restrict__ pos,
    __nv_bfloat16* __restrict__ atth, __nv_bfloat16* __restrict__ attl)
{
    extern __shared__ char sm[];
    const uint32_t sb = smem_u32(sm);
    const int b = blockIdx.z, hd = blockIdx.y;
    const int s0 = blockIdx.x * TQ;
    const int tid = threadIdx.x, wid = tid >> 5, lane = tid & 31;

    // ---- K tiles via cp.async: [n][d] 128B rows, hi+lo ----
    {
        const char* kh = (const char*)(khg + (size_t)(b * HEADS + hd) * NKV * DH);
        const char* kl = (const char*)(klg + (size_t)(b * HEADS + hd) * NKV * DH);
#pragma unroll
        for (int i = 0; i < 10; i++) {
            const int c = tid + i * 256;
            const uint32_t dst = sb + A_SA_K + (c >> 3) * K_ROW + (c & 7) * 16;
            cpasync16(dst,          kh + (size_t)c * 16);
            cpasync16(dst + A_K_LO, kl + (size_t)c * 16);
        }
        CP_COMMIT();
    }
    // ---- Q: load fp32, scale, split fp16 hi/lo into [si][dd] ----
    {
        const float* qg = qkv + ((size_t)b * QKVC + hd * DH) * S + s0;
#pragma unroll
        for (int i = 0; i < 16; i++) {
            const int idx = tid + i * 256;
            const int dd = idx >> 6, si = idx & 63;
            const float v = qg[(size_t)dd * S + si] * 0.125f;
            const __half hi = __float2half_rn(v);
            *(__half*)(sm + A_SA_Q + si * Q_ROW + dd * 2) = hi;
            *(__half*)(sm + A_SA_Q + A_Q_LO + si * Q_ROW + dd * 2) =
                __float2half_rn(v - __half2float(hi));
        }
    }
    CP_WAIT(0);
    __syncthreads();

    const int m0w = (wid & 3) * 16;

    // ---- QK^T: warp n-half of 160; scores fp32 -> smem ----
    {
        const int n0w = (wid >> 2) * 160;
        float acc[20][4];
#pragma unroll
        for (int t = 0; t < 20; t++) {
            acc[t][0] = 0.f; acc[t][1] = 0.f; acc[t][2] = 0.f; acc[t][3] = 0.f;
        }
#pragma unroll
        for (int k = 0; k < 4; k++) {
            uint32_t ah[4], al[4];
            const uint32_t qa = sb + A_SA_Q + (m0w + (lane & 15)) * Q_ROW
                              + (lane >> 4) * 16 + k * 32;
            LDSM_X4(ah, qa);
            LDSM_X4(al, qa + A_Q_LO);
#pragma unroll
            for (int jn = 0; jn < 10; jn++) {
                uint32_t bh[4], bl[4];
                const uint32_t ka = sb + A_SA_K
                                  + (n0w + jn * 16 + (lane & 15)) * K_ROW
                                  + (lane >> 4) * 16 + k * 32;
                LDSM_X4(bh, ka);
                LDSM_X4(bl, ka + A_K_LO);
                mma_f16(acc[2 * jn],     ah, bh[0], bh[2]);
                mma_f16(acc[2 * jn],     al, bh[0], bh[2]);
                mma_f16(acc[2 * jn],     ah, bl[0], bl[2]);
                mma_f16(acc[2 * jn + 1], ah, bh[1], bh[3]);
                mma_f16(acc[2 * jn + 1], al, bh[1], bh[3]);
                mma_f16(acc[2 * jn + 1], ah, bl[1], bl[3]);
            }
        }
        const int r0 = m0w + (lane >> 2);
#pragma unroll
        for (int jn = 0; jn < 10; jn++)
#pragma unroll
            for (int t = 0; t < 2; t++) {
                const int n = n0w + jn * 16 + t * 8 + (lane & 3) * 2;
                float* p0 = (float*)(sm + A_SA_SC + r0 * SC_ROWB) + n;
                float* p1 = (float*)(sm + A_SA_SC + (r0 + 8) * SC_ROWB) + n;
                *(float2*)p0 = make_float2(acc[2 * jn + t][0], acc[2 * jn + t][1]);
                *(float2*)p1 = make_float2(acc[2 * jn + t][2], acc[2 * jn + t][3]);
            }
    }
    __syncthreads();

    // ---- V loads into dead K region: [d][n] 640B rows, hi+lo ----
    {
        const char* vh = (const char*)(vhg + (size_t)(b * HEADS + hd) * DH * NKV);
        const char* vl = (const char*)(vlg + (size_t)(b * HEADS + hd) * DH * NKV);
#pragma unroll
        for (int i = 0; i < 10; i++) {
            const int c = tid + i * 256;
            const int d = c / 40, o = c % 40;
            const uint32_t dst = sb + A_SA_V + d * V_ROW + o * 16;
            cpasync16(dst,          vh + (size_t)c * 16);
            cpasync16(dst + A_V_LO, vl + (size_t)c * 16);
        }
        CP_COMMIT();
    }

    // ---- softmax per row (quad); P = exp(sc-max) fp16, in place; 1/sum saved ----
    {
        const int r = tid >> 2, cq = tid & 3;
        float* row = (float*)(sm + A_SA_SC + r * SC_ROWB);
        __half* ph = (__half*)(sm + A_SA_SC + r * SC_ROWB);
        const float* pr = pos + (size_t)(s0 + r) * NKV;
        float mx = -1e30f;
        for (int k = cq; k < NKV; k += 4) {
            const float v = row[k] + pr[k];
            row[k] = v;
            mx = fmaxf(mx, v);
        }
        mx = fmaxf(mx, __shfl_xor_sync(0xffffffffu, mx, 1));
        mx = fmaxf(mx, __shfl_xor_sync(0xffffffffu, mx, 2));
        float ssum = 0.f;
#pragma unroll
        for (int c5 = 0; c5 < 5; c5++) {
            float e[16];
#pragma unroll
            for (int j = 0; j < 16; j++) {
                e[j] = __expf(row[c5 * 64 + cq + 4 * j] - mx);
                ssum += e[j];
            }
            __syncwarp();      // all reads of this chunk done before 2B writes alias
#pragma unroll
            for (int j = 0; j < 16; j++)
                ph[c5 * 64 + cq + 4 * j] = __float2half_rn(e[j]);
            __syncwarp();
        }
        ssum += __shfl_xor_sync(0xffffffffu, ssum, 1);
        ssum += __shfl_xor_sync(0xffffffffu, ssum, 2);
        if (cq == 0) *(float*)(sm + A_SA_INV + r * 4) = 1.f / ssum;
    }
    CP_WAIT(0);
    __syncthreads();

    // ---- AV: out[m16][dd32] over K=320 ----
    {
        const int dn0 = (wid >> 2) * 32;
        float oa[4][4];
#pragma unroll
        for (int t = 0; t < 4; t++) {
            oa[t][0] = 0.f; oa[t][1] = 0.f; oa[t][2] = 0.f; oa[t][3] = 0.f;
        }
#pragma unroll
        for (int k = 0; k < 20; k++) {
            uint32_t pa[4], v0h[4], v1h[4], v0l[4], v1l[4];
            LDSM_X4(pa, sb + A_SA_SC + (m0w + (lane & 15)) * SC_ROWB
                        + (lane >> 4) * 16 + k * 32);
            const uint32_t va = sb + A_SA_V + (dn0 + (lane & 15)) * V_ROW
                              + (lane >> 4) * 16 + k * 32;
            LDSM_X4(v0h, va);
            LDSM_X4(v0l, va + A_V_LO);
            LDSM_X4(v1h, va + 16 * V_ROW);
            LDSM_X4(v1l, va + 16 * V_ROW + A_V_LO);
            mma_f16(oa[0], pa, v0h[0], v0h[2]);
            mma_f16(oa[0], pa, v0l[0], v0l[2]);
            mma_f16(oa[1], pa, v0h[1], v0h[3]);
            mma_f16(oa[1], pa, v0l[1], v0l[3]);
            mma_f16(oa[2], pa, v1h[0], v1h[2]);
            mma_f16(oa[2], pa, v1l[0], v1l[2]);
            mma_f16(oa[3], pa, v1h[1], v1h[3]);
            mma_f16(oa[3], pa, v1l[1], v1l[3]);
        }
        const float inv0 = *(const float*)(sm + A_SA_INV + (m0w + (lane >> 2)) * 4);
        const float inv1 = *(const float*)(sm + A_SA_INV + (m0w + 8 + (lane >> 2)) * 4);
        const size_t ro0 = ((size_t)b * S + s0 + m0w + (lane >> 2)) * CIN + hd * DH;
        const size_t ro1 = ro0 + (size_t)8 * CIN;
#pragma unroll
        for (int jt = 0; jt < 4; jt++) {
            const int col = dn0 + jt * 8 + (lane & 3) * 2;
            const float v0 = oa[jt][0] * inv0, v1 = oa[jt][1] * inv0;
            const float v2 = oa[jt][2] * inv1, v3 = oa[jt][3] * inv1;
            __nv_bfloat162 h0 = __floats2bfloat162_rn(v0, v1);
            __nv_bfloat162 h1 = __floats2bfloat162_rn(v2, v3);
            __nv_bfloat162 l0 = __floats2bfloat162_rn(v0 - __bfloat162float(h0.x),
                                                      v1 - __bfloat162float(h0.y));
            __nv_bfloat162 l1 = __floats2bfloat162_rn(v2 - __bfloat162float(h1.x),
                                                      v3 - __bfloat162float(h1.y));
            *(__nv_bfloat162*)(atth + ro0 + col) = h0;
            *(__nv_bfloat162*)(attl + ro0 + col) = l0;
            *(__nv_bfloat162*)(atth + ro1 + col) = h1;
            *(__nv_bfloat162*)(attl + ro1 + col) = l1;
        }
    }
}

// ---------------------------------------------------------------------------
// Launch
// ---------------------------------------------------------------------------
extern "C" void kernel_launch(void* const* d_in, const int* in_sizes, int n_in,
                              void* d_out, int out_size)
{
    const float* x     = (const float*)d_in[0];
    const float* Wqkv  = (const float*)d_in[1];
    const float* Wout  = (const float*)d_in[2];
    const float* bout  = (const float*)d_in[3];
    const float* pos   = (const float*)d_in[4];
    float* out = (float*)d_out;

    float *p_qkv;
    __half *p_kh, *p_kl, *p_vh, *p_vl;
    __nv_bfloat16 *p_xh, *p_xl, *p_ath, *p_atl, *p_wqh, *p_wql, *p_woh, *p_wol;
    cudaGetSymbolAddress((void**)&p_qkv, g_qkv);
    cudaGetSymbolAddress((void**)&p_xh,  g_xh);
    cudaGetSymbolAddress((void**)&p_xl,  g_xl);
    cudaGetSymbolAddress((void**)&p_kh,  g_kh);
    cudaGetSymbolAddress((void**)&p_kl,  g_kl);
    cudaGetSymbolAddress((void**)&p_vh,  g_vh);
    cudaGetSymbolAddress((void**)&p_vl,  g_vl);
    cudaGetSymbolAddress((void**)&p_ath, g_ath);
    cudaGetSymbolAddress((void**)&p_atl, g_atl);
    cudaGetSymbolAddress((void**)&p_wqh, g_wqh);
    cudaGetSymbolAddress((void**)&p_wql, g_wql);
    cudaGetSymbolAddress((void**)&p_woh, g_woh);
    cudaGetSymbolAddress((void**)&p_wol, g_wol);

    cudaFuncSetAttribute(gemm_mma_kernel,
                         cudaFuncAttributeMaxDynamicSharedMemorySize, GSMEM);
    cudaFuncSetAttribute(attn_mma_kernel,
                         cudaFuncAttributeMaxDynamicSharedMemorySize, ATTN2_SMEM);

    // 0) operand prep
    split_kernel<<<(QKVC * KDIM + 255) / 256, 256>>>(Wqkv, p_wqh, p_wql, QKVC * KDIM);
    split_kernel<<<(COUT * KDIM + 255) / 256, 256>>>(Wout, p_woh, p_wol, COUT * KDIM);
    tsplit_kernel<<<dim3(S / 32, KDIM / 32, BATCH), dim3(32, 8)>>>(x, p_xh, p_xl);

    // 1) qkv = Wqkv @ x^T   [B,1536,1024]
    gemm_mma_kernel<<<dim3(S / 128, QKVC / 128, BATCH), 256, GSMEM>>>(
        p_wqh, p_wql, p_xh, p_xl, p_qkv, nullptr, S);

    // 2) pool + sigmoid gates -> fp16 hi/lo K,V
    pool_kernel<<<dim3(BATCH * CIN, 2), 256>>>(p_qkv, p_kh, p_kl, p_vh, p_vl);

    // 3) tensor-core attention -> att hi/lo bf16 [B,S,C]
    attn_mma_kernel<<<dim3(S / TQ, HEADS, BATCH), 256, ATTN2_SMEM>>>(
        p_qkv, p_kh, p_kl, p_vh, p_vl, pos, p_ath, p_atl);

    // 4) out = Wout @ att^T + bout   [B,512,1024]
    gemm_mma_kernel<<<dim3(S / 128, COUT / 128, BATCH), 256, GSMEM>>>(
        p_woh, p_wol, p_ath, p_atl, out, bout, S);
}

// round 5
// speedup vs baseline: 2.3616x; 1.1025x over previous
#include <cuda_runtime.h>
#include <cuda_bf16.h>
#include <cuda_fp16.h>
#include <math.h>
#include <stdint.h>

// ---------------------------------------------------------------------------
// Problem constants
// ---------------------------------------------------------------------------
#define BATCH   32
#define CIN     512
#define COUT    512
#define HEADS   8
#define DH      64
#define S       1024
#define NKV     320
#define QKVC    1536
#define KDIM    512

// ---------------------------------------------------------------------------
// Scratch (device globals)
// ---------------------------------------------------------------------------
__device__ float g_qkv[(size_t)BATCH * QKVC * S];                        // [B,1536,1024]
__device__ __align__(16) __nv_bfloat16 g_xh [(size_t)BATCH * S * KDIM];
__device__ __align__(16) __nv_bfloat16 g_xl [(size_t)BATCH * S * KDIM];
__device__ __align__(16) __half g_kh[(size_t)BATCH * HEADS * NKV * DH];  // K hi [b,h,n,d]
__device__ __align__(16) __half g_kl[(size_t)BATCH * HEADS * NKV * DH];
__device__ __align__(16) __half g_vh[(size_t)BATCH * HEADS * DH * NKV];  // V hi [b,h,d,n]
__device__ __align__(16) __half g_vl[(size_t)BATCH * HEADS * DH * NKV];
__device__ __align__(16) __nv_bfloat16 g_ath[(size_t)BATCH * S * CIN];   // att hi [B,S,C]
__device__ __align__(16) __nv_bfloat16 g_atl[(size_t)BATCH * S * CIN];
__device__ __align__(16) __nv_bfloat16 g_wqh[(size_t)QKVC * KDIM];
__device__ __align__(16) __nv_bfloat16 g_wql[(size_t)QKVC * KDIM];
__device__ __align__(16) __nv_bfloat16 g_woh[(size_t)COUT * KDIM];
__device__ __align__(16) __nv_bfloat16 g_wol[(size_t)COUT * KDIM];

// ---------------------------------------------------------------------------
// PTX helpers
// ---------------------------------------------------------------------------
__device__ __forceinline__ uint32_t smem_u32(const void* p) {
    uint32_t a;
    asm("{ .reg .u64 t; cvta.to.shared.u64 t, %1; cvt.u32.u64 %0, t; }"
        : "=r"(a) : "l"(p));
    return a;
}
__device__ __forceinline__ void cpasync16(uint32_t s, const void* g) {
    asm volatile("cp.async.cg.shared.global [%0], [%1], 16;" :: "r"(s), "l"(g));
}
#define CP_COMMIT() asm volatile("cp.async.commit_group;" ::: "memory")
#define CP_WAIT(N)  asm volatile("cp.async.wait_group %0;" :: "n"(N) : "memory")

#define LDSM_X4(r, addr) \
    asm volatile("ldmatrix.sync.aligned.m8n8.x4.shared.b16 {%0,%1,%2,%3}, [%4];" \
                 : "=r"((r)[0]), "=r"((r)[1]), "=r"((r)[2]), "=r"((r)[3]) : "r"(addr))

__device__ __forceinline__ void mma_bf16(float* d, const uint32_t* a,
                                         uint32_t b0, uint32_t b1) {
    asm volatile(
        "mma.sync.aligned.m16n8k16.row.col.f32.bf16.bf16.f32 "
        "{%0,%1,%2,%3}, {%4,%5,%6,%7}, {%8,%9}, {%0,%1,%2,%3};"
        : "+f"(d[0]), "+f"(d[1]), "+f"(d[2]), "+f"(d[3])
        : "r"(a[0]), "r"(a[1]), "r"(a[2]), "r"(a[3]), "r"(b0), "r"(b1));
}
__device__ __forceinline__ void mma_f16(float* d, const uint32_t* a,
                                        uint32_t b0, uint32_t b1) {
    asm volatile(
        "mma.sync.aligned.m16n8k16.row.col.f32.f16.f16.f32 "
        "{%0,%1,%2,%3}, {%4,%5,%6,%7}, {%8,%9}, {%0,%1,%2,%3};"
        : "+f"(d[0]), "+f"(d[1]), "+f"(d[2]), "+f"(d[3])
        : "r"(a[0]), "r"(a[1]), "r"(a[2]), "r"(a[3]), "r"(b0), "r"(b1));
}

// ---------------------------------------------------------------------------
// fp32 -> bf16 hi/lo split (weights) ; transpose+split for x
// ---------------------------------------------------------------------------
__global__ void split_kernel(const float* __restrict__ a,
                             __nv_bfloat16* __restrict__ h,
                             __nv_bfloat16* __restrict__ l, int n)
{
    int i = blockIdx.x * 256 + threadIdx.x;
    if (i < n) {
        float v = a[i];
        __nv_bfloat16 hi = __float2bfloat16_rn(v);
        h[i] = hi;
        l[i] = __float2bfloat16_rn(v - __bfloat162float(hi));
    }
}

__global__ void __launch_bounds__(256) tsplit_kernel(
    const float* __restrict__ x,
    __nv_bfloat16* __restrict__ oh, __nv_bfloat16* __restrict__ ol)
{
    __shared__ float t[32][33];
    const int n0 = blockIdx.x * 32, k0 = blockIdx.y * 32, b = blockIdx.z;
    const int tx = threadIdx.x, ty = threadIdx.y;
    const float* src = x + ((size_t)b * KDIM + k0) * S + n0;
#pragma unroll
    for (int i = 0; i < 4; i++)
        t[ty + 8 * i][tx] = src[(size_t)(ty + 8 * i) * S + tx];
    __syncthreads();
    __nv_bfloat16* dh = oh + ((size_t)b * S + n0) * KDIM + k0;
    __nv_bfloat16* dl = ol + ((size_t)b * S + n0) * KDIM + k0;
#pragma unroll
    for (int i = 0; i < 4; i++) {
        float v = t[tx][ty + 8 * i];
        __nv_bfloat16 hi = __float2bfloat16_rn(v);
        dh[(size_t)(ty + 8 * i) * KDIM + tx] = hi;
        dl[(size_t)(ty + 8 * i) * KDIM + tx] =
            __float2bfloat16_rn(v - __bfloat162float(hi));
    }
}

// ---------------------------------------------------------------------------
// HMMA bf16 3x-split batched GEMM.
// 3-stage cp.async pipeline, ONE __syncthreads per chunk, 2 CTAs/SM.
// CTA tile 128x128, 8 warps (32x64 warp tile), K chunks of 16.
// ---------------------------------------------------------------------------
#define NCH     32
#define STG_SZ  24576              // 4 tiles x 128 rows x 48B
#define T_AL    6144
#define T_BH    12288
#define T_BL    18432
#define GSMEM   (3 * STG_SZ)       // 73728 B

__global__ void __launch_bounds__(256, 2) gemm_mma_kernel(
    const __nv_bfloat16* __restrict__ Ah, const __nv_bfloat16* __restrict__ Al,
    const __nv_bfloat16* __restrict__ Bh, const __nv_bfloat16* __restrict__ Bl,
    float* __restrict__ C, const float* __restrict__ bias, int Ntot)
{
    extern __shared__ char smem[];
    const uint32_t sbase = smem_u32(smem);

    const int tid = threadIdx.x;
    const int n0 = blockIdx.x * 128;
    const int m0 = blockIdx.y * 128;
    const int M  = gridDim.y * 128;
    const size_t bo = (size_t)blockIdx.z * Ntot * KDIM;
    const size_t co = (size_t)blockIdx.z * M * Ntot;

    const __nv_bfloat16* Bhb = Bh + bo;
    const __nv_bfloat16* Blb = Bl + bo;

    const int lrow = tid >> 1, lhalf = tid & 1;
    const uint32_t lso = (uint32_t)(lrow * 48 + lhalf * 16);

    const int wid = tid >> 5, lane = tid & 31;
    const int wm = (wid & 3) * 32, wn = (wid >> 2) * 64;
    const uint32_t aoff = (uint32_t)((wm + (lane & 15)) * 48 + (lane >> 4) * 16);
    const uint32_t boff = (uint32_t)(T_BH + (wn + (lane & 15)) * 48 + (lane >> 4) * 16);

    float acc[2][8][4];
#pragma unroll
    for (int f = 0; f < 2; f++)
#pragma unroll
        for (int j = 0; j < 8; j++)
#pragma unroll
            for (int r = 0; r < 4; r++) acc[f][j][r] = 0.f;

#define ISSUE(cc, st) do {                                                    \
        const size_t ga = (size_t)(m0 + lrow) * KDIM + (cc) * 16 + lhalf * 8; \
        const size_t gb = (size_t)(n0 + lrow) * KDIM + (cc) * 16 + lhalf * 8; \
        const uint32_t sb = sbase + (st) * STG_SZ + lso;                      \
        cpasync16(sb,         Ah  + ga);                                      \
        cpasync16(sb + T_AL,  Al  + ga);                                      \
        cpasync16(sb + T_BH,  Bhb + gb);                                      \
        cpasync16(sb + T_BL,  Blb + gb);                                      \
    } while (0)

    // prologue: stages 0,1
    ISSUE(0, 0); CP_COMMIT();
    ISSUE(1, 1); CP_COMMIT();

    int st = 0;          // stage of chunk c
    int stn = 2;         // stage of chunk c+2
    for (int c = 0; c < NCH; c++) {
        CP_WAIT(1);                     // chunk c resident
        __syncthreads();                // all warps done reading stage stn (=c-1)
        if (c + 2 < NCH) ISSUE(c + 2, stn);
        CP_COMMIT();

        const uint32_t sa = sbase + (uint32_t)(st * STG_SZ);
        uint32_t ah[2][4], al[2][4];
        LDSM_X4(ah[0], sa + aoff);
        LDSM_X4(ah[1], sa + aoff + 768);
        LDSM_X4(al[0], sa + aoff + T_AL);
        LDSM_X4(al[1], sa + aoff + T_AL + 768);
#pragma unroll
        for (int g = 0; g < 4; g++) {
            uint32_t bh[4], bl[4];
            LDSM_X4(bh, sa + boff + g * 768);
            LDSM_X4(bl, sa + boff + g * 768 + T_AL);
#pragma unroll
            for (int f = 0; f < 2; f++) {
                mma_bf16(acc[f][2 * g],     ah[f], bh[0], bh[2]);
                mma_bf16(acc[f][2 * g],     al[f], bh[0], bh[2]);
                mma_bf16(acc[f][2 * g],     ah[f], bl[0], bl[2]);
                mma_bf16(acc[f][2 * g + 1], ah[f], bh[1], bh[3]);
                mma_bf16(acc[f][2 * g + 1], al[f], bh[1], bh[3]);
                mma_bf16(acc[f][2 * g + 1], ah[f], bl[1], bl[3]);
            }
        }
        st = (st == 2) ? 0 : st + 1;
        stn = (stn == 2) ? 0 : stn + 1;
    }
#undef ISSUE

#pragma unroll
    for (int f = 0; f < 2; f++) {
        const int r0 = m0 + wm + f * 16 + (lane >> 2);
        const float bv0 = bias ? bias[r0] : 0.f;
        const float bv1 = bias ? bias[r0 + 8] : 0.f;
        float* cp0 = C + co + (size_t)r0 * Ntot;
        float* cp1 = cp0 + (size_t)8 * Ntot;
#pragma unroll
        for (int j = 0; j < 8; j++) {
            const int col = n0 + wn + j * 8 + (lane & 3) * 2;
            float2 v0 = make_float2(acc[f][j][0] + bv0, acc[f][j][1] + bv0);
            float2 v1 = make_float2(acc[f][j][2] + bv1, acc[f][j][3] + bv1);
            *(float2*)(cp0 + col) = v0;
            *(float2*)(cp1 + col) = v1;
        }
    }
}

// ---------------------------------------------------------------------------
// Pool + sigmoid gate -> fp16 hi/lo.  K: [b,h,n,d]  V: [b,h,d,n]
// ---------------------------------------------------------------------------
__global__ void __launch_bounds__(256) pool_kernel(
    const float* __restrict__ qkv,
    __half* __restrict__ khg, __half* __restrict__ klg,
    __half* __restrict__ vhg, __half* __restrict__ vlg)
{
    const int bc = blockIdx.x;
    const int b = bc >> 9;
    const int c = bc & 511;
    const int part = blockIdx.y;           // 0 = k, 1 = v
    const int bh = b * HEADS + (c >> 6);
    const int d  = c & 63;
    const float* src = qkv + ((size_t)b * QKVC + 512 + part * 512 + c) * S;

    __shared__ float ts[S];
    const int tid = threadIdx.x;
    ((float4*)ts)[tid] = ((const float4*)src)[tid];
    __syncthreads();

    auto store = [&](int n, float pooled) {
        const float sv = 1.f / (1.f + __expf(-pooled));
        const __half hi = __float2half_rn(sv);
        const __half lo = __float2half_rn(sv - __half2float(hi));
        if (part == 0) {
            const size_t idx = ((size_t)bh * NKV + n) * DH + d;
            khg[idx] = hi; klg[idx] = lo;
        } else {
            const size_t idx = ((size_t)bh * DH + d) * NKV + n;
            vhg[idx] = hi; vlg[idx] = lo;
        }
    };

    if (tid < 32) {
        float s = 0.f;
#pragma unroll
        for (int w = 0; w < 32; w++) s += ts[tid * 32 + w];
        store(tid, s * (1.f / 32.f));
    } else if (tid < 64) {
        const int w = tid - 32;
        float s = 0.f;
#pragma unroll
        for (int hh = 0; hh < 32; hh++) s += ts[hh * 32 + w];
        store(32 + (tid - 32), s * (1.f / 32.f));
    }
    {
        const int ph = tid >> 4, pw = tid & 15;
        const float s = ts[(2 * ph) * 32 + 2 * pw] + ts[(2 * ph) * 32 + 2 * pw + 1]
                      + ts[(2 * ph + 1) * 32 + 2 * pw] + ts[(2 * ph + 1) * 32 + 2 * pw + 1];
        store(64 + tid, s * 0.25f);
    }
}

// ---------------------------------------------------------------------------
// MMA attention (unchanged from R4)
// ---------------------------------------------------------------------------
#define TQ       64
#define Q_ROW    144
#define K_ROW    144
#define V_ROW    656
#define SC_ROWB  1296
#define A_SA_Q   0
#define A_Q_LO   9216
#define A_SA_K   18432
#define A_K_LO   46080
#define A_SA_V   18432
#define A_V_LO   41984
#define A_SA_SC  110592
#define A_SA_INV 193536
#define ATTN2_SMEM 193792

__global__ void __launch_bounds__(256, 1) attn_mma_kernel(
    const float* __restrict__ qkv,
    const __half* __restrict__ khg, const __half* __restrict__ klg,
    const __half* __restrict__ vhg, const __half* __restrict__ vlg,
    const float* __restrict__ pos,
    __nv_bfloat16* __restrict__ atth, __nv_bfloat16* __restrict__ attl)
{
    extern __shared__ char sm[];
    const uint32_t sb = smem_u32(sm);
    const int b = blockIdx.z, hd = blockIdx.y;
    const int s0 = blockIdx.x * TQ;
    const int tid = threadIdx.x, wid = tid >> 5, lane = tid & 31;

    {
        const char* kh = (const char*)(khg + (size_t)(b * HEADS + hd) * NKV * DH);
        const char* kl = (const char*)(klg + (size_t)(b * HEADS + hd) * NKV * DH);
#pragma unroll
        for (int i = 0; i < 10; i++) {
            const int c = tid + i * 256;
            const uint32_t dst = sb + A_SA_K + (c >> 3) * K_ROW + (c & 7) * 16;
            cpasync16(dst,          kh + (size_t)c * 16);
            cpasync16(dst + A_K_LO, kl + (size_t)c * 16);
        }
        CP_COMMIT();
    }
    {
        const float* qg = qkv + ((size_t)b * QKVC + hd * DH) * S + s0;
#pragma unroll
        for (int i = 0; i < 16; i++) {
            const int idx = tid + i * 256;
            const int dd = idx >> 6, si = idx & 63;
            const float v = qg[(size_t)dd * S + si] * 0.125f;
            const __half hi = __float2half_rn(v);
            *(__half*)(sm + A_SA_Q + si * Q_ROW + dd * 2) = hi;
            *(__half*)(sm + A_SA_Q + A_Q_LO + si * Q_ROW + dd * 2) =
                __float2half_rn(v - __half2float(hi));
        }
    }
    CP_WAIT(0);
    __syncthreads();

    const int m0w = (wid & 3) * 16;

    {
        const int n0w = (wid >> 2) * 160;
        float acc[20][4];
#pragma unroll
        for (int t = 0; t < 20; t++) {
            acc[t][0] = 0.f; acc[t][1] = 0.f; acc[t][2] = 0.f; acc[t][3] = 0.f;
        }
#pragma unroll
        for (int k = 0; k < 4; k++) {
            uint32_t ah[4], al[4];
            const uint32_t qa = sb + A_SA_Q + (m0w + (lane & 15)) * Q_ROW
                              + (lane >> 4) * 16 + k * 32;
            LDSM_X4(ah, qa);
            LDSM_X4(al, qa + A_Q_LO);
#pragma unroll
            for (int jn = 0; jn < 10; jn++) {
                uint32_t bh[4], bl[4];
                const uint32_t ka = sb + A_SA_K
                                  + (n0w + jn * 16 + (lane & 15)) * K_ROW
                                  + (lane >> 4) * 16 + k * 32;
                LDSM_X4(bh, ka);
                LDSM_X4(bl, ka + A_K_LO);
                mma_f16(acc[2 * jn],     ah, bh[0], bh[2]);
                mma_f16(acc[2 * jn],     al, bh[0], bh[2]);
                mma_f16(acc[2 * jn],     ah, bl[0], bl[2]);
                mma_f16(acc[2 * jn + 1], ah, bh[1], bh[3]);
                mma_f16(acc[2 * jn + 1], al, bh[1], bh[3]);
                mma_f16(acc[2 * jn + 1], ah, bl[1], bl[3]);
            }
        }
        const int r0 = m0w + (lane >> 2);
#pragma unroll
        for (int jn = 0; jn < 10; jn++)
#pragma unroll
            for (int t = 0; t < 2; t++) {
                const int n = n0w + jn * 16 + t * 8 + (lane & 3) * 2;
                float* p0 = (float*)(sm + A_SA_SC + r0 * SC_ROWB) + n;
                float* p1 = (float*)(sm + A_SA_SC + (r0 + 8) * SC_ROWB) + n;
                *(float2*)p0 = make_float2(acc[2 * jn + t][0], acc[2 * jn + t][1]);
                *(float2*)p1 = make_float2(acc[2 * jn + t][2], acc[2 * jn + t][3]);
            }
    }
    __syncthreads();

    {
        const char* vh = (const char*)(vhg + (size_t)(b * HEADS + hd) * DH * NKV);
        const char* vl = (const char*)(vlg + (size_t)(b * HEADS + hd) * DH * NKV);
#pragma unroll
        for (int i = 0; i < 10; i++) {
            const int c = tid + i * 256;
            const int d = c / 40, o = c % 40;
            const uint32_t dst = sb + A_SA_V + d * V_ROW + o * 16;
            cpasync16(dst,          vh + (size_t)c * 16);
            cpasync16(dst + A_V_LO, vl + (size_t)c * 16);
        }
        CP_COMMIT();
    }

    {
        const int r = tid >> 2, cq = tid & 3;
        float* row = (float*)(sm + A_SA_SC + r * SC_ROWB);
        __half* ph = (__half*)(sm + A_SA_SC + r * SC_ROWB);
        const float* pr = pos + (size_t)(s0 + r) * NKV;
        float mx = -1e30f;
        for (int k = cq; k < NKV; k += 4) {
            const float v = row[k] + pr[k];
            row[k] = v;
            mx = fmaxf(mx, v);
        }
        mx = fmaxf(mx, __shfl_xor_sync(0xffffffffu, mx, 1));
        mx = fmaxf(mx, __shfl_xor_sync(0xffffffffu, mx, 2));
        float ssum = 0.f;
#pragma unroll
        for (int c5 = 0; c5 < 5; c5++) {
            float e[16];
#pragma unroll
            for (int j = 0; j < 16; j++) {
                e[j] = __expf(row[c5 * 64 + cq + 4 * j] - mx);
                ssum += e[j];
            }
            __syncwarp();
#pragma unroll
            for (int j = 0; j < 16; j++)
                ph[c5 * 64 + cq + 4 * j] = __float2half_rn(e[j]);
            __syncwarp();
        }
        ssum += __shfl_xor_sync(0xffffffffu, ssum, 1);
        ssum += __shfl_xor_sync(0xffffffffu, ssum, 2);
        if (cq == 0) *(float*)(sm + A_SA_INV + r * 4) = 1.f / ssum;
    }
    CP_WAIT(0);
    __syncthreads();

    {
        const int dn0 = (wid >> 2) * 32;
        float oa[4][4];
#pragma unroll
        for (int t = 0; t < 4; t++) {
            oa[t][0] = 0.f; oa[t][1] = 0.f; oa[t][2] = 0.f; oa[t][3] = 0.f;
        }
#pragma unroll
        for (int k = 0; k < 20; k++) {
            uint32_t pa[4], v0h[4], v1h[4], v0l[4], v1l[4];
            LDSM_X4(pa, sb + A_SA_SC + (m0w + (lane & 15)) * SC_ROWB
                        + (lane >> 4) * 16 + k * 32);
            const uint32_t va = sb + A_SA_V + (dn0 + (lane & 15)) * V_ROW
                              + (lane >> 4) * 16 + k * 32;
            LDSM_X4(v0h, va);
            LDSM_X4(v0l, va + A_V_LO);
            LDSM_X4(v1h, va + 16 * V_ROW);
            LDSM_X4(v1l, va + 16 * V_ROW + A_V_LO);
            mma_f16(oa[0], pa, v0h[0], v0h[2]);
            mma_f16(oa[0], pa, v0l[0], v0l[2]);
            mma_f16(oa[1], pa, v0h[1], v0h[3]);
            mma_f16(oa[1], pa, v0l[1], v0l[3]);
            mma_f16(oa[2], pa, v1h[0], v1h[2]);
            mma_f16(oa[2], pa, v1l[0], v1l[2]);
            mma_f16(oa[3], pa, v1h[1], v1h[3]);
            mma_f16(oa[3], pa, v1l[1], v1l[3]);
        }
        const float inv0 = *(const float*)(sm + A_SA_INV + (m0w + (lane >> 2)) * 4);
        const float inv1 = *(const float*)(sm + A_SA_INV + (m0w + 8 + (lane >> 2)) * 4);
        const size_t ro0 = ((size_t)b * S + s0 + m0w + (lane >> 2)) * CIN + hd * DH;
        const size_t ro1 = ro0 + (size_t)8 * CIN;
#pragma unroll
        for (int jt = 0; jt < 4; jt++) {
            const int col = dn0 + jt * 8 + (lane & 3) * 2;
            const float v0 = oa[jt][0] * inv0, v1 = oa[jt][1] * inv0;
            const float v2 = oa[jt][2] * inv1, v3 = oa[jt][3] * inv1;
            __nv_bfloat162 h0 = __floats2bfloat162_rn(v0, v1);
            __nv_bfloat162 h1 = __floats2bfloat162_rn(v2, v3);
            __nv_bfloat162 l0 = __floats2bfloat162_rn(v0 - __bfloat162float(h0.x),
                                                      v1 - __bfloat162float(h0.y));
            __nv_bfloat162 l1 = __floats2bfloat162_rn(v2 - __bfloat162float(h1.x),
                                                      v3 - __bfloat162float(h1.y));
            *(__nv_bfloat162*)(atth + ro0 + col) = h0;
            *(__nv_bfloat162*)(attl + ro0 + col) = l0;
            *(__nv_bfloat162*)(atth + ro1 + col) = h1;
            *(__nv_bfloat162*)(attl + ro1 + col) = l1;
        }
    }
}

// ---------------------------------------------------------------------------
// Launch
// ---------------------------------------------------------------------------
extern "C" void kernel_launch(void* const* d_in, const int* in_sizes, int n_in,
                              void* d_out, int out_size)
{
    const float* x     = (const float*)d_in[0];
    const float* Wqkv  = (const float*)d_in[1];
    const float* Wout  = (const float*)d_in[2];
    const float* bout  = (const float*)d_in[3];
    const float* pos   = (const float*)d_in[4];
    float* out = (float*)d_out;

    float *p_qkv;
    __half *p_kh, *p_kl, *p_vh, *p_vl;
    __nv_bfloat16 *p_xh, *p_xl, *p_ath, *p_atl, *p_wqh, *p_wql, *p_woh, *p_wol;
    cudaGetSymbolAddress((void**)&p_qkv, g_qkv);
    cudaGetSymbolAddress((void**)&p_xh,  g_xh);
    cudaGetSymbolAddress((void**)&p_xl,  g_xl);
    cudaGetSymbolAddress((void**)&p_kh,  g_kh);
    cudaGetSymbolAddress((void**)&p_kl,  g_kl);
    cudaGetSymbolAddress((void**)&p_vh,  g_vh);
    cudaGetSymbolAddress((void**)&p_vl,  g_vl);
    cudaGetSymbolAddress((void**)&p_ath, g_ath);
    cudaGetSymbolAddress((void**)&p_atl, g_atl);
    cudaGetSymbolAddress((void**)&p_wqh, g_wqh);
    cudaGetSymbolAddress((void**)&p_wql, g_wql);
    cudaGetSymbolAddress((void**)&p_woh, g_woh);
    cudaGetSymbolAddress((void**)&p_wol, g_wol);

    cudaFuncSetAttribute(gemm_mma_kernel,
                         cudaFuncAttributeMaxDynamicSharedMemorySize, GSMEM);
    cudaFuncSetAttribute(attn_mma_kernel,
                         cudaFuncAttributeMaxDynamicSharedMemorySize, ATTN2_SMEM);

    // 0) operand prep
    split_kernel<<<(QKVC * KDIM + 255) / 256, 256>>>(Wqkv, p_wqh, p_wql, QKVC * KDIM);
    split_kernel<<<(COUT * KDIM + 255) / 256, 256>>>(Wout, p_woh, p_wol, COUT * KDIM);
    tsplit_kernel<<<dim3(S / 32, KDIM / 32, BATCH), dim3(32, 8)>>>(x, p_xh, p_xl);

    // 1) qkv = Wqkv @ x^T   [B,1536,1024]
    gemm_mma_kernel<<<dim3(S / 128, QKVC / 128, BATCH), 256, GSMEM>>>(
        p_wqh, p_wql, p_xh, p_xl, p_qkv, nullptr, S);

    // 2) pool + sigmoid gates -> fp16 hi/lo K,V
    pool_kernel<<<dim3(BATCH * CIN, 2), 256>>>(p_qkv, p_kh, p_kl, p_vh, p_vl);

    // 3) tensor-core attention -> att hi/lo bf16 [B,S,C]
    attn_mma_kernel<<<dim3(S / TQ, HEADS, BATCH), 256, ATTN2_SMEM>>>(
        p_qkv, p_kh, p_kl, p_vh, p_vl, pos, p_ath, p_atl);

    // 4) out = Wout @ att^T + bout   [B,512,1024]
    gemm_mma_kernel<<<dim3(S / 128, COUT / 128, BATCH), 256, GSMEM>>>(
        p_woh, p_wol, p_ath, p_atl, out, bout, S);
}

// round 6
// speedup vs baseline: 2.8256x; 1.1965x over previous
#include <cuda_runtime.h>
#include <cuda_bf16.h>
#include <cuda_fp16.h>
#include <math.h>
#include <stdint.h>

// ---------------------------------------------------------------------------
// Problem constants
// ---------------------------------------------------------------------------
#define BATCH   32
#define CIN     512
#define COUT    512
#define HEADS   8
#define DH      64
#define S       1024
#define NKV     320
#define QKVC    1536
#define KDIM    512

// ---------------------------------------------------------------------------
// Scratch (device globals)
// ---------------------------------------------------------------------------
__device__ float g_qkv[(size_t)BATCH * QKVC * S];                        // [B,1536,1024]
__device__ __align__(16) __nv_bfloat16 g_xh [(size_t)BATCH * S * KDIM];
__device__ __align__(16) __nv_bfloat16 g_xl [(size_t)BATCH * S * KDIM];
__device__ __align__(16) __half g_kh[(size_t)BATCH * HEADS * NKV * DH];  // K fp16 [b,h,n,d]
__device__ __align__(16) __half g_vh[(size_t)BATCH * HEADS * DH * NKV];  // V fp16 [b,h,d,n]
__device__ __align__(16) __nv_bfloat16 g_ath[(size_t)BATCH * S * CIN];   // att hi [B,S,C]
__device__ __align__(16) __nv_bfloat16 g_atl[(size_t)BATCH * S * CIN];
__device__ __align__(16) __nv_bfloat16 g_wqh[(size_t)QKVC * KDIM];
__device__ __align__(16) __nv_bfloat16 g_wql[(size_t)QKVC * KDIM];
__device__ __align__(16) __nv_bfloat16 g_woh[(size_t)COUT * KDIM];
__device__ __align__(16) __nv_bfloat16 g_wol[(size_t)COUT * KDIM];

// ---------------------------------------------------------------------------
// PTX helpers
// ---------------------------------------------------------------------------
__device__ __forceinline__ uint32_t smem_u32(const void* p) {
    uint32_t a;
    asm("{ .reg .u64 t; cvta.to.shared.u64 t, %1; cvt.u32.u64 %0, t; }"
        : "=r"(a) : "l"(p));
    return a;
}
__device__ __forceinline__ void cpasync16(uint32_t s, const void* g) {
    asm volatile("cp.async.cg.shared.global [%0], [%1], 16;" :: "r"(s), "l"(g));
}
#define CP_COMMIT() asm volatile("cp.async.commit_group;" ::: "memory")
#define CP_WAIT(N)  asm volatile("cp.async.wait_group %0;" :: "n"(N) : "memory")

#define LDSM_X4(r, addr) \
    asm volatile("ldmatrix.sync.aligned.m8n8.x4.shared.b16 {%0,%1,%2,%3}, [%4];" \
                 : "=r"((r)[0]), "=r"((r)[1]), "=r"((r)[2]), "=r"((r)[3]) : "r"(addr))

__device__ __forceinline__ void mma_bf16(float* d, const uint32_t* a,
                                         uint32_t b0, uint32_t b1) {
    asm volatile(
        "mma.sync.aligned.m16n8k16.row.col.f32.bf16.bf16.f32 "
        "{%0,%1,%2,%3}, {%4,%5,%6,%7}, {%8,%9}, {%0,%1,%2,%3};"
        : "+f"(d[0]), "+f"(d[1]), "+f"(d[2]), "+f"(d[3])
        : "r"(a[0]), "r"(a[1]), "r"(a[2]), "r"(a[3]), "r"(b0), "r"(b1));
}
__device__ __forceinline__ void mma_f16(float* d, const uint32_t* a,
                                        uint32_t b0, uint32_t b1) {
    asm volatile(
        "mma.sync.aligned.m16n8k16.row.col.f32.f16.f16.f32 "
        "{%0,%1,%2,%3}, {%4,%5,%6,%7}, {%8,%9}, {%0,%1,%2,%3};"
        : "+f"(d[0]), "+f"(d[1]), "+f"(d[2]), "+f"(d[3])
        : "r"(a[0]), "r"(a[1]), "r"(a[2]), "r"(a[3]), "r"(b0), "r"(b1));
}

// ---------------------------------------------------------------------------
// fp32 -> bf16 hi/lo split (weights) ; transpose+split for x
// ---------------------------------------------------------------------------
__global__ void split_kernel(const float* __restrict__ a,
                             __nv_bfloat16* __restrict__ h,
                             __nv_bfloat16* __restrict__ l, int n)
{
    int i = blockIdx.x * 256 + threadIdx.x;
    if (i < n) {
        float v = a[i];
        __nv_bfloat16 hi = __float2bfloat16_rn(v);
        h[i] = hi;
        l[i] = __float2bfloat16_rn(v - __bfloat162float(hi));
    }
}

__global__ void __launch_bounds__(256) tsplit_kernel(
    const float* __restrict__ x,
    __nv_bfloat16* __restrict__ oh, __nv_bfloat16* __restrict__ ol)
{
    __shared__ float t[32][33];
    const int n0 = blockIdx.x * 32, k0 = blockIdx.y * 32, b = blockIdx.z;
    const int tx = threadIdx.x, ty = threadIdx.y;
    const float* src = x + ((size_t)b * KDIM + k0) * S + n0;
#pragma unroll
    for (int i = 0; i < 4; i++)
        t[ty + 8 * i][tx] = src[(size_t)(ty + 8 * i) * S + tx];
    __syncthreads();
    __nv_bfloat16* dh = oh + ((size_t)b * S + n0) * KDIM + k0;
    __nv_bfloat16* dl = ol + ((size_t)b * S + n0) * KDIM + k0;
#pragma unroll
    for (int i = 0; i < 4; i++) {
        float v = t[tx][ty + 8 * i];
        __nv_bfloat16 hi = __float2bfloat16_rn(v);
        dh[(size_t)(ty + 8 * i) * KDIM + tx] = hi;
        dl[(size_t)(ty + 8 * i) * KDIM + tx] =
            __float2bfloat16_rn(v - __bfloat162float(hi));
    }
}

// ---------------------------------------------------------------------------
// HMMA bf16 3x-split batched GEMM (unchanged from R5).
// ---------------------------------------------------------------------------
#define NCH     32
#define STG_SZ  24576
#define T_AL    6144
#define T_BH    12288
#define T_BL    18432
#define GSMEM   (3 * STG_SZ)

__global__ void __launch_bounds__(256, 2) gemm_mma_kernel(
    const __nv_bfloat16* __restrict__ Ah, const __nv_bfloat16* __restrict__ Al,
    const __nv_bfloat16* __restrict__ Bh, const __nv_bfloat16* __restrict__ Bl,
    float* __restrict__ C, const float* __restrict__ bias, int Ntot)
{
    extern __shared__ char smem[];
    const uint32_t sbase = smem_u32(smem);

    const int tid = threadIdx.x;
    const int n0 = blockIdx.x * 128;
    const int m0 = blockIdx.y * 128;
    const int M  = gridDim.y * 128;
    const size_t bo = (size_t)blockIdx.z * Ntot * KDIM;
    const size_t co = (size_t)blockIdx.z * M * Ntot;

    const __nv_bfloat16* Bhb = Bh + bo;
    const __nv_bfloat16* Blb = Bl + bo;

    const int lrow = tid >> 1, lhalf = tid & 1;
    const uint32_t lso = (uint32_t)(lrow * 48 + lhalf * 16);

    const int wid = tid >> 5, lane = tid & 31;
    const int wm = (wid & 3) * 32, wn = (wid >> 2) * 64;
    const uint32_t aoff = (uint32_t)((wm + (lane & 15)) * 48 + (lane >> 4) * 16);
    const uint32_t boff = (uint32_t)(T_BH + (wn + (lane & 15)) * 48 + (lane >> 4) * 16);

    float acc[2][8][4];
#pragma unroll
    for (int f = 0; f < 2; f++)
#pragma unroll
        for (int j = 0; j < 8; j++)
#pragma unroll
            for (int r = 0; r < 4; r++) acc[f][j][r] = 0.f;

#define ISSUE(cc, st) do {                                                    \
        const size_t ga = (size_t)(m0 + lrow) * KDIM + (cc) * 16 + lhalf * 8; \
        const size_t gb = (size_t)(n0 + lrow) * KDIM + (cc) * 16 + lhalf * 8; \
        const uint32_t sb = sbase + (st) * STG_SZ + lso;                      \
        cpasync16(sb,         Ah  + ga);                                      \
        cpasync16(sb + T_AL,  Al  + ga);                                      \
        cpasync16(sb + T_BH,  Bhb + gb);                                      \
        cpasync16(sb + T_BL,  Blb + gb);                                      \
    } while (0)

    ISSUE(0, 0); CP_COMMIT();
    ISSUE(1, 1); CP_COMMIT();

    int st = 0;
    int stn = 2;
    for (int c = 0; c < NCH; c++) {
        CP_WAIT(1);
        __syncthreads();
        if (c + 2 < NCH) ISSUE(c + 2, stn);
        CP_COMMIT();

        const uint32_t sa = sbase + (uint32_t)(st * STG_SZ);
        uint32_t ah[2][4], al[2][4];
        LDSM_X4(ah[0], sa + aoff);
        LDSM_X4(ah[1], sa + aoff + 768);
        LDSM_X4(al[0], sa + aoff + T_AL);
        LDSM_X4(al[1], sa + aoff + T_AL + 768);
#pragma unroll
        for (int g = 0; g < 4; g++) {
            uint32_t bh[4], bl[4];
            LDSM_X4(bh, sa + boff + g * 768);
            LDSM_X4(bl, sa + boff + g * 768 + T_AL);
#pragma unroll
            for (int f = 0; f < 2; f++) {
                mma_bf16(acc[f][2 * g],     ah[f], bh[0], bh[2]);
                mma_bf16(acc[f][2 * g],     al[f], bh[0], bh[2]);
                mma_bf16(acc[f][2 * g],     ah[f], bl[0], bl[2]);
                mma_bf16(acc[f][2 * g + 1], ah[f], bh[1], bh[3]);
                mma_bf16(acc[f][2 * g + 1], al[f], bh[1], bh[3]);
                mma_bf16(acc[f][2 * g + 1], ah[f], bl[1], bl[3]);
            }
        }
        st = (st == 2) ? 0 : st + 1;
        stn = (stn == 2) ? 0 : stn + 1;
    }
#undef ISSUE

#pragma unroll
    for (int f = 0; f < 2; f++) {
        const int r0 = m0 + wm + f * 16 + (lane >> 2);
        const float bv0 = bias ? bias[r0] : 0.f;
        const float bv1 = bias ? bias[r0 + 8] : 0.f;
        float* cp0 = C + co + (size_t)r0 * Ntot;
        float* cp1 = cp0 + (size_t)8 * Ntot;
#pragma unroll
        for (int j = 0; j < 8; j++) {
            const int col = n0 + wn + j * 8 + (lane & 3) * 2;
            float2 v0 = make_float2(acc[f][j][0] + bv0, acc[f][j][1] + bv0);
            float2 v1 = make_float2(acc[f][j][2] + bv1, acc[f][j][3] + bv1);
            *(float2*)(cp0 + col) = v0;
            *(float2*)(cp1 + col) = v1;
        }
    }
}

// ---------------------------------------------------------------------------
// Pool + sigmoid gate -> single fp16.  K: [b,h,n,d]  V: [b,h,d,n]
// ---------------------------------------------------------------------------
__global__ void __launch_bounds__(256) pool_kernel(
    const float* __restrict__ qkv,
    __half* __restrict__ khg, __half* __restrict__ vhg)
{
    const int bc = blockIdx.x;
    const int b = bc >> 9;
    const int c = bc & 511;
    const int part = blockIdx.y;           // 0 = k, 1 = v
    const int bh = b * HEADS + (c >> 6);
    const int d  = c & 63;
    const float* src = qkv + ((size_t)b * QKVC + 512 + part * 512 + c) * S;

    __shared__ float ts[S];
    const int tid = threadIdx.x;
    ((float4*)ts)[tid] = ((const float4*)src)[tid];
    __syncthreads();

    auto store = [&](int n, float pooled) {
        const float sv = 1.f / (1.f + __expf(-pooled));
        const __half hv = __float2half_rn(sv);
        if (part == 0) khg[((size_t)bh * NKV + n) * DH + d] = hv;
        else           vhg[((size_t)bh * DH + d) * NKV + n] = hv;
    };

    if (tid < 32) {
        float s = 0.f;
#pragma unroll
        for (int w = 0; w < 32; w++) s += ts[tid * 32 + w];
        store(tid, s * (1.f / 32.f));
    } else if (tid < 64) {
        const int w = tid - 32;
        float s = 0.f;
#pragma unroll
        for (int hh = 0; hh < 32; hh++) s += ts[hh * 32 + w];
        store(tid, s * (1.f / 32.f));
    }
    {
        const int ph = tid >> 4, pw = tid & 15;
        const float s = ts[(2 * ph) * 32 + 2 * pw] + ts[(2 * ph) * 32 + 2 * pw + 1]
                      + ts[(2 * ph + 1) * 32 + 2 * pw] + ts[(2 * ph + 1) * 32 + 2 * pw + 1];
        store(64 + tid, s * 0.25f);
    }
}

// ---------------------------------------------------------------------------
// MMA attention v2: TQ=32, single-fp16 K/V, Q hi/lo, 2 CTAs/SM.
// smem: Q (hi/lo) | K [n][d] (V [d][n] overlays after QK^T) | scores fp32 | inv
// ---------------------------------------------------------------------------
#define TQ       32
#define Q_ROW    144
#define K_ROW    144
#define V_ROW    656
#define SC_ROWB  1296          // 324 floats
#define A_Q      0
#define A_Q_LO   4608
#define A_K      9216
#define A_V      9216          // overlays K (dead after QK^T)
#define A_SC     55296
#define A_INV    96768
#define ATTN2_SMEM 96896

__global__ void __launch_bounds__(256, 2) attn_mma_kernel(
    const float* __restrict__ qkv,
    const __half* __restrict__ khg, const __half* __restrict__ vhg,
    const float* __restrict__ pos,
    __nv_bfloat16* __restrict__ atth, __nv_bfloat16* __restrict__ attl)
{
    extern __shared__ char sm[];
    const uint32_t sb = smem_u32(sm);
    const int b = blockIdx.z, hd = blockIdx.y;
    const int s0 = blockIdx.x * TQ;
    const int tid = threadIdx.x, wid = tid >> 5, lane = tid & 31;

    // ---- K via cp.async: [n][d], 320 rows x 128B ----
    {
        const char* kh = (const char*)(khg + (size_t)(b * HEADS + hd) * NKV * DH);
#pragma unroll
        for (int i = 0; i < 10; i++) {
            const int c = tid + i * 256;
            cpasync16(sb + A_K + (c >> 3) * K_ROW + (c & 7) * 16,
                      kh + (size_t)c * 16);
        }
        CP_COMMIT();
    }
    // ---- Q: fp32 load, scale, split fp16 hi/lo into [si][dd] ----
    {
        const float* qg = qkv + ((size_t)b * QKVC + hd * DH) * S + s0;
#pragma unroll
        for (int i = 0; i < 8; i++) {
            const int idx = tid + i * 256;
            const int dd = idx >> 5, si = idx & 31;
            const float v = qg[(size_t)dd * S + si] * 0.125f;
            const __half hi = __float2half_rn(v);
            *(__half*)(sm + A_Q + si * Q_ROW + dd * 2) = hi;
            *(__half*)(sm + A_Q + A_Q_LO + si * Q_ROW + dd * 2) =
                __float2half_rn(v - __half2float(hi));
        }
    }
    CP_WAIT(0);
    __syncthreads();

    const int mw = wid & 1;          // 2 m-tiles of 16 rows

    // ---- QK^T: warp = (m16, n80); 2-term (Qh + Ql) x K ----
    {
        const int n0w = (wid >> 1) * 80;     // 4 n-groups of 80
        float acc[10][4];
#pragma unroll
        for (int t = 0; t < 10; t++) {
            acc[t][0] = 0.f; acc[t][1] = 0.f; acc[t][2] = 0.f; acc[t][3] = 0.f;
        }
#pragma unroll
        for (int k = 0; k < 4; k++) {
            uint32_t ah[4], al[4];
            const uint32_t qa = sb + A_Q + (mw * 16 + (lane & 15)) * Q_ROW
                              + (lane >> 4) * 16 + k * 32;
            LDSM_X4(ah, qa);
            LDSM_X4(al, qa + A_Q_LO);
#pragma unroll
            for (int jn = 0; jn < 5; jn++) {
                uint32_t bh[4];
                LDSM_X4(bh, sb + A_K + (n0w + jn * 16 + (lane & 15)) * K_ROW
                            + (lane >> 4) * 16 + k * 32);
                mma_f16(acc[2 * jn],     ah, bh[0], bh[2]);
                mma_f16(acc[2 * jn],     al, bh[0], bh[2]);
                mma_f16(acc[2 * jn + 1], ah, bh[1], bh[3]);
                mma_f16(acc[2 * jn + 1], al, bh[1], bh[3]);
            }
        }
        const int r0 = mw * 16 + (lane >> 2);
#pragma unroll
        for (int jn = 0; jn < 5; jn++)
#pragma unroll
            for (int t = 0; t < 2; t++) {
                const int n = n0w + jn * 16 + t * 8 + (lane & 3) * 2;
                float* p0 = (float*)(sm + A_SC + r0 * SC_ROWB) + n;
                float* p1 = (float*)(sm + A_SC + (r0 + 8) * SC_ROWB) + n;
                *(float2*)p0 = make_float2(acc[2 * jn + t][0], acc[2 * jn + t][1]);
                *(float2*)p1 = make_float2(acc[2 * jn + t][2], acc[2 * jn + t][3]);
            }
    }
    __syncthreads();

    // ---- V into dead K region: [d][n], 64 rows x 640B ----
    {
        const char* vh = (const char*)(vhg + (size_t)(b * HEADS + hd) * DH * NKV);
#pragma unroll
        for (int i = 0; i < 10; i++) {
            const int c = tid + i * 256;
            const int d = c / 40, o = c % 40;
            cpasync16(sb + A_V + d * V_ROW + o * 16, vh + (size_t)c * 16);
        }
        CP_COMMIT();
    }

    // ---- softmax: 8 threads/row; P = exp(sc-max) fp16 in place; inv saved ----
    {
        const int r = tid >> 3, cq = tid & 7;
        float* row = (float*)(sm + A_SC + r * SC_ROWB);
        __half* ph = (__half*)(sm + A_SC + r * SC_ROWB);
        const float* pr = pos + (size_t)(s0 + r) * NKV;
        float mx = -1e30f;
#pragma unroll
        for (int k = cq; k < NKV; k += 8) {
            const float v = row[k] + pr[k];
            row[k] = v;
            mx = fmaxf(mx, v);
        }
        mx = fmaxf(mx, __shfl_xor_sync(0xffffffffu, mx, 1));
        mx = fmaxf(mx, __shfl_xor_sync(0xffffffffu, mx, 2));
        mx = fmaxf(mx, __shfl_xor_sync(0xffffffffu, mx, 4));
        float ssum = 0.f;
#pragma unroll
        for (int c5 = 0; c5 < 5; c5++) {
            float e[8];
#pragma unroll
            for (int j = 0; j < 8; j++) {
                e[j] = __expf(row[c5 * 64 + cq + 8 * j] - mx);
                ssum += e[j];
            }
            __syncwarp();
#pragma unroll
            for (int j = 0; j < 8; j++)
                ph[c5 * 64 + cq + 8 * j] = __float2half_rn(e[j]);
            __syncwarp();
        }
        ssum += __shfl_xor_sync(0xffffffffu, ssum, 1);
        ssum += __shfl_xor_sync(0xffffffffu, ssum, 2);
        ssum += __shfl_xor_sync(0xffffffffu, ssum, 4);
        if (cq == 0) *(float*)(sm + A_INV + r * 4) = 1.f / ssum;
    }
    CP_WAIT(0);
    __syncthreads();

    // ---- AV: warp = (m16, d16); single-V ----
    {
        const int dw = wid >> 1;             // 4 d-groups of 16
        float oa[2][4];
        oa[0][0] = oa[0][1] = oa[0][2] = oa[0][3] = 0.f;
        oa[1][0] = oa[1][1] = oa[1][2] = oa[1][3] = 0.f;
#pragma unroll
        for (int k = 0; k < 20; k++) {
            uint32_t pa[4], vv[4];
            LDSM_X4(pa, sb + A_SC + (mw * 16 + (lane & 15)) * SC_ROWB
                        + (lane >> 4) * 16 + k * 32);
            LDSM_X4(vv, sb + A_V + (dw * 16 + (lane & 15)) * V_ROW
                        + (lane >> 4) * 16 + k * 32);
            mma_f16(oa[0], pa, vv[0], vv[2]);
            mma_f16(oa[1], pa, vv[1], vv[3]);
        }
        const float inv0 = *(const float*)(sm + A_INV + (mw * 16 + (lane >> 2)) * 4);
        const float inv1 = *(const float*)(sm + A_INV + (mw * 16 + 8 + (lane >> 2)) * 4);
        const size_t ro0 = ((size_t)b * S + s0 + mw * 16 + (lane >> 2)) * CIN + hd * DH;
        const size_t ro1 = ro0 + (size_t)8 * CIN;
#pragma unroll
        for (int jt = 0; jt < 2; jt++) {
            const int col = dw * 16 + jt * 8 + (lane & 3) * 2;
            const float v0 = oa[jt][0] * inv0, v1 = oa[jt][1] * inv0;
            const float v2 = oa[jt][2] * inv1, v3 = oa[jt][3] * inv1;
            __nv_bfloat162 h0 = __floats2bfloat162_rn(v0, v1);
            __nv_bfloat162 h1 = __floats2bfloat162_rn(v2, v3);
            __nv_bfloat162 l0 = __floats2bfloat162_rn(v0 - __bfloat162float(h0.x),
                                                      v1 - __bfloat162float(h0.y));
            __nv_bfloat162 l1 = __floats2bfloat162_rn(v2 - __bfloat162float(h1.x),
                                                      v3 - __bfloat162float(h1.y));
            *(__nv_bfloat162*)(atth + ro0 + col) = h0;
            *(__nv_bfloat162*)(attl + ro0 + col) = l0;
            *(__nv_bfloat162*)(atth + ro1 + col) = h1;
            *(__nv_bfloat162*)(attl + ro1 + col) = l1;
        }
    }
}

// ---------------------------------------------------------------------------
// Launch
// ---------------------------------------------------------------------------
extern "C" void kernel_launch(void* const* d_in, const int* in_sizes, int n_in,
                              void* d_out, int out_size)
{
    const float* x     = (const float*)d_in[0];
    const float* Wqkv  = (const float*)d_in[1];
    const float* Wout  = (const float*)d_in[2];
    const float* bout  = (const float*)d_in[3];
    const float* pos   = (const float*)d_in[4];
    float* out = (float*)d_out;

    float *p_qkv;
    __half *p_kh, *p_vh;
    __nv_bfloat16 *p_xh, *p_xl, *p_ath, *p_atl, *p_wqh, *p_wql, *p_woh, *p_wol;
    cudaGetSymbolAddress((void**)&p_qkv, g_qkv);
    cudaGetSymbolAddress((void**)&p_xh,  g_xh);
    cudaGetSymbolAddress((void**)&p_xl,  g_xl);
    cudaGetSymbolAddress((void**)&p_kh,  g_kh);
    cudaGetSymbolAddress((void**)&p_vh,  g_vh);
    cudaGetSymbolAddress((void**)&p_ath, g_ath);
    cudaGetSymbolAddress((void**)&p_atl, g_atl);
    cudaGetSymbolAddress((void**)&p_wqh, g_wqh);
    cudaGetSymbolAddress((void**)&p_wql, g_wql);
    cudaGetSymbolAddress((void**)&p_woh, g_woh);
    cudaGetSymbolAddress((void**)&p_wol, g_wol);

    cudaFuncSetAttribute(gemm_mma_kernel,
                         cudaFuncAttributeMaxDynamicSharedMemorySize, GSMEM);
    cudaFuncSetAttribute(attn_mma_kernel,
                         cudaFuncAttributeMaxDynamicSharedMemorySize, ATTN2_SMEM);

    // 0) operand prep
    split_kernel<<<(QKVC * KDIM + 255) / 256, 256>>>(Wqkv, p_wqh, p_wql, QKVC * KDIM);
    split_kernel<<<(COUT * KDIM + 255) / 256, 256>>>(Wout, p_woh, p_wol, COUT * KDIM);
    tsplit_kernel<<<dim3(S / 32, KDIM / 32, BATCH), dim3(32, 8)>>>(x, p_xh, p_xl);

    // 1) qkv = Wqkv @ x^T   [B,1536,1024]
    gemm_mma_kernel<<<dim3(S / 128, QKVC / 128, BATCH), 256, GSMEM>>>(
        p_wqh, p_wql, p_xh, p_xl, p_qkv, nullptr, S);

    // 2) pool + sigmoid gates -> fp16 K,V
    pool_kernel<<<dim3(BATCH * CIN, 2), 256>>>(p_qkv, p_kh, p_vh);

    // 3) tensor-core attention -> att hi/lo bf16 [B,S,C]
    attn_mma_kernel<<<dim3(S / TQ, HEADS, BATCH), 256, ATTN2_SMEM>>>(
        p_qkv, p_kh, p_vh, pos, p_ath, p_atl);

    // 4) out = Wout @ att^T + bout   [B,512,1024]
    gemm_mma_kernel<<<dim3(S / 128, COUT / 128, BATCH), 256, GSMEM>>>(
        p_woh, p_wol, p_ath, p_atl, out, bout, S);
}

// round 7
// speedup vs baseline: 3.6037x; 1.2754x over previous
#include <cuda_runtime.h>
#include <cuda_bf16.h>
#include <cuda_fp16.h>
#include <math.h>
#include <stdint.h>

// ---------------------------------------------------------------------------
// Problem constants
// ---------------------------------------------------------------------------
#define BATCH   32
#define CIN     512
#define COUT    512
#define HEADS   8
#define DH      64
#define S       1024
#define NKV     320
#define QKVC    1536
#define KDIM    512

// ---------------------------------------------------------------------------
// Scratch (device globals)
// ---------------------------------------------------------------------------
__device__ float g_qkv[(size_t)BATCH * QKVC * S];                        // [B,1536,1024]
__device__ __align__(16) __half g_x  [(size_t)BATCH * S * KDIM];         // xT fp16 [B,1024,512]
__device__ __align__(16) __half g_kh [(size_t)BATCH * HEADS * NKV * DH]; // K fp16 [b,h,n,d]
__device__ __align__(16) __half g_vh [(size_t)BATCH * HEADS * DH * NKV]; // V fp16 [b,h,d,n]
__device__ __align__(16) __half g_at [(size_t)BATCH * S * CIN];          // att fp16 [B,S,C]
__device__ __align__(16) __half g_wqh[(size_t)QKVC * KDIM];
__device__ __align__(16) __half g_wql[(size_t)QKVC * KDIM];
__device__ __align__(16) __half g_woh[(size_t)COUT * KDIM];
__device__ __align__(16) __half g_wol[(size_t)COUT * KDIM];

// ---------------------------------------------------------------------------
// PTX helpers
// ---------------------------------------------------------------------------
__device__ __forceinline__ uint32_t smem_u32(const void* p) {
    uint32_t a;
    asm("{ .reg .u64 t; cvta.to.shared.u64 t, %1; cvt.u32.u64 %0, t; }"
        : "=r"(a) : "l"(p));
    return a;
}
__device__ __forceinline__ void cpasync16(uint32_t s, const void* g) {
    asm volatile("cp.async.cg.shared.global [%0], [%1], 16;" :: "r"(s), "l"(g));
}
#define CP_COMMIT() asm volatile("cp.async.commit_group;" ::: "memory")
#define CP_WAIT(N)  asm volatile("cp.async.wait_group %0;" :: "n"(N) : "memory")

#define LDSM_X4(r, addr) \
    asm volatile("ldmatrix.sync.aligned.m8n8.x4.shared.b16 {%0,%1,%2,%3}, [%4];" \
                 : "=r"((r)[0]), "=r"((r)[1]), "=r"((r)[2]), "=r"((r)[3]) : "r"(addr))

__device__ __forceinline__ void mma_f16(float* d, const uint32_t* a,
                                        uint32_t b0, uint32_t b1) {
    asm volatile(
        "mma.sync.aligned.m16n8k16.row.col.f32.f16.f16.f32 "
        "{%0,%1,%2,%3}, {%4,%5,%6,%7}, {%8,%9}, {%0,%1,%2,%3};"
        : "+f"(d[0]), "+f"(d[1]), "+f"(d[2]), "+f"(d[3])
        : "r"(a[0]), "r"(a[1]), "r"(a[2]), "r"(a[3]), "r"(b0), "r"(b1));
}

// ---------------------------------------------------------------------------
// Weight prep: fp32 -> fp16 hi/lo.  Data prep: x transpose -> fp16.
// ---------------------------------------------------------------------------
__global__ void split_kernel(const float* __restrict__ a,
                             __half* __restrict__ h, __half* __restrict__ l, int n)
{
    int i = blockIdx.x * 256 + threadIdx.x;
    if (i < n) {
        float v = a[i];
        __half hi = __float2half_rn(v);
        h[i] = hi;
        l[i] = __float2half_rn(v - __half2float(hi));
    }
}

__global__ void __launch_bounds__(256) tsplit_kernel(
    const float* __restrict__ x, __half* __restrict__ o)
{
    __shared__ float t[32][33];
    const int n0 = blockIdx.x * 32, k0 = blockIdx.y * 32, b = blockIdx.z;
    const int tx = threadIdx.x, ty = threadIdx.y;
    const float* src = x + ((size_t)b * KDIM + k0) * S + n0;
#pragma unroll
    for (int i = 0; i < 4; i++)
        t[ty + 8 * i][tx] = src[(size_t)(ty + 8 * i) * S + tx];
    __syncthreads();
    __half* d = o + ((size_t)b * S + n0) * KDIM + k0;
#pragma unroll
    for (int i = 0; i < 4; i++)
        d[(size_t)(ty + 8 * i) * KDIM + tx] = __float2half_rn(t[tx][ty + 8 * i]);
}

// ---------------------------------------------------------------------------
// HMMA fp16 2-term batched GEMM: C = (Ah+Al) @ B^T (+bias), fp32 accum.
// CTA tile 128x128, 8 warps (32x64), K chunks of 16, 4-stage cp.async, 2 CTA/SM.
// ---------------------------------------------------------------------------
#define NCH     32
#define STG_SZ  18432              // 3 tiles x 128 rows x 48B
#define T_AL    6144
#define T_B     12288
#define GSMEM   (4 * STG_SZ)       // 73728 B

__global__ void __launch_bounds__(256, 2) gemm_mma_kernel(
    const __half* __restrict__ Ah, const __half* __restrict__ Al,
    const __half* __restrict__ B,
    float* __restrict__ C, const float* __restrict__ bias, int Ntot)
{
    extern __shared__ char smem[];
    const uint32_t sbase = smem_u32(smem);

    const int tid = threadIdx.x;
    const int n0 = blockIdx.x * 128;
    const int m0 = blockIdx.y * 128;
    const int M  = gridDim.y * 128;
    const size_t bo = (size_t)blockIdx.z * Ntot * KDIM;
    const size_t co = (size_t)blockIdx.z * M * Ntot;

    const __half* Bb = B + bo;

    const int lrow = tid >> 1, lhalf = tid & 1;
    const uint32_t lso = (uint32_t)(lrow * 48 + lhalf * 16);

    const int wid = tid >> 5, lane = tid & 31;
    const int wm = (wid & 3) * 32, wn = (wid >> 2) * 64;
    const uint32_t aoff = (uint32_t)((wm + (lane & 15)) * 48 + (lane >> 4) * 16);
    const uint32_t boff = (uint32_t)(T_B + (wn + (lane & 15)) * 48 + (lane >> 4) * 16);

    float acc[2][8][4];
#pragma unroll
    for (int f = 0; f < 2; f++)
#pragma unroll
        for (int j = 0; j < 8; j++)
#pragma unroll
            for (int r = 0; r < 4; r++) acc[f][j][r] = 0.f;

#define ISSUE(cc, st) do {                                                    \
        const size_t ga = (size_t)(m0 + lrow) * KDIM + (cc) * 16 + lhalf * 8; \
        const size_t gb = (size_t)(n0 + lrow) * KDIM + (cc) * 16 + lhalf * 8; \
        const uint32_t sp = sbase + (st) * STG_SZ + lso;                      \
        cpasync16(sp,         Ah + ga);                                       \
        cpasync16(sp + T_AL,  Al + ga);                                       \
        cpasync16(sp + T_B,   Bb + gb);                                       \
    } while (0)

    // prologue: stages 0,1,2
    ISSUE(0, 0); CP_COMMIT();
    ISSUE(1, 1); CP_COMMIT();
    ISSUE(2, 2); CP_COMMIT();

    for (int c = 0; c < NCH; c++) {
        CP_WAIT(2);                     // chunk c resident
        __syncthreads();                // all warps done reading stage (c+3)&3
        if (c + 3 < NCH) ISSUE(c + 3, (c + 3) & 3);
        CP_COMMIT();

        const uint32_t sa = sbase + (uint32_t)((c & 3) * STG_SZ);
        uint32_t ah[2][4], al[2][4];
        LDSM_X4(ah[0], sa + aoff);
        LDSM_X4(ah[1], sa + aoff + 768);
        LDSM_X4(al[0], sa + aoff + T_AL);
        LDSM_X4(al[1], sa + aoff + T_AL + 768);
#pragma unroll
        for (int g = 0; g < 4; g++) {
            uint32_t bh[4];
            LDSM_X4(bh, sa + boff + g * 768);
#pragma unroll
            for (int f = 0; f < 2; f++) {
                mma_f16(acc[f][2 * g],     ah[f], bh[0], bh[2]);
                mma_f16(acc[f][2 * g],     al[f], bh[0], bh[2]);
                mma_f16(acc[f][2 * g + 1], ah[f], bh[1], bh[3]);
                mma_f16(acc[f][2 * g + 1], al[f], bh[1], bh[3]);
            }
        }
    }
#undef ISSUE

#pragma unroll
    for (int f = 0; f < 2; f++) {
        const int r0 = m0 + wm + f * 16 + (lane >> 2);
        const float bv0 = bias ? bias[r0] : 0.f;
        const float bv1 = bias ? bias[r0 + 8] : 0.f;
        float* cp0 = C + co + (size_t)r0 * Ntot;
        float* cp1 = cp0 + (size_t)8 * Ntot;
#pragma unroll
        for (int j = 0; j < 8; j++) {
            const int col = n0 + wn + j * 8 + (lane & 3) * 2;
            float2 v0 = make_float2(acc[f][j][0] + bv0, acc[f][j][1] + bv0);
            float2 v1 = make_float2(acc[f][j][2] + bv1, acc[f][j][3] + bv1);
            *(float2*)(cp0 + col) = v0;
            *(float2*)(cp1 + col) = v1;
        }
    }
}

// ---------------------------------------------------------------------------
// Pool + sigmoid gate -> single fp16.  K: [b,h,n,d]  V: [b,h,d,n]
// ---------------------------------------------------------------------------
__global__ void __launch_bounds__(256) pool_kernel(
    const float* __restrict__ qkv,
    __half* __restrict__ khg, __half* __restrict__ vhg)
{
    const int bc = blockIdx.x;
    const int b = bc >> 9;
    const int c = bc & 511;
    const int part = blockIdx.y;           // 0 = k, 1 = v
    const int bh = b * HEADS + (c >> 6);
    const int d  = c & 63;
    const float* src = qkv + ((size_t)b * QKVC + 512 + part * 512 + c) * S;

    __shared__ float ts[S];
    const int tid = threadIdx.x;
    ((float4*)ts)[tid] = ((const float4*)src)[tid];
    __syncthreads();

    auto store = [&](int n, float pooled) {
        const float sv = 1.f / (1.f + __expf(-pooled));
        const __half hv = __float2half_rn(sv);
        if (part == 0) khg[((size_t)bh * NKV + n) * DH + d] = hv;
        else           vhg[((size_t)bh * DH + d) * NKV + n] = hv;
    };

    if (tid < 32) {
        float s = 0.f;
#pragma unroll
        for (int w = 0; w < 32; w++) s += ts[tid * 32 + w];
        store(tid, s * (1.f / 32.f));
    } else if (tid < 64) {
        const int w = tid - 32;
        float s = 0.f;
#pragma unroll
        for (int hh = 0; hh < 32; hh++) s += ts[hh * 32 + w];
        store(tid, s * (1.f / 32.f));
    }
    {
        const int ph = tid >> 4, pw = tid & 15;
        const float s = ts[(2 * ph) * 32 + 2 * pw] + ts[(2 * ph) * 32 + 2 * pw + 1]
                      + ts[(2 * ph + 1) * 32 + 2 * pw] + ts[(2 * ph + 1) * 32 + 2 * pw + 1];
        store(64 + tid, s * 0.25f);
    }
}

// ---------------------------------------------------------------------------
// MMA attention: TQ=32, single-fp16 K/V, Q hi/lo, 2 CTAs/SM.
// Epilogue writes single fp16 att [B,S,C].
// ---------------------------------------------------------------------------
#define TQ       32
#define Q_ROW    144
#define K_ROW    144
#define V_ROW    656
#define SC_ROWB  1296
#define A_Q      0
#define A_Q_LO   4608
#define A_K      9216
#define A_V      9216
#define A_SC     55296
#define A_INV    96768
#define ATTN2_SMEM 96896

__global__ void __launch_bounds__(256, 2) attn_mma_kernel(
    const float* __restrict__ qkv,
    const __half* __restrict__ khg, const __half* __restrict__ vhg,
    const float* __restrict__ pos,
    __half* __restrict__ att)
{
    extern __shared__ char sm[];
    const uint32_t sb = smem_u32(sm);
    const int b = blockIdx.z, hd = blockIdx.y;
    const int s0 = blockIdx.x * TQ;
    const int tid = threadIdx.x, wid = tid >> 5, lane = tid & 31;

    {
        const char* kh = (const char*)(khg + (size_t)(b * HEADS + hd) * NKV * DH);
#pragma unroll
        for (int i = 0; i < 10; i++) {
            const int c = tid + i * 256;
            cpasync16(sb + A_K + (c >> 3) * K_ROW + (c & 7) * 16,
                      kh + (size_t)c * 16);
        }
        CP_COMMIT();
    }
    {
        const float* qg = qkv + ((size_t)b * QKVC + hd * DH) * S + s0;
#pragma unroll
        for (int i = 0; i < 8; i++) {
            const int idx = tid + i * 256;
            const int dd = idx >> 5, si = idx & 31;
            const float v = qg[(size_t)dd * S + si] * 0.125f;
            const __half hi = __float2half_rn(v);
            *(__half*)(sm + A_Q + si * Q_ROW + dd * 2) = hi;
            *(__half*)(sm + A_Q + A_Q_LO + si * Q_ROW + dd * 2) =
                __float2half_rn(v - __half2float(hi));
        }
    }
    CP_WAIT(0);
    __syncthreads();

    const int mw = wid & 1;

    {
        const int n0w = (wid >> 1) * 80;
        float acc[10][4];
#pragma unroll
        for (int t = 0; t < 10; t++) {
            acc[t][0] = 0.f; acc[t][1] = 0.f; acc[t][2] = 0.f; acc[t][3] = 0.f;
        }
#pragma unroll
        for (int k = 0; k < 4; k++) {
            uint32_t ah[4], al[4];
            const uint32_t qa = sb + A_Q + (mw * 16 + (lane & 15)) * Q_ROW
                              + (lane >> 4) * 16 + k * 32;
            LDSM_X4(ah, qa);
            LDSM_X4(al, qa + A_Q_LO);
#pragma unroll
            for (int jn = 0; jn < 5; jn++) {
                uint32_t bh[4];
                LDSM_X4(bh, sb + A_K + (n0w + jn * 16 + (lane & 15)) * K_ROW
                            + (lane >> 4) * 16 + k * 32);
                mma_f16(acc[2 * jn],     ah, bh[0], bh[2]);
                mma_f16(acc[2 * jn],     al, bh[0], bh[2]);
                mma_f16(acc[2 * jn + 1], ah, bh[1], bh[3]);
                mma_f16(acc[2 * jn + 1], al, bh[1], bh[3]);
            }
        }
        const int r0 = mw * 16 + (lane >> 2);
#pragma unroll
        for (int jn = 0; jn < 5; jn++)
#pragma unroll
            for (int t = 0; t < 2; t++) {
                const int n = n0w + jn * 16 + t * 8 + (lane & 3) * 2;
                float* p0 = (float*)(sm + A_SC + r0 * SC_ROWB) + n;
                float* p1 = (float*)(sm + A_SC + (r0 + 8) * SC_ROWB) + n;
                *(float2*)p0 = make_float2(acc[2 * jn + t][0], acc[2 * jn + t][1]);
                *(float2*)p1 = make_float2(acc[2 * jn + t][2], acc[2 * jn + t][3]);
            }
    }
    __syncthreads();

    {
        const char* vh = (const char*)(vhg + (size_t)(b * HEADS + hd) * DH * NKV);
#pragma unroll
        for (int i = 0; i < 10; i++) {
            const int c = tid + i * 256;
            const int d = c / 40, o = c % 40;
            cpasync16(sb + A_V + d * V_ROW + o * 16, vh + (size_t)c * 16);
        }
        CP_COMMIT();
    }

    {
        const int r = tid >> 3, cq = tid & 7;
        float* row = (float*)(sm + A_SC + r * SC_ROWB);
        __half* ph = (__half*)(sm + A_SC + r * SC_ROWB);
        const float* pr = pos + (size_t)(s0 + r) * NKV;
        float mx = -1e30f;
#pragma unroll
        for (int k = cq; k < NKV; k += 8) {
            const float v = row[k] + pr[k];
            row[k] = v;
            mx = fmaxf(mx, v);
        }
        mx = fmaxf(mx, __shfl_xor_sync(0xffffffffu, mx, 1));
        mx = fmaxf(mx, __shfl_xor_sync(0xffffffffu, mx, 2));
        mx = fmaxf(mx, __shfl_xor_sync(0xffffffffu, mx, 4));
        float ssum = 0.f;
#pragma unroll
        for (int c5 = 0; c5 < 5; c5++) {
            float e[8];
#pragma unroll
            for (int j = 0; j < 8; j++) {
                e[j] = __expf(row[c5 * 64 + cq + 8 * j] - mx);
                ssum += e[j];
            }
            __syncwarp();
#pragma unroll
            for (int j = 0; j < 8; j++)
                ph[c5 * 64 + cq + 8 * j] = __float2half_rn(e[j]);
            __syncwarp();
        }
        ssum += __shfl_xor_sync(0xffffffffu, ssum, 1);
        ssum += __shfl_xor_sync(0xffffffffu, ssum, 2);
        ssum += __shfl_xor_sync(0xffffffffu, ssum, 4);
        if (cq == 0) *(float*)(sm + A_INV + r * 4) = 1.f / ssum;
    }
    CP_WAIT(0);
    __syncthreads();

    {
        const int dw = wid >> 1;
        float oa[2][4];
        oa[0][0] = oa[0][1] = oa[0][2] = oa[0][3] = 0.f;
        oa[1][0] = oa[1][1] = oa[1][2] = oa[1][3] = 0.f;
#pragma unroll
        for (int k = 0; k < 20; k++) {
            uint32_t pa[4], vv[4];
            LDSM_X4(pa, sb + A_SC + (mw * 16 + (lane & 15)) * SC_ROWB
                        + (lane >> 4) * 16 + k * 32);
            LDSM_X4(vv, sb + A_V + (dw * 16 + (lane & 15)) * V_ROW
                        + (lane >> 4) * 16 + k * 32);
            mma_f16(oa[0], pa, vv[0], vv[2]);
            mma_f16(oa[1], pa, vv[1], vv[3]);
        }
        const float inv0 = *(const float*)(sm + A_INV + (mw * 16 + (lane >> 2)) * 4);
        const float inv1 = *(const float*)(sm + A_INV + (mw * 16 + 8 + (lane >> 2)) * 4);
        const size_t ro0 = ((size_t)b * S + s0 + mw * 16 + (lane >> 2)) * CIN + hd * DH;
        const size_t ro1 = ro0 + (size_t)8 * CIN;
#pragma unroll
        for (int jt = 0; jt < 2; jt++) {
            const int col = dw * 16 + jt * 8 + (lane & 3) * 2;
            __half2 h0 = __floats2half2_rn(oa[jt][0] * inv0, oa[jt][1] * inv0);
            __half2 h1 = __floats2half2_rn(oa[jt][2] * inv1, oa[jt][3] * inv1);
            *(__half2*)(att + ro0 + col) = h0;
            *(__half2*)(att + ro1 + col) = h1;
        }
    }
}

// ---------------------------------------------------------------------------
// Launch
// ---------------------------------------------------------------------------
extern "C" void kernel_launch(void* const* d_in, const int* in_sizes, int n_in,
                              void* d_out, int out_size)
{
    const float* x     = (const float*)d_in[0];
    const float* Wqkv  = (const float*)d_in[1];
    const float* Wout  = (const float*)d_in[2];
    const float* bout  = (const float*)d_in[3];
    const float* pos   = (const float*)d_in[4];
    float* out = (float*)d_out;

    float *p_qkv;
    __half *p_x, *p_kh, *p_vh, *p_at, *p_wqh, *p_wql, *p_woh, *p_wol;
    cudaGetSymbolAddress((void**)&p_qkv, g_qkv);
    cudaGetSymbolAddress((void**)&p_x,   g_x);
    cudaGetSymbolAddress((void**)&p_kh,  g_kh);
    cudaGetSymbolAddress((void**)&p_vh,  g_vh);
    cudaGetSymbolAddress((void**)&p_at,  g_at);
    cudaGetSymbolAddress((void**)&p_wqh, g_wqh);
    cudaGetSymbolAddress((void**)&p_wql, g_wql);
    cudaGetSymbolAddress((void**)&p_woh, g_woh);
    cudaGetSymbolAddress((void**)&p_wol, g_wol);

    cudaFuncSetAttribute(gemm_mma_kernel,
                         cudaFuncAttributeMaxDynamicSharedMemorySize, GSMEM);
    cudaFuncSetAttribute(attn_mma_kernel,
                         cudaFuncAttributeMaxDynamicSharedMemorySize, ATTN2_SMEM);

    // 0) operand prep
    split_kernel<<<(QKVC * KDIM + 255) / 256, 256>>>(Wqkv, p_wqh, p_wql, QKVC * KDIM);
    split_kernel<<<(COUT * KDIM + 255) / 256, 256>>>(Wout, p_woh, p_wol, COUT * KDIM);
    tsplit_kernel<<<dim3(S / 32, KDIM / 32, BATCH), dim3(32, 8)>>>(x, p_x);

    // 1) qkv = Wqkv @ x^T   [B,1536,1024]
    gemm_mma_kernel<<<dim3(S / 128, QKVC / 128, BATCH), 256, GSMEM>>>(
        p_wqh, p_wql, p_x, p_qkv, nullptr, S);

    // 2) pool + sigmoid gates -> fp16 K,V
    pool_kernel<<<dim3(BATCH * CIN, 2), 256>>>(p_qkv, p_kh, p_vh);

    // 3) tensor-core attention -> att fp16 [B,S,C]
    attn_mma_kernel<<<dim3(S / TQ, HEADS, BATCH), 256, ATTN2_SMEM>>>(
        p_qkv, p_kh, p_vh, pos, p_at);

    // 4) out = Wout @ att^T + bout   [B,512,1024]
    gemm_mma_kernel<<<dim3(S / 128, COUT / 128, BATCH), 256, GSMEM>>>(
        p_woh, p_wol, p_at, out, bout, S);
}

// round 8
// speedup vs baseline: 4.0318x; 1.1188x over previous
#include <cuda_runtime.h>
#include <cuda_bf16.h>
#include <cuda_fp16.h>
#include <math.h>
#include <stdint.h>

// ---------------------------------------------------------------------------
// Problem constants
// ---------------------------------------------------------------------------
#define BATCH   32
#define CIN     512
#define COUT    512
#define HEADS   8
#define DH      64
#define S       1024
#define NKV     320
#define NKVP    384          // padded to tile multiple
#define QKVC    1536
#define KDIM    512

// ---------------------------------------------------------------------------
// Scratch (device globals)
// ---------------------------------------------------------------------------
__device__ float g_q  [(size_t)BATCH * CIN * S];                  // Q [B,512,1024]
__device__ float g_kvp[(size_t)BATCH * 1024 * NKVP];              // kv pre-sigmoid [B,1024,384]
__device__ __align__(16) __half g_x  [(size_t)BATCH * S * KDIM];  // xT fp16 [B,1024,512]
__device__ __align__(16) __half g_xp [(size_t)BATCH * NKVP * KDIM]; // pooled xT fp16 [B,384,512]
__device__ __align__(16) __half g_kh [(size_t)BATCH * HEADS * NKV * DH]; // K [b,h,n,d]
__device__ __align__(16) __half g_vh [(size_t)BATCH * HEADS * DH * NKV]; // V [b,h,d,n]
__device__ __align__(16) __half g_at [(size_t)BATCH * S * CIN];   // att fp16 [B,S,C]
__device__ __align__(16) __half g_wqh[(size_t)QKVC * KDIM];
__device__ __align__(16) __half g_wql[(size_t)QKVC * KDIM];
__device__ __align__(16) __half g_woh[(size_t)COUT * KDIM];
__device__ __align__(16) __half g_wol[(size_t)COUT * KDIM];

// ---------------------------------------------------------------------------
// PTX helpers
// ---------------------------------------------------------------------------
__device__ __forceinline__ uint32_t smem_u32(const void* p) {
    uint32_t a;
    asm("{ .reg .u64 t; cvta.to.shared.u64 t, %1; cvt.u32.u64 %0, t; }"
        : "=r"(a) : "l"(p));
    return a;
}
__device__ __forceinline__ void cpasync16(uint32_t s, const void* g) {
    asm volatile("cp.async.cg.shared.global [%0], [%1], 16;" :: "r"(s), "l"(g));
}
#define CP_COMMIT() asm volatile("cp.async.commit_group;" ::: "memory")
#define CP_WAIT(N)  asm volatile("cp.async.wait_group %0;" :: "n"(N) : "memory")

#define LDSM_X4(r, addr) \
    asm volatile("ldmatrix.sync.aligned.m8n8.x4.shared.b16 {%0,%1,%2,%3}, [%4];" \
                 : "=r"((r)[0]), "=r"((r)[1]), "=r"((r)[2]), "=r"((r)[3]) : "r"(addr))

__device__ __forceinline__ void mma_f16(float* d, const uint32_t* a,
                                        uint32_t b0, uint32_t b1) {
    asm volatile(
        "mma.sync.aligned.m16n8k16.row.col.f32.f16.f16.f32 "
        "{%0,%1,%2,%3}, {%4,%5,%6,%7}, {%8,%9}, {%0,%1,%2,%3};"
        : "+f"(d[0]), "+f"(d[1]), "+f"(d[2]), "+f"(d[3])
        : "r"(a[0]), "r"(a[1]), "r"(a[2]), "r"(a[3]), "r"(b0), "r"(b1));
}

// ---------------------------------------------------------------------------
// Weight prep: fp32 -> fp16 hi/lo.  Data prep: x transpose -> fp16.
// ---------------------------------------------------------------------------
__global__ void split_kernel(const float* __restrict__ a,
                             __half* __restrict__ h, __half* __restrict__ l, int n)
{
    int i = blockIdx.x * 256 + threadIdx.x;
    if (i < n) {
        float v = a[i];
        __half hi = __float2half_rn(v);
        h[i] = hi;
        l[i] = __float2half_rn(v - __half2float(hi));
    }
}

__global__ void __launch_bounds__(256) tsplit_kernel(
    const float* __restrict__ x, __half* __restrict__ o)
{
    __shared__ float t[32][33];
    const int n0 = blockIdx.x * 32, k0 = blockIdx.y * 32, b = blockIdx.z;
    const int tx = threadIdx.x, ty = threadIdx.y;
    const float* src = x + ((size_t)b * KDIM + k0) * S + n0;
#pragma unroll
    for (int i = 0; i < 4; i++)
        t[ty + 8 * i][tx] = src[(size_t)(ty + 8 * i) * S + tx];
    __syncthreads();
    __half* d = o + ((size_t)b * S + n0) * KDIM + k0;
#pragma unroll
    for (int i = 0; i < 4; i++)
        d[(size_t)(ty + 8 * i) * KDIM + tx] = __float2half_rn(t[tx][ty + 8 * i]);
}

// ---------------------------------------------------------------------------
// Pool x -> xpT fp16 [B, 384(pad), 512].  n: 0-31 row-mean, 32-63 col-mean,
// 64-319 2x2 avg.  Rows 320-383 zero.
// ---------------------------------------------------------------------------
__global__ void __launch_bounds__(256) pool_x_kernel(
    const float* __restrict__ x, __half* __restrict__ xp)
{
    const int bc = blockIdx.x;           // b*512 + c
    const int b = bc >> 9, c = bc & 511;
    const float* src = x + (size_t)bc * S;
    __half* dst = xp + (size_t)b * NKVP * KDIM + c;   // [b][n][c]

    __shared__ float ts[S];
    const int tid = threadIdx.x;
    ((float4*)ts)[tid] = ((const float4*)src)[tid];
    __syncthreads();

    if (tid < 32) {                      // mean over width -> n = h
        float s = 0.f;
#pragma unroll
        for (int w = 0; w < 32; w++) s += ts[tid * 32 + w];
        dst[(size_t)tid * KDIM] = __float2half_rn(s * (1.f / 32.f));
    } else if (tid < 64) {               // mean over height -> n = 32 + w
        const int w = tid - 32;
        float s = 0.f;
#pragma unroll
        for (int hh = 0; hh < 32; hh++) s += ts[hh * 32 + w];
        dst[(size_t)tid * KDIM] = __float2half_rn(s * (1.f / 32.f));
    } else if (tid < 128) {              // zero pad rows 320..383
        dst[(size_t)(256 + tid) * KDIM] = __float2half_rn(0.f);
    }
    {                                    // 2x2 avg -> n = 64 + tid
        const int ph = tid >> 4, pw = tid & 15;
        const float s = ts[(2 * ph) * 32 + 2 * pw] + ts[(2 * ph) * 32 + 2 * pw + 1]
                      + ts[(2 * ph + 1) * 32 + 2 * pw] + ts[(2 * ph + 1) * 32 + 2 * pw + 1];
        dst[(size_t)(64 + tid) * KDIM] = __float2half_rn(s * 0.25f);
    }
}

// ---------------------------------------------------------------------------
// HMMA fp16 2-term batched GEMM (unchanged from R7).
// ---------------------------------------------------------------------------
#define STG_SZ  18432
#define T_AL    6144
#define T_B     12288
#define GSMEM   (4 * STG_SZ)

__global__ void __launch_bounds__(256, 2) gemm_mma_kernel(
    const __half* __restrict__ Ah, const __half* __restrict__ Al,
    const __half* __restrict__ B,
    float* __restrict__ C, const float* __restrict__ bias, int Ntot)
{
    extern __shared__ char smem[];
    const uint32_t sbase = smem_u32(smem);

    const int tid = threadIdx.x;
    const int n0 = blockIdx.x * 128;
    const int m0 = blockIdx.y * 128;
    const int M  = gridDim.y * 128;
    const size_t bo = (size_t)blockIdx.z * Ntot * KDIM;
    const size_t co = (size_t)blockIdx.z * M * Ntot;

    const __half* Bb = B + bo;

    const int lrow = tid >> 1, lhalf = tid & 1;
    const uint32_t lso = (uint32_t)(lrow * 48 + lhalf * 16);

    const int wid = tid >> 5, lane = tid & 31;
    const int wm = (wid & 3) * 32, wn = (wid >> 2) * 64;
    const uint32_t aoff = (uint32_t)((wm + (lane & 15)) * 48 + (lane >> 4) * 16);
    const uint32_t boff = (uint32_t)(T_B + (wn + (lane & 15)) * 48 + (lane >> 4) * 16);

    float acc[2][8][4];
#pragma unroll
    for (int f = 0; f < 2; f++)
#pragma unroll
        for (int j = 0; j < 8; j++)
#pragma unroll
            for (int r = 0; r < 4; r++) acc[f][j][r] = 0.f;

#define ISSUE(cc, st) do {                                                    \
        const size_t ga = (size_t)(m0 + lrow) * KDIM + (cc) * 16 + lhalf * 8; \
        const size_t gb = (size_t)(n0 + lrow) * KDIM + (cc) * 16 + lhalf * 8; \
        const uint32_t sp = sbase + (st) * STG_SZ + lso;                      \
        cpasync16(sp,         Ah + ga);                                       \
        cpasync16(sp + T_AL,  Al + ga);                                       \
        cpasync16(sp + T_B,   Bb + gb);                                       \
    } while (0)

    ISSUE(0, 0); CP_COMMIT();
    ISSUE(1, 1); CP_COMMIT();
    ISSUE(2, 2); CP_COMMIT();

    const int NCH = KDIM / 16;
    for (int c = 0; c < NCH; c++) {
        CP_WAIT(2);
        __syncthreads();
        if (c + 3 < NCH) ISSUE(c + 3, (c + 3) & 3);
        CP_COMMIT();

        const uint32_t sa = sbase + (uint32_t)((c & 3) * STG_SZ);
        uint32_t ah[2][4], al[2][4];
        LDSM_X4(ah[0], sa + aoff);
        LDSM_X4(ah[1], sa + aoff + 768);
        LDSM_X4(al[0], sa + aoff + T_AL);
        LDSM_X4(al[1], sa + aoff + T_AL + 768);
#pragma unroll
        for (int g = 0; g < 4; g++) {
            uint32_t bh[4];
            LDSM_X4(bh, sa + boff + g * 768);
#pragma unroll
            for (int f = 0; f < 2; f++) {
                mma_f16(acc[f][2 * g],     ah[f], bh[0], bh[2]);
                mma_f16(acc[f][2 * g],     al[f], bh[0], bh[2]);
                mma_f16(acc[f][2 * g + 1], ah[f], bh[1], bh[3]);
                mma_f16(acc[f][2 * g + 1], al[f], bh[1], bh[3]);
            }
        }
    }
#undef ISSUE

#pragma unroll
    for (int f = 0; f < 2; f++) {
        const int r0 = m0 + wm + f * 16 + (lane >> 2);
        const float bv0 = bias ? bias[r0] : 0.f;
        const float bv1 = bias ? bias[r0 + 8] : 0.f;
        float* cp0 = C + co + (size_t)r0 * Ntot;
        float* cp1 = cp0 + (size_t)8 * Ntot;
#pragma unroll
        for (int j = 0; j < 8; j++) {
            const int col = n0 + wn + j * 8 + (lane & 3) * 2;
            float2 v0 = make_float2(acc[f][j][0] + bv0, acc[f][j][1] + bv0);
            float2 v1 = make_float2(acc[f][j][2] + bv1, acc[f][j][3] + bv1);
            *(float2*)(cp0 + col) = v0;
            *(float2*)(cp1 + col) = v1;
        }
    }
}

// ---------------------------------------------------------------------------
// kv gate: sigmoid(kv_pre) -> K fp16 [b,h,n,d], V fp16 [b,h,d,n]
// grid (1024, B); block reads one channel row (384 floats, 320 valid)
// ---------------------------------------------------------------------------
__global__ void __launch_bounds__(256) kvgate_kernel(
    const float* __restrict__ kvp,
    __half* __restrict__ khg, __half* __restrict__ vhg)
{
    const int c = blockIdx.x;             // 0..1023 (0-511 K, 512-1023 V)
    const int b = blockIdx.y;
    const float* src = kvp + ((size_t)b * 1024 + c) * NKVP;
    const int isv = c >> 9;
    const int cc = c & 511;
    const int bh = b * HEADS + (cc >> 6);
    const int d  = cc & 63;
    __half* kdst = khg + ((size_t)bh * NKV) * DH + d;     // + n*64
    __half* vdst = vhg + ((size_t)bh * DH + d) * NKV;     // + n

    for (int n = threadIdx.x; n < NKV; n += 256) {
        const float sv = 1.f / (1.f + __expf(-src[n]));
        const __half hv = __float2half_rn(sv);
        if (isv) vdst[n] = hv;
        else     kdst[(size_t)n * DH] = hv;
    }
}

// ---------------------------------------------------------------------------
// MMA attention (as R7; q stride now CIN)
// ---------------------------------------------------------------------------
#define TQ       32
#define Q_ROW    144
#define K_ROW    144
#define V_ROW    656
#define SC_ROWB  1296
#define A_Q      0
#define A_Q_LO   4608
#define A_K      9216
#define A_V      9216
#define A_SC     55296
#define A_INV    96768
#define ATTN2_SMEM 96896

__global__ void __launch_bounds__(256, 2) attn_mma_kernel(
    const float* __restrict__ q,
    const __half* __restrict__ khg, const __half* __restrict__ vhg,
    const float* __restrict__ pos,
    __half* __restrict__ att)
{
    extern __shared__ char sm[];
    const uint32_t sb = smem_u32(sm);
    const int b = blockIdx.z, hd = blockIdx.y;
    const int s0 = blockIdx.x * TQ;
    const int tid = threadIdx.x, wid = tid >> 5, lane = tid & 31;

    {
        const char* kh = (const char*)(khg + (size_t)(b * HEADS + hd) * NKV * DH);
#pragma unroll
        for (int i = 0; i < 10; i++) {
            const int c = tid + i * 256;
            cpasync16(sb + A_K + (c >> 3) * K_ROW + (c & 7) * 16,
                      kh + (size_t)c * 16);
        }
        CP_COMMIT();
    }
    {
        const float* qg = q + ((size_t)b * CIN + hd * DH) * S + s0;
#pragma unroll
        for (int i = 0; i < 8; i++) {
            const int idx = tid + i * 256;
            const int dd = idx >> 5, si = idx & 31;
            const float v = qg[(size_t)dd * S + si] * 0.125f;
            const __half hi = __float2half_rn(v);
            *(__half*)(sm + A_Q + si * Q_ROW + dd * 2) = hi;
            *(__half*)(sm + A_Q + A_Q_LO + si * Q_ROW + dd * 2) =
                __float2half_rn(v - __half2float(hi));
        }
    }
    CP_WAIT(0);
    __syncthreads();

    const int mw = wid & 1;

    {
        const int n0w = (wid >> 1) * 80;
        float acc[10][4];
#pragma unroll
        for (int t = 0; t < 10; t++) {
            acc[t][0] = 0.f; acc[t][1] = 0.f; acc[t][2] = 0.f; acc[t][3] = 0.f;
        }
#pragma unroll
        for (int k = 0; k < 4; k++) {
            uint32_t ah[4], al[4];
            const uint32_t qa = sb + A_Q + (mw * 16 + (lane & 15)) * Q_ROW
                              + (lane >> 4) * 16 + k * 32;
            LDSM_X4(ah, qa);
            LDSM_X4(al, qa + A_Q_LO);
#pragma unroll
            for (int jn = 0; jn < 5; jn++) {
                uint32_t bh[4];
                LDSM_X4(bh, sb + A_K + (n0w + jn * 16 + (lane & 15)) * K_ROW
                            + (lane >> 4) * 16 + k * 32);
                mma_f16(acc[2 * jn],     ah, bh[0], bh[2]);
                mma_f16(acc[2 * jn],     al, bh[0], bh[2]);
                mma_f16(acc[2 * jn + 1], ah, bh[1], bh[3]);
                mma_f16(acc[2 * jn + 1], al, bh[1], bh[3]);
            }
        }
        const int r0 = mw * 16 + (lane >> 2);
#pragma unroll
        for (int jn = 0; jn < 5; jn++)
#pragma unroll
            for (int t = 0; t < 2; t++) {
                const int n = n0w + jn * 16 + t * 8 + (lane & 3) * 2;
                float* p0 = (float*)(sm + A_SC + r0 * SC_ROWB) + n;
                float* p1 = (float*)(sm + A_SC + (r0 + 8) * SC_ROWB) + n;
                *(float2*)p0 = make_float2(acc[2 * jn + t][0], acc[2 * jn + t][1]);
                *(float2*)p1 = make_float2(acc[2 * jn + t][2], acc[2 * jn + t][3]);
            }
    }
    __syncthreads();

    {
        const char* vh = (const char*)(vhg + (size_t)(b * HEADS + hd) * DH * NKV);
#pragma unroll
        for (int i = 0; i < 10; i++) {
            const int c = tid + i * 256;
            const int d = c / 40, o = c % 40;
            cpasync16(sb + A_V + d * V_ROW + o * 16, vh + (size_t)c * 16);
        }
        CP_COMMIT();
    }

    {
        const int r = tid >> 3, cq = tid & 7;
        float* row = (float*)(sm + A_SC + r * SC_ROWB);
        __half* ph = (__half*)(sm + A_SC + r * SC_ROWB);
        const float* pr = pos + (size_t)(s0 + r) * NKV;
        float mx = -1e30f;
#pragma unroll
        for (int k = cq; k < NKV; k += 8) {
            const float v = row[k] + pr[k];
            row[k] = v;
            mx = fmaxf(mx, v);
        }
        mx = fmaxf(mx, __shfl_xor_sync(0xffffffffu, mx, 1));
        mx = fmaxf(mx, __shfl_xor_sync(0xffffffffu, mx, 2));
        mx = fmaxf(mx, __shfl_xor_sync(0xffffffffu, mx, 4));
        float ssum = 0.f;
#pragma unroll
        for (int c5 = 0; c5 < 5; c5++) {
            float e[8];
#pragma unroll
            for (int j = 0; j < 8; j++) {
                e[j] = __expf(row[c5 * 64 + cq + 8 * j] - mx);
                ssum += e[j];
            }
            __syncwarp();
#pragma unroll
            for (int j = 0; j < 8; j++)
                ph[c5 * 64 + cq + 8 * j] = __float2half_rn(e[j]);
            __syncwarp();
        }
        ssum += __shfl_xor_sync(0xffffffffu, ssum, 1);
        ssum += __shfl_xor_sync(0xffffffffu, ssum, 2);
        ssum += __shfl_xor_sync(0xffffffffu, ssum, 4);
        if (cq == 0) *(float*)(sm + A_INV + r * 4) = 1.f / ssum;
    }
    CP_WAIT(0);
    __syncthreads();

    {
        const int dw = wid >> 1;
        float oa[2][4];
        oa[0][0] = oa[0][1] = oa[0][2] = oa[0][3] = 0.f;
        oa[1][0] = oa[1][1] = oa[1][2] = oa[1][3] = 0.f;
#pragma unroll
        for (int k = 0; k < 20; k++) {
            uint32_t pa[4], vv[4];
            LDSM_X4(pa, sb + A_SC + (mw * 16 + (lane & 15)) * SC_ROWB
                        + (lane >> 4) * 16 + k * 32);
            LDSM_X4(vv, sb + A_V + (dw * 16 + (lane & 15)) * V_ROW
                        + (lane >> 4) * 16 + k * 32);
            mma_f16(oa[0], pa, vv[0], vv[2]);
            mma_f16(oa[1], pa, vv[1], vv[3]);
        }
        const float inv0 = *(const float*)(sm + A_INV + (mw * 16 + (lane >> 2)) * 4);
        const float inv1 = *(const float*)(sm + A_INV + (mw * 16 + 8 + (lane >> 2)) * 4);
        const size_t ro0 = ((size_t)b * S + s0 + mw * 16 + (lane >> 2)) * CIN + hd * DH;
        const size_t ro1 = ro0 + (size_t)8 * CIN;
#pragma unroll
        for (int jt = 0; jt < 2; jt++) {
            const int col = dw * 16 + jt * 8 + (lane & 3) * 2;
            __half2 h0 = __floats2half2_rn(oa[jt][0] * inv0, oa[jt][1] * inv0);
            __half2 h1 = __floats2half2_rn(oa[jt][2] * inv1, oa[jt][3] * inv1);
            *(__half2*)(att + ro0 + col) = h0;
            *(__half2*)(att + ro1 + col) = h1;
        }
    }
}

// ---------------------------------------------------------------------------
// Launch
// ---------------------------------------------------------------------------
extern "C" void kernel_launch(void* const* d_in, const int* in_sizes, int n_in,
                              void* d_out, int out_size)
{
    const float* x     = (const float*)d_in[0];
    const float* Wqkv  = (const float*)d_in[1];
    const float* Wout  = (const float*)d_in[2];
    const float* bout  = (const float*)d_in[3];
    const float* pos   = (const float*)d_in[4];
    float* out = (float*)d_out;

    float *p_q, *p_kvp;
    __half *p_x, *p_xp, *p_kh, *p_vh, *p_at, *p_wqh, *p_wql, *p_woh, *p_wol;
    cudaGetSymbolAddress((void**)&p_q,   g_q);
    cudaGetSymbolAddress((void**)&p_kvp, g_kvp);
    cudaGetSymbolAddress((void**)&p_x,   g_x);
    cudaGetSymbolAddress((void**)&p_xp,  g_xp);
    cudaGetSymbolAddress((void**)&p_kh,  g_kh);
    cudaGetSymbolAddress((void**)&p_vh,  g_vh);
    cudaGetSymbolAddress((void**)&p_at,  g_at);
    cudaGetSymbolAddress((void**)&p_wqh, g_wqh);
    cudaGetSymbolAddress((void**)&p_wql, g_wql);
    cudaGetSymbolAddress((void**)&p_woh, g_woh);
    cudaGetSymbolAddress((void**)&p_wol, g_wol);

    cudaFuncSetAttribute(gemm_mma_kernel,
                         cudaFuncAttributeMaxDynamicSharedMemorySize, GSMEM);
    cudaFuncSetAttribute(attn_mma_kernel,
                         cudaFuncAttributeMaxDynamicSharedMemorySize, ATTN2_SMEM);

    // 0) operand prep
    split_kernel<<<(QKVC * KDIM + 255) / 256, 256>>>(Wqkv, p_wqh, p_wql, QKVC * KDIM);
    split_kernel<<<(COUT * KDIM + 255) / 256, 256>>>(Wout, p_woh, p_wol, COUT * KDIM);
    tsplit_kernel<<<dim3(S / 32, KDIM / 32, BATCH), dim3(32, 8)>>>(x, p_x);
    pool_x_kernel<<<BATCH * CIN, 256>>>(x, p_xp);

    // 1) Q = Wq @ x^T   [B,512,1024]
    gemm_mma_kernel<<<dim3(S / 128, CIN / 128, BATCH), 256, GSMEM>>>(
        p_wqh, p_wql, p_x, p_q, nullptr, S);

    // 2) kv_pre = Wkv @ xp^T   [B,1024,384]
    gemm_mma_kernel<<<dim3(NKVP / 128, 1024 / 128, BATCH), 256, GSMEM>>>(
        p_wqh + (size_t)CIN * KDIM, p_wql + (size_t)CIN * KDIM,
        p_xp, p_kvp, nullptr, NKVP);

    // 3) sigmoid gate -> K, V fp16
    kvgate_kernel<<<dim3(1024, BATCH), 256>>>(p_kvp, p_kh, p_vh);

    // 4) tensor-core attention -> att fp16 [B,S,C]
    attn_mma_kernel<<<dim3(S / TQ, HEADS, BATCH), 256, ATTN2_SMEM>>>(
        p_q, p_kh, p_vh, pos, p_at);

    // 5) out = Wout @ att^T + bout   [B,512,1024]
    gemm_mma_kernel<<<dim3(S / 128, COUT / 128, BATCH), 256, GSMEM>>>(
        p_woh, p_wol, p_at, out, bout, S);
}

// round 9
// speedup vs baseline: 4.4849x; 1.1124x over previous
#include <cuda_runtime.h>
#include <cuda_bf16.h>
#include <cuda_fp16.h>
#include <math.h>
#include <stdint.h>

// ---------------------------------------------------------------------------
// Problem constants
// ---------------------------------------------------------------------------
#define BATCH   32
#define CIN     512
#define COUT    512
#define HEADS   8
#define DH      64
#define S       1024
#define NKV     320
#define NKVP    384          // padded to tile multiple
#define QKVC    1536
#define KDIM    512

// ---------------------------------------------------------------------------
// Scratch (device globals)
// ---------------------------------------------------------------------------
__device__ float g_q   [(size_t)BATCH * CIN * S];                 // Q [B,512,1024]
__device__ float g_kvp [(size_t)BATCH * 1024 * NKVP];             // kv pre-sigmoid [B,1024,384]
__device__ float g_pool[(size_t)BATCH * CIN * NKV];               // pooled x fp32 [B,512,320]
__device__ __align__(16) __half g_x  [(size_t)BATCH * S * KDIM];  // xT fp16 [B,1024,512]
__device__ __align__(16) __half g_xp [(size_t)BATCH * NKVP * KDIM]; // pooled xT fp16 [B,384,512]
__device__ __align__(16) __half g_kh [(size_t)BATCH * HEADS * NKV * DH]; // K [b,h,n,d]
__device__ __align__(16) __half g_vh [(size_t)BATCH * HEADS * DH * NKV]; // V [b,h,d,n]
__device__ __align__(16) __half g_at [(size_t)BATCH * S * CIN];   // att fp16 [B,S,C]
__device__ __align__(16) __half g_wqh[(size_t)QKVC * KDIM];
__device__ __align__(16) __half g_wql[(size_t)QKVC * KDIM];
__device__ __align__(16) __half g_woh[(size_t)COUT * KDIM];
__device__ __align__(16) __half g_wol[(size_t)COUT * KDIM];

// ---------------------------------------------------------------------------
// PTX helpers
// ---------------------------------------------------------------------------
__device__ __forceinline__ uint32_t smem_u32(const void* p) {
    uint32_t a;
    asm("{ .reg .u64 t; cvta.to.shared.u64 t, %1; cvt.u32.u64 %0, t; }"
        : "=r"(a) : "l"(p));
    return a;
}
__device__ __forceinline__ void cpasync16(uint32_t s, const void* g) {
    asm volatile("cp.async.cg.shared.global [%0], [%1], 16;" :: "r"(s), "l"(g));
}
#define CP_COMMIT() asm volatile("cp.async.commit_group;" ::: "memory")
#define CP_WAIT(N)  asm volatile("cp.async.wait_group %0;" :: "n"(N) : "memory")

#define LDSM_X4(r, addr) \
    asm volatile("ldmatrix.sync.aligned.m8n8.x4.shared.b16 {%0,%1,%2,%3}, [%4];" \
                 : "=r"((r)[0]), "=r"((r)[1]), "=r"((r)[2]), "=r"((r)[3]) : "r"(addr))

__device__ __forceinline__ void mma_f16(float* d, const uint32_t* a,
                                        uint32_t b0, uint32_t b1) {
    asm volatile(
        "mma.sync.aligned.m16n8k16.row.col.f32.f16.f16.f32 "
        "{%0,%1,%2,%3}, {%4,%5,%6,%7}, {%8,%9}, {%0,%1,%2,%3};"
        : "+f"(d[0]), "+f"(d[1]), "+f"(d[2]), "+f"(d[3])
        : "r"(a[0]), "r"(a[1]), "r"(a[2]), "r"(a[3]), "r"(b0), "r"(b1));
}

// ---------------------------------------------------------------------------
// Weight prep: fp32 -> fp16 hi/lo.  Data prep: x transpose -> fp16.
// ---------------------------------------------------------------------------
__global__ void split_kernel(const float* __restrict__ a,
                             __half* __restrict__ h, __half* __restrict__ l, int n)
{
    int i = blockIdx.x * 256 + threadIdx.x;
    if (i < n) {
        float v = a[i];
        __half hi = __float2half_rn(v);
        h[i] = hi;
        l[i] = __float2half_rn(v - __half2float(hi));
    }
}

__global__ void __launch_bounds__(256) tsplit_kernel(
    const float* __restrict__ x, __half* __restrict__ o)
{
    __shared__ float t[32][33];
    const int n0 = blockIdx.x * 32, k0 = blockIdx.y * 32, b = blockIdx.z;
    const int tx = threadIdx.x, ty = threadIdx.y;
    const float* src = x + ((size_t)b * KDIM + k0) * S + n0;
#pragma unroll
    for (int i = 0; i < 4; i++)
        t[ty + 8 * i][tx] = src[(size_t)(ty + 8 * i) * S + tx];
    __syncthreads();
    __half* d = o + ((size_t)b * S + n0) * KDIM + k0;
#pragma unroll
    for (int i = 0; i < 4; i++)
        d[(size_t)(ty + 8 * i) * KDIM + tx] = __float2half_rn(t[tx][ty + 8 * i]);
}

// ---------------------------------------------------------------------------
// Pool x -> pooled fp32 [b][c][320]  (all writes contiguous per block)
// ---------------------------------------------------------------------------
__global__ void __launch_bounds__(256) pool_x_kernel(
    const float* __restrict__ x, float* __restrict__ pooled)
{
    const int bc = blockIdx.x;           // b*512 + c
    const float* src = x + (size_t)bc * S;
    float* dst = pooled + (size_t)bc * NKV;

    __shared__ float ts[S];
    const int tid = threadIdx.x;
    ((float4*)ts)[tid] = ((const float4*)src)[tid];
    __syncthreads();

    if (tid < 32) {                      // mean over width -> n = h
        float s = 0.f;
#pragma unroll
        for (int w = 0; w < 32; w++) s += ts[tid * 32 + w];
        dst[tid] = s * (1.f / 32.f);
    } else if (tid < 64) {               // mean over height -> n = 32 + w
        const int w = tid - 32;
        float s = 0.f;
#pragma unroll
        for (int hh = 0; hh < 32; hh++) s += ts[hh * 32 + w];
        dst[tid] = s * (1.f / 32.f);
    }
    {                                    // 2x2 avg -> n = 64 + tid
        const int ph = tid >> 4, pw = tid & 15;
        const float s = ts[(2 * ph) * 32 + 2 * pw] + ts[(2 * ph) * 32 + 2 * pw + 1]
                      + ts[(2 * ph + 1) * 32 + 2 * pw] + ts[(2 * ph + 1) * 32 + 2 * pw + 1];
        dst[64 + tid] = s * 0.25f;
    }
}

// ---------------------------------------------------------------------------
// Transpose pooled [b][c][320] -> xp fp16 [b][n][c], rows 320..383 zero.
// 32x32 smem tiles; coalesced both directions.
// ---------------------------------------------------------------------------
__global__ void __launch_bounds__(256) xpose_kernel(
    const float* __restrict__ pooled, __half* __restrict__ xp)
{
    __shared__ float t[32][33];
    const int c0 = blockIdx.x * 32, n0 = blockIdx.y * 32, b = blockIdx.z;
    const int tx = threadIdx.x, ty = threadIdx.y;
    const bool valid = (n0 < NKV);
    if (valid) {
        const float* src = pooled + ((size_t)b * CIN + c0) * NKV + n0;
#pragma unroll
        for (int i = 0; i < 4; i++)
            t[ty + 8 * i][tx] = src[(size_t)(ty + 8 * i) * NKV + tx];
    }
    __syncthreads();
    __half* d = xp + ((size_t)b * NKVP + n0) * KDIM + c0;
#pragma unroll
    for (int i = 0; i < 4; i++)
        d[(size_t)(ty + 8 * i) * KDIM + tx] =
            __float2half_rn(valid ? t[tx][ty + 8 * i] : 0.f);
}

// ---------------------------------------------------------------------------
// HMMA fp16 2-term batched GEMM (unchanged from R7).
// ---------------------------------------------------------------------------
#define STG_SZ  18432
#define T_AL    6144
#define T_B     12288
#define GSMEM   (4 * STG_SZ)

__global__ void __launch_bounds__(256, 2) gemm_mma_kernel(
    const __half* __restrict__ Ah, const __half* __restrict__ Al,
    const __half* __restrict__ B,
    float* __restrict__ C, const float* __restrict__ bias, int Ntot)
{
    extern __shared__ char smem[];
    const uint32_t sbase = smem_u32(smem);

    const int tid = threadIdx.x;
    const int n0 = blockIdx.x * 128;
    const int m0 = blockIdx.y * 128;
    const int M  = gridDim.y * 128;
    const size_t bo = (size_t)blockIdx.z * Ntot * KDIM;
    const size_t co = (size_t)blockIdx.z * M * Ntot;

    const __half* Bb = B + bo;

    const int lrow = tid >> 1, lhalf = tid & 1;
    const uint32_t lso = (uint32_t)(lrow * 48 + lhalf * 16);

    const int wid = tid >> 5, lane = tid & 31;
    const int wm = (wid & 3) * 32, wn = (wid >> 2) * 64;
    const uint32_t aoff = (uint32_t)((wm + (lane & 15)) * 48 + (lane >> 4) * 16);
    const uint32_t boff = (uint32_t)(T_B + (wn + (lane & 15)) * 48 + (lane >> 4) * 16);

    float acc[2][8][4];
#pragma unroll
    for (int f = 0; f < 2; f++)
#pragma unroll
        for (int j = 0; j < 8; j++)
#pragma unroll
            for (int r = 0; r < 4; r++) acc[f][j][r] = 0.f;

#define ISSUE(cc, st) do {                                                    \
        const size_t ga = (size_t)(m0 + lrow) * KDIM + (cc) * 16 + lhalf * 8; \
        const size_t gb = (size_t)(n0 + lrow) * KDIM + (cc) * 16 + lhalf * 8; \
        const uint32_t sp = sbase + (st) * STG_SZ + lso;                      \
        cpasync16(sp,         Ah + ga);                                       \
        cpasync16(sp + T_AL,  Al + ga);                                       \
        cpasync16(sp + T_B,   Bb + gb);                                       \
    } while (0)

    ISSUE(0, 0); CP_COMMIT();
    ISSUE(1, 1); CP_COMMIT();
    ISSUE(2, 2); CP_COMMIT();

    const int NCH = KDIM / 16;
    for (int c = 0; c < NCH; c++) {
        CP_WAIT(2);
        __syncthreads();
        if (c + 3 < NCH) ISSUE(c + 3, (c + 3) & 3);
        CP_COMMIT();

        const uint32_t sa = sbase + (uint32_t)((c & 3) * STG_SZ);
        uint32_t ah[2][4], al[2][4];
        LDSM_X4(ah[0], sa + aoff);
        LDSM_X4(ah[1], sa + aoff + 768);
        LDSM_X4(al[0], sa + aoff + T_AL);
        LDSM_X4(al[1], sa + aoff + T_AL + 768);
#pragma unroll
        for (int g = 0; g < 4; g++) {
            uint32_t bh[4];
            LDSM_X4(bh, sa + boff + g * 768);
#pragma unroll
            for (int f = 0; f < 2; f++) {
                mma_f16(acc[f][2 * g],     ah[f], bh[0], bh[2]);
                mma_f16(acc[f][2 * g],     al[f], bh[0], bh[2]);
                mma_f16(acc[f][2 * g + 1], ah[f], bh[1], bh[3]);
                mma_f16(acc[f][2 * g + 1], al[f], bh[1], bh[3]);
            }
        }
    }
#undef ISSUE

#pragma unroll
    for (int f = 0; f < 2; f++) {
        const int r0 = m0 + wm + f * 16 + (lane >> 2);
        const float bv0 = bias ? bias[r0] : 0.f;
        const float bv1 = bias ? bias[r0 + 8] : 0.f;
        float* cp0 = C + co + (size_t)r0 * Ntot;
        float* cp1 = cp0 + (size_t)8 * Ntot;
#pragma unroll
        for (int j = 0; j < 8; j++) {
            const int col = n0 + wn + j * 8 + (lane & 3) * 2;
            float2 v0 = make_float2(acc[f][j][0] + bv0, acc[f][j][1] + bv0);
            float2 v1 = make_float2(acc[f][j][2] + bv1, acc[f][j][3] + bv1);
            *(float2*)(cp0 + col) = v0;
            *(float2*)(cp1 + col) = v1;
        }
    }
}

// ---------------------------------------------------------------------------
// kv gates.  K: smem 64x64 tile transpose -> [b,h,n,d] coalesced.
//            V: elementwise, already coalesced -> [b,h,d,n].
// ---------------------------------------------------------------------------
__global__ void __launch_bounds__(256) kvgate_k_kernel(
    const float* __restrict__ kvp, __half* __restrict__ khg)
{
    __shared__ float t[64 * 65];
    const int n0 = blockIdx.x * 64;      // 5 tiles
    const int h = blockIdx.y, b = blockIdx.z;
    const int tid = threadIdx.x;

    // read: row = channel d, cols = n'  (coalesced 256B rows)
#pragma unroll
    for (int j = 0; j < 16; j++) {
        const int idx = tid + j * 256;
        const int d = idx >> 6, np = idx & 63;
        t[np * 65 + d] = kvp[((size_t)(b * 1024 + h * 64 + d)) * NKVP + n0 + np];
    }
    __syncthreads();

    __half* dst = khg + ((size_t)(b * HEADS + h) * NKV + n0) * DH;
#pragma unroll
    for (int j = 0; j < 16; j++) {
        const int idx = tid + j * 256;
        const int np = idx >> 6, d = idx & 63;
        const float v = t[np * 65 + d];
        dst[(size_t)np * DH + d] = __float2half_rn(1.f / (1.f + __expf(-v)));
    }
}

__global__ void __launch_bounds__(256) kvgate_v_kernel(
    const float* __restrict__ kvp, __half* __restrict__ vhg)
{
    const int c = blockIdx.x;             // 0..511 (V channels)
    const int b = blockIdx.y;
    const float* src = kvp + ((size_t)(b * 1024 + 512 + c)) * NKVP;
    __half* dst = vhg + ((size_t)((b * HEADS + (c >> 6)) * DH + (c & 63))) * NKV;
    for (int n = threadIdx.x; n < NKV; n += 256) {
        dst[n] = __float2half_rn(1.f / (1.f + __expf(-src[n])));
    }
}

// ---------------------------------------------------------------------------
// MMA attention: TQ=32, single-fp16 Q/K/V, 2 CTAs/SM.
// ---------------------------------------------------------------------------
#define TQ       32
#define Q_ROW    144
#define K_ROW    144
#define V_ROW    656
#define SC_ROWB  1296
#define A_Q      0
#define A_K      4608
#define A_V      4608
#define A_SC     50688
#define A_INV    92160
#define ATTN2_SMEM 92288

__global__ void __launch_bounds__(256, 2) attn_mma_kernel(
    const float* __restrict__ q,
    const __half* __restrict__ khg, const __half* __restrict__ vhg,
    const float* __restrict__ pos,
    __half* __restrict__ att)
{
    extern __shared__ char sm[];
    const uint32_t sb = smem_u32(sm);
    const int b = blockIdx.z, hd = blockIdx.y;
    const int s0 = blockIdx.x * TQ;
    const int tid = threadIdx.x, wid = tid >> 5, lane = tid & 31;

    {
        const char* kh = (const char*)(khg + (size_t)(b * HEADS + hd) * NKV * DH);
#pragma unroll
        for (int i = 0; i < 10; i++) {
            const int c = tid + i * 256;
            cpasync16(sb + A_K + (c >> 3) * K_ROW + (c & 7) * 16,
                      kh + (size_t)c * 16);
        }
        CP_COMMIT();
    }
    {
        const float* qg = q + ((size_t)b * CIN + hd * DH) * S + s0;
#pragma unroll
        for (int i = 0; i < 8; i++) {
            const int idx = tid + i * 256;
            const int dd = idx >> 5, si = idx & 31;
            const float v = qg[(size_t)dd * S + si] * 0.125f;
            *(__half*)(sm + A_Q + si * Q_ROW + dd * 2) = __float2half_rn(v);
        }
    }
    CP_WAIT(0);
    __syncthreads();

    const int mw = wid & 1;

    {
        const int n0w = (wid >> 1) * 80;
        float acc[10][4];
#pragma unroll
        for (int t = 0; t < 10; t++) {
            acc[t][0] = 0.f; acc[t][1] = 0.f; acc[t][2] = 0.f; acc[t][3] = 0.f;
        }
#pragma unroll
        for (int k = 0; k < 4; k++) {
            uint32_t ah[4];
            LDSM_X4(ah, sb + A_Q + (mw * 16 + (lane & 15)) * Q_ROW
                        + (lane >> 4) * 16 + k * 32);
#pragma unroll
            for (int jn = 0; jn < 5; jn++) {
                uint32_t bh[4];
                LDSM_X4(bh, sb + A_K + (n0w + jn * 16 + (lane & 15)) * K_ROW
                            + (lane >> 4) * 16 + k * 32);
                mma_f16(acc[2 * jn],     ah, bh[0], bh[2]);
                mma_f16(acc[2 * jn + 1], ah, bh[1], bh[3]);
            }
        }
        const int r0 = mw * 16 + (lane >> 2);
#pragma unroll
        for (int jn = 0; jn < 5; jn++)
#pragma unroll
            for (int t = 0; t < 2; t++) {
                const int n = n0w + jn * 16 + t * 8 + (lane & 3) * 2;
                float* p0 = (float*)(sm + A_SC + r0 * SC_ROWB) + n;
                float* p1 = (float*)(sm + A_SC + (r0 + 8) * SC_ROWB) + n;
                *(float2*)p0 = make_float2(acc[2 * jn + t][0], acc[2 * jn + t][1]);
                *(float2*)p1 = make_float2(acc[2 * jn + t][2], acc[2 * jn + t][3]);
            }
    }
    __syncthreads();

    {
        const char* vh = (const char*)(vhg + (size_t)(b * HEADS + hd) * DH * NKV);
#pragma unroll
        for (int i = 0; i < 10; i++) {
            const int c = tid + i * 256;
            const int d = c / 40, o = c % 40;
            cpasync16(sb + A_V + d * V_ROW + o * 16, vh + (size_t)c * 16);
        }
        CP_COMMIT();
    }

    {
        const int r = tid >> 3, cq = tid & 7;
        float* row = (float*)(sm + A_SC + r * SC_ROWB);
        __half* ph = (__half*)(sm + A_SC + r * SC_ROWB);
        const float* pr = pos + (size_t)(s0 + r) * NKV;
        float mx = -1e30f;
#pragma unroll
        for (int k = cq; k < NKV; k += 8) {
            const float v = row[k] + pr[k];
            row[k] = v;
            mx = fmaxf(mx, v);
        }
        mx = fmaxf(mx, __shfl_xor_sync(0xffffffffu, mx, 1));
        mx = fmaxf(mx, __shfl_xor_sync(0xffffffffu, mx, 2));
        mx = fmaxf(mx, __shfl_xor_sync(0xffffffffu, mx, 4));
        float ssum = 0.f;
#pragma unroll
        for (int c5 = 0; c5 < 5; c5++) {
            float e[8];
#pragma unroll
            for (int j = 0; j < 8; j++) {
                e[j] = __expf(row[c5 * 64 + cq + 8 * j] - mx);
                ssum += e[j];
            }
            __syncwarp();
#pragma unroll
            for (int j = 0; j < 8; j++)
                ph[c5 * 64 + cq + 8 * j] = __float2half_rn(e[j]);
            __syncwarp();
        }
        ssum += __shfl_xor_sync(0xffffffffu, ssum, 1);
        ssum += __shfl_xor_sync(0xffffffffu, ssum, 2);
        ssum += __shfl_xor_sync(0xffffffffu, ssum, 4);
        if (cq == 0) *(float*)(sm + A_INV + r * 4) = 1.f / ssum;
    }
    CP_WAIT(0);
    __syncthreads();

    {
        const int dw = wid >> 1;
        float oa[2][4];
        oa[0][0] = oa[0][1] = oa[0][2] = oa[0][3] = 0.f;
        oa[1][0] = oa[1][1] = oa[1][2] = oa[1][3] = 0.f;
#pragma unroll
        for (int k = 0; k < 20; k++) {
            uint32_t pa[4], vv[4];
            LDSM_X4(pa, sb + A_SC + (mw * 16 + (lane & 15)) * SC_ROWB
                        + (lane >> 4) * 16 + k * 32);
            LDSM_X4(vv, sb + A_V + (dw * 16 + (lane & 15)) * V_ROW
                        + (lane >> 4) * 16 + k * 32);
            mma_f16(oa[0], pa, vv[0], vv[2]);
            mma_f16(oa[1], pa, vv[1], vv[3]);
        }
        const float inv0 = *(const float*)(sm + A_INV + (mw * 16 + (lane >> 2)) * 4);
        const float inv1 = *(const float*)(sm + A_INV + (mw * 16 + 8 + (lane >> 2)) * 4);
        const size_t ro0 = ((size_t)b * S + s0 + mw * 16 + (lane >> 2)) * CIN + hd * DH;
        const size_t ro1 = ro0 + (size_t)8 * CIN;
#pragma unroll
        for (int jt = 0; jt < 2; jt++) {
            const int col = dw * 16 + jt * 8 + (lane & 3) * 2;
            __half2 h0 = __floats2half2_rn(oa[jt][0] * inv0, oa[jt][1] * inv0);
            __half2 h1 = __floats2half2_rn(oa[jt][2] * inv1, oa[jt][3] * inv1);
            *(__half2*)(att + ro0 + col) = h0;
            *(__half2*)(att + ro1 + col) = h1;
        }
    }
}

// ---------------------------------------------------------------------------
// Launch
// ---------------------------------------------------------------------------
extern "C" void kernel_launch(void* const* d_in, const int* in_sizes, int n_in,
                              void* d_out, int out_size)
{
    const float* x     = (const float*)d_in[0];
    const float* Wqkv  = (const float*)d_in[1];
    const float* Wout  = (const float*)d_in[2];
    const float* bout  = (const float*)d_in[3];
    const float* pos   = (const float*)d_in[4];
    float* out = (float*)d_out;

    float *p_q, *p_kvp, *p_pool;
    __half *p_x, *p_xp, *p_kh, *p_vh, *p_at, *p_wqh, *p_wql, *p_woh, *p_wol;
    cudaGetSymbolAddress((void**)&p_q,    g_q);
    cudaGetSymbolAddress((void**)&p_kvp,  g_kvp);
    cudaGetSymbolAddress((void**)&p_pool, g_pool);
    cudaGetSymbolAddress((void**)&p_x,    g_x);
    cudaGetSymbolAddress((void**)&p_xp,   g_xp);
    cudaGetSymbolAddress((void**)&p_kh,   g_kh);
    cudaGetSymbolAddress((void**)&p_vh,   g_vh);
    cudaGetSymbolAddress((void**)&p_at,   g_at);
    cudaGetSymbolAddress((void**)&p_wqh,  g_wqh);
    cudaGetSymbolAddress((void**)&p_wql,  g_wql);
    cudaGetSymbolAddress((void**)&p_woh,  g_woh);
    cudaGetSymbolAddress((void**)&p_wol,  g_wol);

    cudaFuncSetAttribute(gemm_mma_kernel,
                         cudaFuncAttributeMaxDynamicSharedMemorySize, GSMEM);
    cudaFuncSetAttribute(attn_mma_kernel,
                         cudaFuncAttributeMaxDynamicSharedMemorySize, ATTN2_SMEM);

    // 0) operand prep
    split_kernel<<<(QKVC * KDIM + 255) / 256, 256>>>(Wqkv, p_wqh, p_wql, QKVC * KDIM);
    split_kernel<<<(COUT * KDIM + 255) / 256, 256>>>(Wout, p_woh, p_wol, COUT * KDIM);
    tsplit_kernel<<<dim3(S / 32, KDIM / 32, BATCH), dim3(32, 8)>>>(x, p_x);
    pool_x_kernel<<<BATCH * CIN, 256>>>(x, p_pool);
    xpose_kernel<<<dim3(KDIM / 32, NKVP / 32, BATCH), dim3(32, 8)>>>(p_pool, p_xp);

    // 1) Q = Wq @ x^T   [B,512,1024]
    gemm_mma_kernel<<<dim3(S / 128, CIN / 128, BATCH), 256, GSMEM>>>(
        p_wqh, p_wql, p_x, p_q, nullptr, S);

    // 2) kv_pre = Wkv @ xp^T   [B,1024,384]
    gemm_mma_kernel<<<dim3(NKVP / 128, 1024 / 128, BATCH), 256, GSMEM>>>(
        p_wqh + (size_t)CIN * KDIM, p_wql + (size_t)CIN * KDIM,
        p_xp, p_kvp, nullptr, NKVP);

    // 3) sigmoid gates -> K (tiled transpose), V (elementwise)
    kvgate_k_kernel<<<dim3(NKV / 64, HEADS, BATCH), 256>>>(p_kvp, p_kh);
    kvgate_v_kernel<<<dim3(512, BATCH), 256>>>(p_kvp, p_vh);

    // 4) tensor-core attention -> att fp16 [B,S,C]
    attn_mma_kernel<<<dim3(S / TQ, HEADS, BATCH), 256, ATTN2_SMEM>>>(
        p_q, p_kh, p_vh, pos, p_at);

    // 5) out = Wout @ att^T + bout   [B,512,1024]
    gemm_mma_kernel<<<dim3(S / 128, COUT / 128, BATCH), 256, GSMEM>>>(
        p_woh, p_wol, p_at, out, bout, S);
}

// round 11
// speedup vs baseline: 4.5610x; 1.0170x over previous
#include <cuda_runtime.h>
#include <cuda_bf16.h>
#include <cuda_fp16.h>
#include <math.h>
#include <stdint.h>

// ---------------------------------------------------------------------------
// Problem constants
// ---------------------------------------------------------------------------
#define BATCH   32
#define CIN     512
#define COUT    512
#define HEADS   8
#define DH      64
#define S       1024
#define NKV     320
#define NKVP    384
#define QKVC    1536
#define KDIM    512

// ---------------------------------------------------------------------------
// Scratch (device globals)
// ---------------------------------------------------------------------------
__device__ float g_kvp [(size_t)BATCH * 1024 * NKVP];             // kv pre-sigmoid
__device__ float g_pool[(size_t)BATCH * CIN * NKV];               // pooled x fp32
__device__ __align__(16) __half g_qh [(size_t)BATCH * CIN * S];   // Q fp16 (pre-scaled)
__device__ __align__(16) __half g_x  [(size_t)BATCH * S * KDIM];  // xT fp16
__device__ __align__(16) __half g_xp [(size_t)BATCH * NKVP * KDIM];
__device__ __align__(16) __half g_kh [(size_t)BATCH * HEADS * NKV * DH]; // K [b,h,n,d]
__device__ __align__(16) __half g_vh [(size_t)BATCH * HEADS * DH * NKV]; // V [b,h,d,n]
__device__ __align__(16) __half g_at [(size_t)BATCH * S * CIN];   // att fp16 [B,S,C]
__device__ __align__(16) __half g_wqh[(size_t)QKVC * KDIM];
__device__ __align__(16) __half g_wql[(size_t)QKVC * KDIM];
__device__ __align__(16) __half g_woh[(size_t)COUT * KDIM];
__device__ __align__(16) __half g_wol[(size_t)COUT * KDIM];

// ---------------------------------------------------------------------------
// PTX helpers
// ---------------------------------------------------------------------------
__device__ __forceinline__ uint32_t smem_u32(const void* p) {
    uint32_t a;
    asm("{ .reg .u64 t; cvta.to.shared.u64 t, %1; cvt.u32.u64 %0, t; }"
        : "=r"(a) : "l"(p));
    return a;
}
__device__ __forceinline__ void cpasync16(uint32_t s, const void* g) {
    asm volatile("cp.async.cg.shared.global [%0], [%1], 16;" :: "r"(s), "l"(g));
}
#define CP_COMMIT() asm volatile("cp.async.commit_group;" ::: "memory")
#define CP_WAIT(N)  asm volatile("cp.async.wait_group %0;" :: "n"(N) : "memory")

#define LDSM_X4(r, addr) \
    asm volatile("ldmatrix.sync.aligned.m8n8.x4.shared.b16 {%0,%1,%2,%3}, [%4];" \
                 : "=r"((r)[0]), "=r"((r)[1]), "=r"((r)[2]), "=r"((r)[3]) : "r"(addr))
#define LDSM_X4_T(r, addr) \
    asm volatile("ldmatrix.sync.aligned.m8n8.x4.trans.shared.b16 {%0,%1,%2,%3}, [%4];" \
                 : "=r"((r)[0]), "=r"((r)[1]), "=r"((r)[2]), "=r"((r)[3]) : "r"(addr))

__device__ __forceinline__ void mma_f16(float* d, const uint32_t* a,
                                        uint32_t b0, uint32_t b1) {
    asm volatile(
        "mma.sync.aligned.m16n8k16.row.col.f32.f16.f16.f32 "
        "{%0,%1,%2,%3}, {%4,%5,%6,%7}, {%8,%9}, {%0,%1,%2,%3};"
        : "+f"(d[0]), "+f"(d[1]), "+f"(d[2]), "+f"(d[3])
        : "r"(a[0]), "r"(a[1]), "r"(a[2]), "r"(a[3]), "r"(b0), "r"(b1));
}

// ---------------------------------------------------------------------------
// Weight prep: fp32 -> fp16 hi/lo with optional scale fold.
// ---------------------------------------------------------------------------
__global__ void split_kernel(const float* __restrict__ a,
                             __half* __restrict__ h, __half* __restrict__ l,
                             int n, float scale)
{
    int i = blockIdx.x * 256 + threadIdx.x;
    if (i < n) {
        float v = a[i] * scale;
        __half hi = __float2half_rn(v);
        h[i] = hi;
        l[i] = __float2half_rn(v - __half2float(hi));
    }
}

__global__ void __launch_bounds__(256) tsplit_kernel(
    const float* __restrict__ x, __half* __restrict__ o)
{
    __shared__ float t[32][33];
    const int n0 = blockIdx.x * 32, k0 = blockIdx.y * 32, b = blockIdx.z;
    const int tx = threadIdx.x, ty = threadIdx.y;
    const float* src = x + ((size_t)b * KDIM + k0) * S + n0;
#pragma unroll
    for (int i = 0; i < 4; i++)
        t[ty + 8 * i][tx] = src[(size_t)(ty + 8 * i) * S + tx];
    __syncthreads();
    __half* d = o + ((size_t)b * S + n0) * KDIM + k0;
#pragma unroll
    for (int i = 0; i < 4; i++)
        d[(size_t)(ty + 8 * i) * KDIM + tx] = __float2half_rn(t[tx][ty + 8 * i]);
}

// ---------------------------------------------------------------------------
// Pool x -> pooled fp32 [b][c][320]
// ---------------------------------------------------------------------------
__global__ void __launch_bounds__(256) pool_x_kernel(
    const float* __restrict__ x, float* __restrict__ pooled)
{
    const int bc = blockIdx.x;
    const float* src = x + (size_t)bc * S;
    float* dst = pooled + (size_t)bc * NKV;

    __shared__ float ts[S];
    const int tid = threadIdx.x;
    ((float4*)ts)[tid] = ((const float4*)src)[tid];
    __syncthreads();

    if (tid < 32) {
        float s = 0.f;
#pragma unroll
        for (int w = 0; w < 32; w++) s += ts[tid * 32 + w];
        dst[tid] = s * (1.f / 32.f);
    } else if (tid < 64) {
        const int w = tid - 32;
        float s = 0.f;
#pragma unroll
        for (int hh = 0; hh < 32; hh++) s += ts[hh * 32 + w];
        dst[tid] = s * (1.f / 32.f);
    }
    {
        const int ph = tid >> 4, pw = tid & 15;
        const float s = ts[(2 * ph) * 32 + 2 * pw] + ts[(2 * ph) * 32 + 2 * pw + 1]
                      + ts[(2 * ph + 1) * 32 + 2 * pw] + ts[(2 * ph + 1) * 32 + 2 * pw + 1];
        dst[64 + tid] = s * 0.25f;
    }
}

// ---------------------------------------------------------------------------
// Transpose pooled [b][c][320] -> xp fp16 [b][n][c]; rows 320..383 zero.
// ---------------------------------------------------------------------------
__global__ void __launch_bounds__(256) xpose_kernel(
    const float* __restrict__ pooled, __half* __restrict__ xp)
{
    __shared__ float t[32][33];
    const int c0 = blockIdx.x * 32, n0 = blockIdx.y * 32, b = blockIdx.z;
    const int tx = threadIdx.x, ty = threadIdx.y;
    const bool valid = (n0 < NKV);
    if (valid) {
        const float* src = pooled + ((size_t)b * CIN + c0) * NKV + n0;
#pragma unroll
        for (int i = 0; i < 4; i++)
            t[ty + 8 * i][tx] = src[(size_t)(ty + 8 * i) * NKV + tx];
    }
    __syncthreads();
    __half* d = xp + ((size_t)b * NKVP + n0) * KDIM + c0;
#pragma unroll
    for (int i = 0; i < 4; i++)
        d[(size_t)(ty + 8 * i) * KDIM + tx] =
            __float2half_rn(valid ? t[tx][ty + 8 * i] : 0.f);
}

// ---------------------------------------------------------------------------
// HMMA fp16 2-term batched GEMM.  k-chunk 32 (80B rows), 3-stage, 2 CTAs/SM.
// Per-tile = 128 rows * 80B = 10240 B.  Stage = 3 tiles = 30720 B.
// ---------------------------------------------------------------------------
#define T_AL    10240
#define T_B     20480
#define STG_SZ  30720
#define GSMEM   (3 * STG_SZ)       // 92160 B

__global__ void __launch_bounds__(256, 2) gemm_mma_kernel(
    const __half* __restrict__ Ah, const __half* __restrict__ Al,
    const __half* __restrict__ B,
    float* __restrict__ C, __half* __restrict__ Ch,
    const float* __restrict__ bias, int Ntot)
{
    extern __shared__ char smem[];
    const uint32_t sbase = smem_u32(smem);

    const int tid = threadIdx.x;
    const int n0 = blockIdx.x * 128;
    const int m0 = blockIdx.y * 128;
    const int M  = gridDim.y * 128;
    const size_t bo = (size_t)blockIdx.z * Ntot * KDIM;
    const size_t co = (size_t)blockIdx.z * M * Ntot;

    const __half* Bb = B + bo;

    const int wid = tid >> 5, lane = tid & 31;
    const int wm = (wid & 3) * 32, wn = (wid >> 2) * 64;
    const uint32_t aoff = (uint32_t)((wm + (lane & 15)) * 80 + (lane >> 4) * 16);
    const uint32_t boff = (uint32_t)(T_B + (wn + (lane & 15)) * 80 + (lane >> 4) * 16);

    float acc[2][8][4];
#pragma unroll
    for (int f = 0; f < 2; f++)
#pragma unroll
        for (int j = 0; j < 8; j++)
#pragma unroll
            for (int r = 0; r < 4; r++) acc[f][j][r] = 0.f;

#define ISSUE(cc, st) do {                                                     \
        const uint32_t sp = sbase + (st) * STG_SZ;                             \
        _Pragma("unroll")                                                      \
        for (int it = 0; it < 2; it++) {                                       \
            const int idx = tid + it * 256;                                    \
            const int row = idx >> 2, ch = idx & 3;                            \
            const uint32_t so = (uint32_t)(row * 80 + ch * 16);                \
            const size_t ga = (size_t)(m0 + row) * KDIM + (cc) * 32 + ch * 8;  \
            const size_t gb = (size_t)(n0 + row) * KDIM + (cc) * 32 + ch * 8;  \
            cpasync16(sp + so,        Ah + ga);                                \
            cpasync16(sp + T_AL + so, Al + ga);                                \
            cpasync16(sp + T_B + so,  Bb + gb);                                \
        }                                                                      \
    } while (0)

    ISSUE(0, 0); CP_COMMIT();
    ISSUE(1, 1); CP_COMMIT();

    const int NCH = KDIM / 32;       // 16
    int st = 0, stn = 2;
    for (int c = 0; c < NCH; c++) {
        CP_WAIT(1);                  // chunk c resident
        __syncthreads();             // safe to overwrite stage stn
        if (c + 2 < NCH) ISSUE(c + 2, stn);
        CP_COMMIT();

        const uint32_t sa = sbase + (uint32_t)(st * STG_SZ);
#pragma unroll
        for (int kk = 0; kk < 2; kk++) {
            uint32_t ah[2][4], al[2][4];
            LDSM_X4(ah[0], sa + aoff + kk * 32);
            LDSM_X4(ah[1], sa + aoff + kk * 32 + 1280);
            LDSM_X4(al[0], sa + T_AL + aoff + kk * 32);
            LDSM_X4(al[1], sa + T_AL + aoff + kk * 32 + 1280);
#pragma unroll
            for (int g = 0; g < 4; g++) {
                uint32_t bh[4];
                LDSM_X4(bh, sa + boff + kk * 32 + g * 1280);
#pragma unroll
                for (int f = 0; f < 2; f++) {
                    mma_f16(acc[f][2 * g],     ah[f], bh[0], bh[2]);
                    mma_f16(acc[f][2 * g],     al[f], bh[0], bh[2]);
                    mma_f16(acc[f][2 * g + 1], ah[f], bh[1], bh[3]);
                    mma_f16(acc[f][2 * g + 1], al[f], bh[1], bh[3]);
                }
            }
        }
        st = (st == 2) ? 0 : st + 1;
        stn = (stn == 2) ? 0 : stn + 1;
    }
#undef ISSUE

    if (Ch) {
#pragma unroll
        for (int f = 0; f < 2; f++) {
            const int r0 = m0 + wm + f * 16 + (lane >> 2);
            __half* cp0 = Ch + co + (size_t)r0 * Ntot;
            __half* cp1 = cp0 + (size_t)8 * Ntot;
#pragma unroll
            for (int j = 0; j < 8; j++) {
                const int col = n0 + wn + j * 8 + (lane & 3) * 2;
                *(__half2*)(cp0 + col) = __floats2half2_rn(acc[f][j][0], acc[f][j][1]);
                *(__half2*)(cp1 + col) = __floats2half2_rn(acc[f][j][2], acc[f][j][3]);
            }
        }
    } else {
#pragma unroll
        for (int f = 0; f < 2; f++) {
            const int r0 = m0 + wm + f * 16 + (lane >> 2);
            const float bv0 = bias ? bias[r0] : 0.f;
            const float bv1 = bias ? bias[r0 + 8] : 0.f;
            float* cp0 = C + co + (size_t)r0 * Ntot;
            float* cp1 = cp0 + (size_t)8 * Ntot;
#pragma unroll
            for (int j = 0; j < 8; j++) {
                const int col = n0 + wn + j * 8 + (lane & 3) * 2;
                *(float2*)(cp0 + col) = make_float2(acc[f][j][0] + bv0, acc[f][j][1] + bv0);
                *(float2*)(cp1 + col) = make_float2(acc[f][j][2] + bv1, acc[f][j][3] + bv1);
            }
        }
    }
}

// ---------------------------------------------------------------------------
// kv gates.  K: smem 64x64 tile transpose; V: elementwise.
// ---------------------------------------------------------------------------
__global__ void __launch_bounds__(256) kvgate_k_kernel(
    const float* __restrict__ kvp, __half* __restrict__ khg)
{
    __shared__ float t[64 * 65];
    const int n0 = blockIdx.x * 64;
    const int h = blockIdx.y, b = blockIdx.z;
    const int tid = threadIdx.x;

#pragma unroll
    for (int j = 0; j < 16; j++) {
        const int idx = tid + j * 256;
        const int d = idx >> 6, np = idx & 63;
        t[np * 65 + d] = kvp[((size_t)(b * 1024 + h * 64 + d)) * NKVP + n0 + np];
    }
    __syncthreads();

    __half* dst = khg + ((size_t)(b * HEADS + h) * NKV + n0) * DH;
#pragma unroll
    for (int j = 0; j < 16; j++) {
        const int idx = tid + j * 256;
        const int np = idx >> 6, d = idx & 63;
        const float v = t[np * 65 + d];
        dst[(size_t)np * DH + d] = __float2half_rn(1.f / (1.f + __expf(-v)));
    }
}

__global__ void __launch_bounds__(256) kvgate_v_kernel(
    const float* __restrict__ kvp, __half* __restrict__ vhg)
{
    const int c = blockIdx.x;
    const int b = blockIdx.y;
    const float* src = kvp + ((size_t)(b * 1024 + 512 + c)) * NKVP;
    __half* dst = vhg + ((size_t)((b * HEADS + (c >> 6)) * DH + (c & 63))) * NKV;
    for (int n = threadIdx.x; n < NKV; n += 256) {
        dst[n] = __float2half_rn(1.f / (1.f + __expf(-src[n])));
    }
}

// ---------------------------------------------------------------------------
// MMA attention: TQ=32, fp16 Q (pre-scaled) loaded [dd][si] + ldmatrix.trans.
// ---------------------------------------------------------------------------
#define TQ       32
#define Q_ROW    80
#define K_ROW    144
#define V_ROW    656
#define SC_ROWB  1296
#define A_Q      0
#define A_K      5120
#define A_V      5120
#define A_SC     51200
#define A_INV    92672
#define ATTN2_SMEM 92800

__global__ void __launch_bounds__(256, 2) attn_mma_kernel(
    const __half* __restrict__ qh,
    const __half* __restrict__ khg, const __half* __restrict__ vhg,
    const float* __restrict__ pos,
    __half* __restrict__ att)
{
    extern __shared__ char sm[];
    const uint32_t sb = smem_u32(sm);
    const int b = blockIdx.z, hd = blockIdx.y;
    const int s0 = blockIdx.x * TQ;
    const int tid = threadIdx.x, wid = tid >> 5, lane = tid & 31;

    // ---- K via cp.async: [n][d], 320 rows x 128B ----
    {
        const char* kh = (const char*)(khg + (size_t)(b * HEADS + hd) * NKV * DH);
#pragma unroll
        for (int i = 0; i < 10; i++) {
            const int c = tid + i * 256;
            cpasync16(sb + A_K + (c >> 3) * K_ROW + (c & 7) * 16,
                      kh + (size_t)c * 16);
        }
    }
    // ---- Q via cp.async: [dd][si], 64 rows x 64B, stride 80 ----
    {
        const __half* qg = qh + ((size_t)b * CIN + hd * DH) * S + s0;
        const int row = tid >> 2, ch = tid & 3;
        cpasync16(sb + A_Q + row * Q_ROW + ch * 16, qg + (size_t)row * S + ch * 8);
    }
    CP_COMMIT();
    CP_WAIT(0);
    __syncthreads();

    const int mw = wid & 1;

    // ---- QK^T (A via ldmatrix.trans from [dd][si]) ----
    {
        const int n0w = (wid >> 1) * 80;
        const uint32_t qaddr0 = sb + A_Q
            + (uint32_t)(((lane & 7) + ((lane >> 4) << 3)) * Q_ROW
            + (mw * 16 + (((lane >> 3) & 1) << 3)) * 2);
        float acc[10][4];
#pragma unroll
        for (int t = 0; t < 10; t++) {
            acc[t][0] = 0.f; acc[t][1] = 0.f; acc[t][2] = 0.f; acc[t][3] = 0.f;
        }
#pragma unroll
        for (int k = 0; k < 4; k++) {
            uint32_t ah[4];
            LDSM_X4_T(ah, qaddr0 + k * 16 * Q_ROW);
#pragma unroll
            for (int jn = 0; jn < 5; jn++) {
                uint32_t bh[4];
                LDSM_X4(bh, sb + A_K + (n0w + jn * 16 + (lane & 15)) * K_ROW
                            + (lane >> 4) * 16 + k * 32);
                mma_f16(acc[2 * jn],     ah, bh[0], bh[2]);
                mma_f16(acc[2 * jn + 1], ah, bh[1], bh[3]);
            }
        }
        const int r0 = mw * 16 + (lane >> 2);
#pragma unroll
        for (int jn = 0; jn < 5; jn++)
#pragma unroll
            for (int t = 0; t < 2; t++) {
                const int n = n0w + jn * 16 + t * 8 + (lane & 3) * 2;
                float* p0 = (float*)(sm + A_SC + r0 * SC_ROWB) + n;
                float* p1 = (float*)(sm + A_SC + (r0 + 8) * SC_ROWB) + n;
                *(float2*)p0 = make_float2(acc[2 * jn + t][0], acc[2 * jn + t][1]);
                *(float2*)p1 = make_float2(acc[2 * jn + t][2], acc[2 * jn + t][3]);
            }
    }
    __syncthreads();

    // ---- V into dead K region: [d][n], 64 rows x 640B ----
    {
        const char* vh = (const char*)(vhg + (size_t)(b * HEADS + hd) * DH * NKV);
#pragma unroll
        for (int i = 0; i < 10; i++) {
            const int c = tid + i * 256;
            const int d = c / 40, o = c % 40;
            cpasync16(sb + A_V + d * V_ROW + o * 16, vh + (size_t)c * 16);
        }
        CP_COMMIT();
    }

    // ---- softmax ----
    {
        const int r = tid >> 3, cq = tid & 7;
        float* row = (float*)(sm + A_SC + r * SC_ROWB);
        __half* ph = (__half*)(sm + A_SC + r * SC_ROWB);
        const float* pr = pos + (size_t)(s0 + r) * NKV;
        float mx = -1e30f;
#pragma unroll
        for (int k = cq; k < NKV; k += 8) {
            const float v = row[k] + pr[k];
            row[k] = v;
            mx = fmaxf(mx, v);
        }
        mx = fmaxf(mx, __shfl_xor_sync(0xffffffffu, mx, 1));
        mx = fmaxf(mx, __shfl_xor_sync(0xffffffffu, mx, 2));
        mx = fmaxf(mx, __shfl_xor_sync(0xffffffffu, mx, 4));
        float ssum = 0.f;
#pragma unroll
        for (int c5 = 0; c5 < 5; c5++) {
            float e[8];
#pragma unroll
            for (int j = 0; j < 8; j++) {
                e[j] = __expf(row[c5 * 64 + cq + 8 * j] - mx);
                ssum += e[j];
            }
            __syncwarp();
#pragma unroll
            for (int j = 0; j < 8; j++)
                ph[c5 * 64 + cq + 8 * j] = __float2half_rn(e[j]);
            __syncwarp();
        }
        ssum += __shfl_xor_sync(0xffffffffu, ssum, 1);
        ssum += __shfl_xor_sync(0xffffffffu, ssum, 2);
        ssum += __shfl_xor_sync(0xffffffffu, ssum, 4);
        if (cq == 0) *(float*)(sm + A_INV + r * 4) = 1.f / ssum;
    }
    CP_WAIT(0);
    __syncthreads();

    // ---- AV ----
    {
        const int dw = wid >> 1;
        float oa[2][4];
        oa[0][0] = oa[0][1] = oa[0][2] = oa[0][3] = 0.f;
        oa[1][0] = oa[1][1] = oa[1][2] = oa[1][3] = 0.f;
#pragma unroll
        for (int k = 0; k < 20; k++) {
            uint32_t pa[4], vv[4];
            LDSM_X4(pa, sb + A_SC + (mw * 16 + (lane & 15)) * SC_ROWB
                        + (lane >> 4) * 16 + k * 32);
            LDSM_X4(vv, sb + A_V + (dw * 16 + (lane & 15)) * V_ROW
                        + (lane >> 4) * 16 + k * 32);
            mma_f16(oa[0], pa, vv[0], vv[2]);
            mma_f16(oa[1], pa, vv[1], vv[3]);
        }
        const float inv0 = *(const float*)(sm + A_INV + (mw * 16 + (lane >> 2)) * 4);
        const float inv1 = *(const float*)(sm + A_INV + (mw * 16 + 8 + (lane >> 2)) * 4);
        const size_t ro0 = ((size_t)b * S + s0 + mw * 16 + (lane >> 2)) * CIN + hd * DH;
        const size_t ro1 = ro0 + (size_t)8 * CIN;
#pragma unroll
        for (int jt = 0; jt < 2; jt++) {
            const int col = dw * 16 + jt * 8 + (lane & 3) * 2;
            __half2 h0 = __floats2half2_rn(oa[jt][0] * inv0, oa[jt][1] * inv0);
            __half2 h1 = __floats2half2_rn(oa[jt][2] * inv1, oa[jt][3] * inv1);
            *(__half2*)(att + ro0 + col) = h0;
            *(__half2*)(att + ro1 + col) = h1;
        }
    }
}

// ---------------------------------------------------------------------------
// Launch
// ---------------------------------------------------------------------------
extern "C" void kernel_launch(void* const* d_in, const int* in_sizes, int n_in,
                              void* d_out, int out_size)
{
    const float* x     = (const float*)d_in[0];
    const float* Wqkv  = (const float*)d_in[1];
    const float* Wout  = (const float*)d_in[2];
    const float* bout  = (const float*)d_in[3];
    const float* pos   = (const float*)d_in[4];
    float* out = (float*)d_out;

    float *p_kvp, *p_pool;
    __half *p_qh, *p_x, *p_xp, *p_kh, *p_vh, *p_at, *p_wqh, *p_wql, *p_woh, *p_wol;
    cudaGetSymbolAddress((void**)&p_kvp,  g_kvp);
    cudaGetSymbolAddress((void**)&p_pool, g_pool);
    cudaGetSymbolAddress((void**)&p_qh,   g_qh);
    cudaGetSymbolAddress((void**)&p_x,    g_x);
    cudaGetSymbolAddress((void**)&p_xp,   g_xp);
    cudaGetSymbolAddress((void**)&p_kh,   g_kh);
    cudaGetSymbolAddress((void**)&p_vh,   g_vh);
    cudaGetSymbolAddress((void**)&p_at,   g_at);
    cudaGetSymbolAddress((void**)&p_wqh,  g_wqh);
    cudaGetSymbolAddress((void**)&p_wql,  g_wql);
    cudaGetSymbolAddress((void**)&p_woh,  g_woh);
    cudaGetSymbolAddress((void**)&p_wol,  g_wol);

    cudaFuncSetAttribute(gemm_mma_kernel,
                         cudaFuncAttributeMaxDynamicSharedMemorySize, GSMEM);
    cudaFuncSetAttribute(attn_mma_kernel,
                         cudaFuncAttributeMaxDynamicSharedMemorySize, ATTN2_SMEM);

    // 0) operand prep.  Wq gets the 1/sqrt(d)=0.125 scale folded in (exact).
    split_kernel<<<(CIN * KDIM + 255) / 256, 256>>>(Wqkv, p_wqh, p_wql,
                                                    CIN * KDIM, 0.125f);
    split_kernel<<<(1024 * KDIM + 255) / 256, 256>>>(
        Wqkv + (size_t)CIN * KDIM, p_wqh + (size_t)CIN * KDIM,
        p_wql + (size_t)CIN * KDIM, 1024 * KDIM, 1.f);
    split_kernel<<<(COUT * KDIM + 255) / 256, 256>>>(Wout, p_woh, p_wol,
                                                     COUT * KDIM, 1.f);
    tsplit_kernel<<<dim3(S / 32, KDIM / 32, BATCH), dim3(32, 8)>>>(x, p_x);
    pool_x_kernel<<<BATCH * CIN, 256>>>(x, p_pool);
    xpose_kernel<<<dim3(KDIM / 32, NKVP / 32, BATCH), dim3(32, 8)>>>(p_pool, p_xp);

    // 1) Q = (0.125*Wq) @ x^T -> fp16 [B,512,1024]
    gemm_mma_kernel<<<dim3(S / 128, CIN / 128, BATCH), 256, GSMEM>>>(
        p_wqh, p_wql, p_x, nullptr, p_qh, nullptr, S);

    // 2) kv_pre = Wkv @ xp^T   [B,1024,384]
    gemm_mma_kernel<<<dim3(NKVP / 128, 1024 / 128, BATCH), 256, GSMEM>>>(
        p_wqh + (size_t)CIN * KDIM, p_wql + (size_t)CIN * KDIM,
        p_xp, p_kvp, nullptr, nullptr, NKVP);

    // 3) sigmoid gates -> K (tiled transpose), V (elementwise)
    kvgate_k_kernel<<<dim3(NKV / 64, HEADS, BATCH), 256>>>(p_kvp, p_kh);
    kvgate_v_kernel<<<dim3(512, BATCH), 256>>>(p_kvp, p_vh);

    // 4) tensor-core attention -> att fp16 [B,S,C]
    attn_mma_kernel<<<dim3(S / TQ, HEADS, BATCH), 256, ATTN2_SMEM>>>(
        p_qh, p_kh, p_vh, pos, p_at);

    // 5) out = Wout @ att^T + bout   [B,512,1024]
    gemm_mma_kernel<<<dim3(S / 128, COUT / 128, BATCH), 256, GSMEM>>>(
        p_woh, p_wol, p_at, out, nullptr, bout, S);
}

// round 12
// speedup vs baseline: 5.8408x; 1.2806x over previous
#include <cuda_runtime.h>
#include <cuda_bf16.h>
#include <cuda_fp16.h>
#include <math.h>
#include <stdint.h>

// ---------------------------------------------------------------------------
// Problem constants
// ---------------------------------------------------------------------------
#define BATCH   32
#define CIN     512
#define COUT    512
#define HEADS   8
#define DH      64
#define S       1024
#define NKV     320
#define NKVP    384
#define QKVC    1536
#define KDIM    512

// ---------------------------------------------------------------------------
// Scratch (device globals)
// ---------------------------------------------------------------------------
__device__ float g_kvp [(size_t)BATCH * 1024 * NKVP];             // kv pre-sigmoid
__device__ float g_pool[(size_t)BATCH * CIN * NKV];               // pooled x fp32
__device__ __align__(16) __half g_qh [(size_t)BATCH * CIN * S];   // Q fp16 (pre-scaled)
__device__ __align__(16) __half g_x  [(size_t)BATCH * S * KDIM];  // xT fp16
__device__ __align__(16) __half g_xp [(size_t)BATCH * NKVP * KDIM];
__device__ __align__(16) __half g_kh [(size_t)BATCH * HEADS * NKV * DH]; // K [b,h,n,d]
__device__ __align__(16) __half g_vh [(size_t)BATCH * HEADS * DH * NKV]; // V [b,h,d,n]
__device__ __align__(16) __half g_at [(size_t)BATCH * S * CIN];   // att fp16 [B,S,C]
__device__ __align__(16) __half g_wq [(size_t)QKVC * KDIM];       // Wqkv fp16 (Wq pre-scaled)
__device__ __align__(16) __half g_wo [(size_t)COUT * KDIM];       // Wout fp16

// ---------------------------------------------------------------------------
// PTX helpers
// ---------------------------------------------------------------------------
__device__ __forceinline__ uint32_t smem_u32(const void* p) {
    uint32_t a;
    asm("{ .reg .u64 t; cvta.to.shared.u64 t, %1; cvt.u32.u64 %0, t; }"
        : "=r"(a) : "l"(p));
    return a;
}
__device__ __forceinline__ void cpasync16(uint32_t s, const void* g) {
    asm volatile("cp.async.cg.shared.global [%0], [%1], 16;" :: "r"(s), "l"(g));
}
#define CP_COMMIT() asm volatile("cp.async.commit_group;" ::: "memory")
#define CP_WAIT(N)  asm volatile("cp.async.wait_group %0;" :: "n"(N) : "memory")

#define LDSM_X4(r, addr) \
    asm volatile("ldmatrix.sync.aligned.m8n8.x4.shared.b16 {%0,%1,%2,%3}, [%4];" \
                 : "=r"((r)[0]), "=r"((r)[1]), "=r"((r)[2]), "=r"((r)[3]) : "r"(addr))
#define LDSM_X4_T(r, addr) \
    asm volatile("ldmatrix.sync.aligned.m8n8.x4.trans.shared.b16 {%0,%1,%2,%3}, [%4];" \
                 : "=r"((r)[0]), "=r"((r)[1]), "=r"((r)[2]), "=r"((r)[3]) : "r"(addr))

__device__ __forceinline__ void mma_f16(float* d, const uint32_t* a,
                                        uint32_t b0, uint32_t b1) {
    asm volatile(
        "mma.sync.aligned.m16n8k16.row.col.f32.f16.f16.f32 "
        "{%0,%1,%2,%3}, {%4,%5,%6,%7}, {%8,%9}, {%0,%1,%2,%3};"
        : "+f"(d[0]), "+f"(d[1]), "+f"(d[2]), "+f"(d[3])
        : "r"(a[0]), "r"(a[1]), "r"(a[2]), "r"(a[3]), "r"(b0), "r"(b1));
}

// ---------------------------------------------------------------------------
// Weight prep: fp32 -> fp16; Wq region gets 0.125 scale folded (exact pow2).
// ---------------------------------------------------------------------------
__global__ void cvt_wqkv_kernel(const float* __restrict__ a, __half* __restrict__ h)
{
    int i = blockIdx.x * 256 + threadIdx.x;
    if (i < QKVC * KDIM) {
        const float sc = (i < CIN * KDIM) ? 0.125f : 1.f;
        h[i] = __float2half_rn(a[i] * sc);
    }
}
__global__ void cvt_kernel(const float* __restrict__ a, __half* __restrict__ h, int n)
{
    int i = blockIdx.x * 256 + threadIdx.x;
    if (i < n) h[i] = __float2half_rn(a[i]);
}

__global__ void __launch_bounds__(256) tsplit_kernel(
    const float* __restrict__ x, __half* __restrict__ o)
{
    __shared__ float t[32][33];
    const int n0 = blockIdx.x * 32, k0 = blockIdx.y * 32, b = blockIdx.z;
    const int tx = threadIdx.x, ty = threadIdx.y;
    const float* src = x + ((size_t)b * KDIM + k0) * S + n0;
#pragma unroll
    for (int i = 0; i < 4; i++)
        t[ty + 8 * i][tx] = src[(size_t)(ty + 8 * i) * S + tx];
    __syncthreads();
    __half* d = o + ((size_t)b * S + n0) * KDIM + k0;
#pragma unroll
    for (int i = 0; i < 4; i++)
        d[(size_t)(ty + 8 * i) * KDIM + tx] = __float2half_rn(t[tx][ty + 8 * i]);
}

// ---------------------------------------------------------------------------
// Pool x -> pooled fp32 [b][c][320]
// ---------------------------------------------------------------------------
__global__ void __launch_bounds__(256) pool_x_kernel(
    const float* __restrict__ x, float* __restrict__ pooled)
{
    const int bc = blockIdx.x;
    const float* src = x + (size_t)bc * S;
    float* dst = pooled + (size_t)bc * NKV;

    __shared__ float ts[S];
    const int tid = threadIdx.x;
    ((float4*)ts)[tid] = ((const float4*)src)[tid];
    __syncthreads();

    if (tid < 32) {
        float s = 0.f;
#pragma unroll
        for (int w = 0; w < 32; w++) s += ts[tid * 32 + w];
        dst[tid] = s * (1.f / 32.f);
    } else if (tid < 64) {
        const int w = tid - 32;
        float s = 0.f;
#pragma unroll
        for (int hh = 0; hh < 32; hh++) s += ts[hh * 32 + w];
        dst[tid] = s * (1.f / 32.f);
    }
    {
        const int ph = tid >> 4, pw = tid & 15;
        const float s = ts[(2 * ph) * 32 + 2 * pw] + ts[(2 * ph) * 32 + 2 * pw + 1]
                      + ts[(2 * ph + 1) * 32 + 2 * pw] + ts[(2 * ph + 1) * 32 + 2 * pw + 1];
        dst[64 + tid] = s * 0.25f;
    }
}

// ---------------------------------------------------------------------------
// Transpose pooled [b][c][320] -> xp fp16 [b][n][c]; rows 320..383 zero.
// ---------------------------------------------------------------------------
__global__ void __launch_bounds__(256) xpose_kernel(
    const float* __restrict__ pooled, __half* __restrict__ xp)
{
    __shared__ float t[32][33];
    const int c0 = blockIdx.x * 32, n0 = blockIdx.y * 32, b = blockIdx.z;
    const int tx = threadIdx.x, ty = threadIdx.y;
    const bool valid = (n0 < NKV);
    if (valid) {
        const float* src = pooled + ((size_t)b * CIN + c0) * NKV + n0;
#pragma unroll
        for (int i = 0; i < 4; i++)
            t[ty + 8 * i][tx] = src[(size_t)(ty + 8 * i) * NKV + tx];
    }
    __syncthreads();
    __half* d = xp + ((size_t)b * NKVP + n0) * KDIM + c0;
#pragma unroll
    for (int i = 0; i < 4; i++)
        d[(size_t)(ty + 8 * i) * KDIM + tx] =
            __float2half_rn(valid ? t[tx][ty + 8 * i] : 0.f);
}

// ---------------------------------------------------------------------------
// HMMA fp16 single-weight batched GEMM.  k-chunk 32 (80B rows), 4-stage,
// 2 CTAs/SM.  Stage = A(10240) + B(10240) = 20480 B.
// ---------------------------------------------------------------------------
#define T_B     10240
#define STG_SZ  20480
#define GSMEM   (4 * STG_SZ)       // 81920 B

__global__ void __launch_bounds__(256, 2) gemm_mma_kernel(
    const __half* __restrict__ A, const __half* __restrict__ B,
    float* __restrict__ C, __half* __restrict__ Ch,
    const float* __restrict__ bias, int Ntot)
{
    extern __shared__ char smem[];
    const uint32_t sbase = smem_u32(smem);

    const int tid = threadIdx.x;
    const int n0 = blockIdx.x * 128;
    const int m0 = blockIdx.y * 128;
    const int M  = gridDim.y * 128;
    const size_t bo = (size_t)blockIdx.z * Ntot * KDIM;
    const size_t co = (size_t)blockIdx.z * M * Ntot;

    const __half* Bb = B + bo;

    const int wid = tid >> 5, lane = tid & 31;
    const int wm = (wid & 3) * 32, wn = (wid >> 2) * 64;
    const uint32_t aoff = (uint32_t)((wm + (lane & 15)) * 80 + (lane >> 4) * 16);
    const uint32_t boff = (uint32_t)(T_B + (wn + (lane & 15)) * 80 + (lane >> 4) * 16);

    float acc[2][8][4];
#pragma unroll
    for (int f = 0; f < 2; f++)
#pragma unroll
        for (int j = 0; j < 8; j++)
#pragma unroll
            for (int r = 0; r < 4; r++) acc[f][j][r] = 0.f;

#define ISSUE(cc, st) do {                                                     \
        const uint32_t sp = sbase + (st) * STG_SZ;                             \
        _Pragma("unroll")                                                      \
        for (int it = 0; it < 2; it++) {                                       \
            const int idx = tid + it * 256;                                    \
            const int row = idx >> 2, ch = idx & 3;                            \
            const uint32_t so = (uint32_t)(row * 80 + ch * 16);                \
            const size_t ga = (size_t)(m0 + row) * KDIM + (cc) * 32 + ch * 8;  \
            const size_t gb = (size_t)(n0 + row) * KDIM + (cc) * 32 + ch * 8;  \
            cpasync16(sp + so,       A  + ga);                                 \
            cpasync16(sp + T_B + so, Bb + gb);                                 \
        }                                                                      \
    } while (0)

    ISSUE(0, 0); CP_COMMIT();
    ISSUE(1, 1); CP_COMMIT();
    ISSUE(2, 2); CP_COMMIT();

    const int NCH = KDIM / 32;       // 16
    for (int c = 0; c < NCH; c++) {
        CP_WAIT(2);                  // chunk c resident
        __syncthreads();             // all warps done reading stage (c+3)&3
        if (c + 3 < NCH) ISSUE(c + 3, (c + 3) & 3);
        CP_COMMIT();

        const uint32_t sa = sbase + (uint32_t)((c & 3) * STG_SZ);
#pragma unroll
        for (int kk = 0; kk < 2; kk++) {
            uint32_t ah[2][4];
            LDSM_X4(ah[0], sa + aoff + kk * 32);
            LDSM_X4(ah[1], sa + aoff + kk * 32 + 1280);
#pragma unroll
            for (int g = 0; g < 4; g++) {
                uint32_t bh[4];
                LDSM_X4(bh, sa + boff + kk * 32 + g * 1280);
#pragma unroll
                for (int f = 0; f < 2; f++) {
                    mma_f16(acc[f][2 * g],     ah[f], bh[0], bh[2]);
                    mma_f16(acc[f][2 * g + 1], ah[f], bh[1], bh[3]);
                }
            }
        }
    }
#undef ISSUE

    if (Ch) {
#pragma unroll
        for (int f = 0; f < 2; f++) {
            const int r0 = m0 + wm + f * 16 + (lane >> 2);
            __half* cp0 = Ch + co + (size_t)r0 * Ntot;
            __half* cp1 = cp0 + (size_t)8 * Ntot;
#pragma unroll
            for (int j = 0; j < 8; j++) {
                const int col = n0 + wn + j * 8 + (lane & 3) * 2;
                *(__half2*)(cp0 + col) = __floats2half2_rn(acc[f][j][0], acc[f][j][1]);
                *(__half2*)(cp1 + col) = __floats2half2_rn(acc[f][j][2], acc[f][j][3]);
            }
        }
    } else {
#pragma unroll
        for (int f = 0; f < 2; f++) {
            const int r0 = m0 + wm + f * 16 + (lane >> 2);
            const float bv0 = bias ? bias[r0] : 0.f;
            const float bv1 = bias ? bias[r0 + 8] : 0.f;
            float* cp0 = C + co + (size_t)r0 * Ntot;
            float* cp1 = cp0 + (size_t)8 * Ntot;
#pragma unroll
            for (int j = 0; j < 8; j++) {
                const int col = n0 + wn + j * 8 + (lane & 3) * 2;
                *(float2*)(cp0 + col) = make_float2(acc[f][j][0] + bv0, acc[f][j][1] + bv0);
                *(float2*)(cp1 + col) = make_float2(acc[f][j][2] + bv1, acc[f][j][3] + bv1);
            }
        }
    }
}

// ---------------------------------------------------------------------------
// kv gates.  K: smem 64x64 tile transpose; V: elementwise.
// ---------------------------------------------------------------------------
__global__ void __launch_bounds__(256) kvgate_k_kernel(
    const float* __restrict__ kvp, __half* __restrict__ khg)
{
    __shared__ float t[64 * 65];
    const int n0 = blockIdx.x * 64;
    const int h = blockIdx.y, b = blockIdx.z;
    const int tid = threadIdx.x;

#pragma unroll
    for (int j = 0; j < 16; j++) {
        const int idx = tid + j * 256;
        const int d = idx >> 6, np = idx & 63;
        t[np * 65 + d] = kvp[((size_t)(b * 1024 + h * 64 + d)) * NKVP + n0 + np];
    }
    __syncthreads();

    __half* dst = khg + ((size_t)(b * HEADS + h) * NKV + n0) * DH;
#pragma unroll
    for (int j = 0; j < 16; j++) {
        const int idx = tid + j * 256;
        const int np = idx >> 6, d = idx & 63;
        const float v = t[np * 65 + d];
        dst[(size_t)np * DH + d] = __float2half_rn(1.f / (1.f + __expf(-v)));
    }
}

__global__ void __launch_bounds__(256) kvgate_v_kernel(
    const float* __restrict__ kvp, __half* __restrict__ vhg)
{
    const int c = blockIdx.x;
    const int b = blockIdx.y;
    const float* src = kvp + ((size_t)(b * 1024 + 512 + c)) * NKVP;
    __half* dst = vhg + ((size_t)((b * HEADS + (c >> 6)) * DH + (c & 63))) * NKV;
    for (int n = threadIdx.x; n < NKV; n += 256) {
        dst[n] = __float2half_rn(1.f / (1.f + __expf(-src[n])));
    }
}

// ---------------------------------------------------------------------------
// MMA attention: TQ=32, fp16 Q (pre-scaled) loaded [dd][si] + ldmatrix.trans.
// ---------------------------------------------------------------------------
#define TQ       32
#define Q_ROW    80
#define K_ROW    144
#define V_ROW    656
#define SC_ROWB  1296
#define A_Q      0
#define A_K      5120
#define A_V      5120
#define A_SC     51200
#define A_INV    92672
#define ATTN2_SMEM 92800

__global__ void __launch_bounds__(256, 2) attn_mma_kernel(
    const __half* __restrict__ qh,
    const __half* __restrict__ khg, const __half* __restrict__ vhg,
    const float* __restrict__ pos,
    __half* __restrict__ att)
{
    extern __shared__ char sm[];
    const uint32_t sb = smem_u32(sm);
    const int b = blockIdx.z, hd = blockIdx.y;
    const int s0 = blockIdx.x * TQ;
    const int tid = threadIdx.x, wid = tid >> 5, lane = tid & 31;

    // ---- K via cp.async: [n][d], 320 rows x 128B ----
    {
        const char* kh = (const char*)(khg + (size_t)(b * HEADS + hd) * NKV * DH);
#pragma unroll
        for (int i = 0; i < 10; i++) {
            const int c = tid + i * 256;
            cpasync16(sb + A_K + (c >> 3) * K_ROW + (c & 7) * 16,
                      kh + (size_t)c * 16);
        }
    }
    // ---- Q via cp.async: [dd][si], 64 rows x 64B, stride 80 ----
    {
        const __half* qg = qh + ((size_t)b * CIN + hd * DH) * S + s0;
        const int row = tid >> 2, ch = tid & 3;
        cpasync16(sb + A_Q + row * Q_ROW + ch * 16, qg + (size_t)row * S + ch * 8);
    }
    CP_COMMIT();
    CP_WAIT(0);
    __syncthreads();

    const int mw = wid & 1;

    // ---- QK^T (A via ldmatrix.trans from [dd][si]) ----
    {
        const int n0w = (wid >> 1) * 80;
        const uint32_t qaddr0 = sb + A_Q
            + (uint32_t)(((lane & 7) + ((lane >> 4) << 3)) * Q_ROW
            + (mw * 16 + (((lane >> 3) & 1) << 3)) * 2);
        float acc[10][4];
#pragma unroll
        for (int t = 0; t < 10; t++) {
            acc[t][0] = 0.f; acc[t][1] = 0.f; acc[t][2] = 0.f; acc[t][3] = 0.f;
        }
#pragma unroll
        for (int k = 0; k < 4; k++) {
            uint32_t ah[4];
            LDSM_X4_T(ah, qaddr0 + k * 16 * Q_ROW);
#pragma unroll
            for (int jn = 0; jn < 5; jn++) {
                uint32_t bh[4];
                LDSM_X4(bh, sb + A_K + (n0w + jn * 16 + (lane & 15)) * K_ROW
                            + (lane >> 4) * 16 + k * 32);
                mma_f16(acc[2 * jn],     ah, bh[0], bh[2]);
                mma_f16(acc[2 * jn + 1], ah, bh[1], bh[3]);
            }
        }
        const int r0 = mw * 16 + (lane >> 2);
#pragma unroll
        for (int jn = 0; jn < 5; jn++)
#pragma unroll
            for (int t = 0; t < 2; t++) {
                const int n = n0w + jn * 16 + t * 8 + (lane & 3) * 2;
                float* p0 = (float*)(sm + A_SC + r0 * SC_ROWB) + n;
                float* p1 = (float*)(sm + A_SC + (r0 + 8) * SC_ROWB) + n;
                *(float2*)p0 = make_float2(acc[2 * jn + t][0], acc[2 * jn + t][1]);
                *(float2*)p1 = make_float2(acc[2 * jn + t][2], acc[2 * jn + t][3]);
            }
    }
    __syncthreads();

    // ---- V into dead K region: [d][n], 64 rows x 640B ----
    {
        const char* vh = (const char*)(vhg + (size_t)(b * HEADS + hd) * DH * NKV);
#pragma unroll
        for (int i = 0; i < 10; i++) {
            const int c = tid + i * 256;
            const int d = c / 40, o = c % 40;
            cpasync16(sb + A_V + d * V_ROW + o * 16, vh + (size_t)c * 16);
        }
        CP_COMMIT();
    }

    // ---- softmax ----
    {
        const int r = tid >> 3, cq = tid & 7;
        float* row = (float*)(sm + A_SC + r * SC_ROWB);
        __half* ph = (__half*)(sm + A_SC + r * SC_ROWB);
        const float* pr = pos + (size_t)(s0 + r) * NKV;
        float mx = -1e30f;
#pragma unroll
        for (int k = cq; k < NKV; k += 8) {
            const float v = row[k] + pr[k];
            row[k] = v;
            mx = fmaxf(mx, v);
        }
        mx = fmaxf(mx, __shfl_xor_sync(0xffffffffu, mx, 1));
        mx = fmaxf(mx, __shfl_xor_sync(0xffffffffu, mx, 2));
        mx = fmaxf(mx, __shfl_xor_sync(0xffffffffu, mx, 4));
        float ssum = 0.f;
#pragma unroll
        for (int c5 = 0; c5 < 5; c5++) {
            float e[8];
#pragma unroll
            for (int j = 0; j < 8; j++) {
                e[j] = __expf(row[c5 * 64 + cq + 8 * j] - mx);
                ssum += e[j];
            }
            __syncwarp();
#pragma unroll
            for (int j = 0; j < 8; j++)
                ph[c5 * 64 + cq + 8 * j] = __float2half_rn(e[j]);
            __syncwarp();
        }
        ssum += __shfl_xor_sync(0xffffffffu, ssum, 1);
        ssum += __shfl_xor_sync(0xffffffffu, ssum, 2);
        ssum += __shfl_xor_sync(0xffffffffu, ssum, 4);
        if (cq == 0) *(float*)(sm + A_INV + r * 4) = 1.f / ssum;
    }
    CP_WAIT(0);
    __syncthreads();

    // ---- AV ----
    {
        const int dw = wid >> 1;
        float oa[2][4];
        oa[0][0] = oa[0][1] = oa[0][2] = oa[0][3] = 0.f;
        oa[1][0] = oa[1][1] = oa[1][2] = oa[1][3] = 0.f;
#pragma unroll
        for (int k = 0; k < 20; k++) {
            uint32_t pa[4], vv[4];
            LDSM_X4(pa, sb + A_SC + (mw * 16 + (lane & 15)) * SC_ROWB
                        + (lane >> 4) * 16 + k * 32);
            LDSM_X4(vv, sb + A_V + (dw * 16 + (lane & 15)) * V_ROW
                        + (lane >> 4) * 16 + k * 32);
            mma_f16(oa[0], pa, vv[0], vv[2]);
            mma_f16(oa[1], pa, vv[1], vv[3]);
        }
        const float inv0 = *(const float*)(sm + A_INV + (mw * 16 + (lane >> 2)) * 4);
        const float inv1 = *(const float*)(sm + A_INV + (mw * 16 + 8 + (lane >> 2)) * 4);
        const size_t ro0 = ((size_t)b * S + s0 + mw * 16 + (lane >> 2)) * CIN + hd * DH;
        const size_t ro1 = ro0 + (size_t)8 * CIN;
#pragma unroll
        for (int jt = 0; jt < 2; jt++) {
            const int col = dw * 16 + jt * 8 + (lane & 3) * 2;
            __half2 h0 = __floats2half2_rn(oa[jt][0] * inv0, oa[jt][1] * inv0);
            __half2 h1 = __floats2half2_rn(oa[jt][2] * inv1, oa[jt][3] * inv1);
            *(__half2*)(att + ro0 + col) = h0;
            *(__half2*)(att + ro1 + col) = h1;
        }
    }
}

// ---------------------------------------------------------------------------
// Launch
// ---------------------------------------------------------------------------
extern "C" void kernel_launch(void* const* d_in, const int* in_sizes, int n_in,
                              void* d_out, int out_size)
{
    const float* x     = (const float*)d_in[0];
    const float* Wqkv  = (const float*)d_in[1];
    const float* Wout  = (const float*)d_in[2];
    const float* bout  = (const float*)d_in[3];
    const float* pos   = (const float*)d_in[4];
    float* out = (float*)d_out;

    float *p_kvp, *p_pool;
    __half *p_qh, *p_x, *p_xp, *p_kh, *p_vh, *p_at, *p_wq, *p_wo;
    cudaGetSymbolAddress((void**)&p_kvp,  g_kvp);
    cudaGetSymbolAddress((void**)&p_pool, g_pool);
    cudaGetSymbolAddress((void**)&p_qh,   g_qh);
    cudaGetSymbolAddress((void**)&p_x,    g_x);
    cudaGetSymbolAddress((void**)&p_xp,   g_xp);
    cudaGetSymbolAddress((void**)&p_kh,   g_kh);
    cudaGetSymbolAddress((void**)&p_vh,   g_vh);
    cudaGetSymbolAddress((void**)&p_at,   g_at);
    cudaGetSymbolAddress((void**)&p_wq,   g_wq);
    cudaGetSymbolAddress((void**)&p_wo,   g_wo);

    cudaFuncSetAttribute(gemm_mma_kernel,
                         cudaFuncAttributeMaxDynamicSharedMemorySize, GSMEM);
    cudaFuncSetAttribute(attn_mma_kernel,
                         cudaFuncAttributeMaxDynamicSharedMemorySize, ATTN2_SMEM);

    // 0) operand prep
    cvt_wqkv_kernel<<<(QKVC * KDIM + 255) / 256, 256>>>(Wqkv, p_wq);
    cvt_kernel<<<(COUT * KDIM + 255) / 256, 256>>>(Wout, p_wo, COUT * KDIM);
    tsplit_kernel<<<dim3(S / 32, KDIM / 32, BATCH), dim3(32, 8)>>>(x, p_x);
    pool_x_kernel<<<BATCH * CIN, 256>>>(x, p_pool);
    xpose_kernel<<<dim3(KDIM / 32, NKVP / 32, BATCH), dim3(32, 8)>>>(p_pool, p_xp);

    // 1) Q = (0.125*Wq) @ x^T -> fp16 [B,512,1024]
    gemm_mma_kernel<<<dim3(S / 128, CIN / 128, BATCH), 256, GSMEM>>>(
        p_wq, p_x, nullptr, p_qh, nullptr, S);

    // 2) kv_pre = Wkv @ xp^T   [B,1024,384]
    gemm_mma_kernel<<<dim3(NKVP / 128, 1024 / 128, BATCH), 256, GSMEM>>>(
        p_wq + (size_t)CIN * KDIM, p_xp, p_kvp, nullptr, nullptr, NKVP);

    // 3) sigmoid gates -> K (tiled transpose), V (elementwise)
    kvgate_k_kernel<<<dim3(NKV / 64, HEADS, BATCH), 256>>>(p_kvp, p_kh);
    kvgate_v_kernel<<<dim3(512, BATCH), 256>>>(p_kvp, p_vh);

    // 4) tensor-core attention -> att fp16 [B,S,C]
    attn_mma_kernel<<<dim3(S / TQ, HEADS, BATCH), 256, ATTN2_SMEM>>>(
        p_qh, p_kh, p_vh, pos, p_at);

    // 5) out = Wout @ att^T + bout   [B,512,1024]
    gemm_mma_kernel<<<dim3(S / 128, COUT / 128, BATCH), 256, GSMEM>>>(
        p_wo, p_at, out, nullptr, bout, S);
}

// round 13
// speedup vs baseline: 7.1564x; 1.2252x over previous
#include <cuda_runtime.h>
#include <cuda_bf16.h>
#include <cuda_fp16.h>
#include <math.h>
#include <stdint.h>

// ---------------------------------------------------------------------------
// Problem constants
// ---------------------------------------------------------------------------
#define BATCH   32
#define CIN     512
#define COUT    512
#define HEADS   8
#define DH      64
#define S       1024
#define NKV     320
#define NKVP    384
#define QKVC    1536
#define KDIM    512

// ---------------------------------------------------------------------------
// Scratch (device globals)
// ---------------------------------------------------------------------------
__device__ float g_kvp [(size_t)BATCH * 1024 * NKVP];
__device__ float g_pool[(size_t)BATCH * CIN * NKV];
__device__ __align__(16) __half g_qh [(size_t)BATCH * CIN * S];   // Q fp16 (pre-scaled)
__device__ __align__(16) __half g_x  [(size_t)BATCH * S * KDIM];
__device__ __align__(16) __half g_xp [(size_t)BATCH * NKVP * KDIM];
__device__ __align__(16) __half g_kh [(size_t)BATCH * HEADS * NKV * DH]; // K [b,h,n,d]
__device__ __align__(16) __half g_vh [(size_t)BATCH * HEADS * DH * NKV]; // V [b,h,d,n]
__device__ __align__(16) __half g_at [(size_t)BATCH * S * CIN];
__device__ __align__(16) __half g_wq [(size_t)QKVC * KDIM];
__device__ __align__(16) __half g_wo [(size_t)COUT * KDIM];

// ---------------------------------------------------------------------------
// PTX helpers
// ---------------------------------------------------------------------------
__device__ __forceinline__ uint32_t smem_u32(const void* p) {
    uint32_t a;
    asm("{ .reg .u64 t; cvta.to.shared.u64 t, %1; cvt.u32.u64 %0, t; }"
        : "=r"(a) : "l"(p));
    return a;
}
__device__ __forceinline__ void cpasync16(uint32_t s, const void* g) {
    asm volatile("cp.async.cg.shared.global [%0], [%1], 16;" :: "r"(s), "l"(g));
}
#define CP_COMMIT() asm volatile("cp.async.commit_group;" ::: "memory")
#define CP_WAIT(N)  asm volatile("cp.async.wait_group %0;" :: "n"(N) : "memory")

#define LDSM_X4(r, addr) \
    asm volatile("ldmatrix.sync.aligned.m8n8.x4.shared.b16 {%0,%1,%2,%3}, [%4];" \
                 : "=r"((r)[0]), "=r"((r)[1]), "=r"((r)[2]), "=r"((r)[3]) : "r"(addr))
#define LDSM_X4_T(r, addr) \
    asm volatile("ldmatrix.sync.aligned.m8n8.x4.trans.shared.b16 {%0,%1,%2,%3}, [%4];" \
                 : "=r"((r)[0]), "=r"((r)[1]), "=r"((r)[2]), "=r"((r)[3]) : "r"(addr))

__device__ __forceinline__ void mma_f16(float* d, const uint32_t* a,
                                        uint32_t b0, uint32_t b1) {
    asm volatile(
        "mma.sync.aligned.m16n8k16.row.col.f32.f16.f16.f32 "
        "{%0,%1,%2,%3}, {%4,%5,%6,%7}, {%8,%9}, {%0,%1,%2,%3};"
        : "+f"(d[0]), "+f"(d[1]), "+f"(d[2]), "+f"(d[3])
        : "r"(a[0]), "r"(a[1]), "r"(a[2]), "r"(a[3]), "r"(b0), "r"(b1));
}

// ---------------------------------------------------------------------------
// Weight prep
// ---------------------------------------------------------------------------
__global__ void cvt_wqkv_kernel(const float* __restrict__ a, __half* __restrict__ h)
{
    int i = blockIdx.x * 256 + threadIdx.x;
    if (i < QKVC * KDIM) {
        const float sc = (i < CIN * KDIM) ? 0.125f : 1.f;
        h[i] = __float2half_rn(a[i] * sc);
    }
}
__global__ void cvt_kernel(const float* __restrict__ a, __half* __restrict__ h, int n)
{
    int i = blockIdx.x * 256 + threadIdx.x;
    if (i < n) h[i] = __float2half_rn(a[i]);
}

__global__ void __launch_bounds__(256) tsplit_kernel(
    const float* __restrict__ x, __half* __restrict__ o)
{
    __shared__ float t[32][33];
    const int n0 = blockIdx.x * 32, k0 = blockIdx.y * 32, b = blockIdx.z;
    const int tx = threadIdx.x, ty = threadIdx.y;
    const float* src = x + ((size_t)b * KDIM + k0) * S + n0;
#pragma unroll
    for (int i = 0; i < 4; i++)
        t[ty + 8 * i][tx] = src[(size_t)(ty + 8 * i) * S + tx];
    __syncthreads();
    __half* d = o + ((size_t)b * S + n0) * KDIM + k0;
#pragma unroll
    for (int i = 0; i < 4; i++)
        d[(size_t)(ty + 8 * i) * KDIM + tx] = __float2half_rn(t[tx][ty + 8 * i]);
}

// ---------------------------------------------------------------------------
// Pool x -> pooled fp32 [b][c][320]
// ---------------------------------------------------------------------------
__global__ void __launch_bounds__(256) pool_x_kernel(
    const float* __restrict__ x, float* __restrict__ pooled)
{
    const int bc = blockIdx.x;
    const float* src = x + (size_t)bc * S;
    float* dst = pooled + (size_t)bc * NKV;

    __shared__ float ts[S];
    const int tid = threadIdx.x;
    ((float4*)ts)[tid] = ((const float4*)src)[tid];
    __syncthreads();

    if (tid < 32) {
        float s = 0.f;
#pragma unroll
        for (int w = 0; w < 32; w++) s += ts[tid * 32 + w];
        dst[tid] = s * (1.f / 32.f);
    } else if (tid < 64) {
        const int w = tid - 32;
        float s = 0.f;
#pragma unroll
        for (int hh = 0; hh < 32; hh++) s += ts[hh * 32 + w];
        dst[tid] = s * (1.f / 32.f);
    }
    {
        const int ph = tid >> 4, pw = tid & 15;
        const float s = ts[(2 * ph) * 32 + 2 * pw] + ts[(2 * ph) * 32 + 2 * pw + 1]
                      + ts[(2 * ph + 1) * 32 + 2 * pw] + ts[(2 * ph + 1) * 32 + 2 * pw + 1];
        dst[64 + tid] = s * 0.25f;
    }
}

// ---------------------------------------------------------------------------
// Transpose pooled [b][c][320] -> xp fp16 [b][n][c]; rows 320..383 zero.
// ---------------------------------------------------------------------------
__global__ void __launch_bounds__(256) xpose_kernel(
    const float* __restrict__ pooled, __half* __restrict__ xp)
{
    __shared__ float t[32][33];
    const int c0 = blockIdx.x * 32, n0 = blockIdx.y * 32, b = blockIdx.z;
    const int tx = threadIdx.x, ty = threadIdx.y;
    const bool valid = (n0 < NKV);
    if (valid) {
        const float* src = pooled + ((size_t)b * CIN + c0) * NKV + n0;
#pragma unroll
        for (int i = 0; i < 4; i++)
            t[ty + 8 * i][tx] = src[(size_t)(ty + 8 * i) * NKV + tx];
    }
    __syncthreads();
    __half* d = xp + ((size_t)b * NKVP + n0) * KDIM + c0;
#pragma unroll
    for (int i = 0; i < 4; i++)
        d[(size_t)(ty + 8 * i) * KDIM + tx] =
            __float2half_rn(valid ? t[tx][ty + 8 * i] : 0.f);
}

// ---------------------------------------------------------------------------
// HMMA fp16 single-weight batched GEMM (unchanged from R12).
// ---------------------------------------------------------------------------
#define T_B     10240
#define STG_SZ  20480
#define GSMEM   (4 * STG_SZ)

__global__ void __launch_bounds__(256, 2) gemm_mma_kernel(
    const __half* __restrict__ A, const __half* __restrict__ B,
    float* __restrict__ C, __half* __restrict__ Ch,
    const float* __restrict__ bias, int Ntot)
{
    extern __shared__ char smem[];
    const uint32_t sbase = smem_u32(smem);

    const int tid = threadIdx.x;
    const int n0 = blockIdx.x * 128;
    const int m0 = blockIdx.y * 128;
    const int M  = gridDim.y * 128;
    const size_t bo = (size_t)blockIdx.z * Ntot * KDIM;
    const size_t co = (size_t)blockIdx.z * M * Ntot;

    const __half* Bb = B + bo;

    const int wid = tid >> 5, lane = tid & 31;
    const int wm = (wid & 3) * 32, wn = (wid >> 2) * 64;
    const uint32_t aoff = (uint32_t)((wm + (lane & 15)) * 80 + (lane >> 4) * 16);
    const uint32_t boff = (uint32_t)(T_B + (wn + (lane & 15)) * 80 + (lane >> 4) * 16);

    float acc[2][8][4];
#pragma unroll
    for (int f = 0; f < 2; f++)
#pragma unroll
        for (int j = 0; j < 8; j++)
#pragma unroll
            for (int r = 0; r < 4; r++) acc[f][j][r] = 0.f;

#define ISSUE(cc, st) do {                                                     \
        const uint32_t sp = sbase + (st) * STG_SZ;                             \
        _Pragma("unroll")                                                      \
        for (int it = 0; it < 2; it++) {                                       \
            const int idx = tid + it * 256;                                    \
            const int row = idx >> 2, ch = idx & 3;                            \
            const uint32_t so = (uint32_t)(row * 80 + ch * 16);                \
            const size_t ga = (size_t)(m0 + row) * KDIM + (cc) * 32 + ch * 8;  \
            const size_t gb = (size_t)(n0 + row) * KDIM + (cc) * 32 + ch * 8;  \
            cpasync16(sp + so,       A  + ga);                                 \
            cpasync16(sp + T_B + so, Bb + gb);                                 \
        }                                                                      \
    } while (0)

    ISSUE(0, 0); CP_COMMIT();
    ISSUE(1, 1); CP_COMMIT();
    ISSUE(2, 2); CP_COMMIT();

    const int NCH = KDIM / 32;
    for (int c = 0; c < NCH; c++) {
        CP_WAIT(2);
        __syncthreads();
        if (c + 3 < NCH) ISSUE(c + 3, (c + 3) & 3);
        CP_COMMIT();

        const uint32_t sa = sbase + (uint32_t)((c & 3) * STG_SZ);
#pragma unroll
        for (int kk = 0; kk < 2; kk++) {
            uint32_t ah[2][4];
            LDSM_X4(ah[0], sa + aoff + kk * 32);
            LDSM_X4(ah[1], sa + aoff + kk * 32 + 1280);
#pragma unroll
            for (int g = 0; g < 4; g++) {
                uint32_t bh[4];
                LDSM_X4(bh, sa + boff + kk * 32 + g * 1280);
#pragma unroll
                for (int f = 0; f < 2; f++) {
                    mma_f16(acc[f][2 * g],     ah[f], bh[0], bh[2]);
                    mma_f16(acc[f][2 * g + 1], ah[f], bh[1], bh[3]);
                }
            }
        }
    }
#undef ISSUE

    if (Ch) {
#pragma unroll
        for (int f = 0; f < 2; f++) {
            const int r0 = m0 + wm + f * 16 + (lane >> 2);
            __half* cp0 = Ch + co + (size_t)r0 * Ntot;
            __half* cp1 = cp0 + (size_t)8 * Ntot;
#pragma unroll
            for (int j = 0; j < 8; j++) {
                const int col = n0 + wn + j * 8 + (lane & 3) * 2;
                *(__half2*)(cp0 + col) = __floats2half2_rn(acc[f][j][0], acc[f][j][1]);
                *(__half2*)(cp1 + col) = __floats2half2_rn(acc[f][j][2], acc[f][j][3]);
            }
        }
    } else {
#pragma unroll
        for (int f = 0; f < 2; f++) {
            const int r0 = m0 + wm + f * 16 + (lane >> 2);
            const float bv0 = bias ? bias[r0] : 0.f;
            const float bv1 = bias ? bias[r0 + 8] : 0.f;
            float* cp0 = C + co + (size_t)r0 * Ntot;
            float* cp1 = cp0 + (size_t)8 * Ntot;
#pragma unroll
            for (int j = 0; j < 8; j++) {
                const int col = n0 + wn + j * 8 + (lane & 3) * 2;
                *(float2*)(cp0 + col) = make_float2(acc[f][j][0] + bv0, acc[f][j][1] + bv0);
                *(float2*)(cp1 + col) = make_float2(acc[f][j][2] + bv1, acc[f][j][3] + bv1);
            }
        }
    }
}

// ---------------------------------------------------------------------------
// kv gates.
// ---------------------------------------------------------------------------
__global__ void __launch_bounds__(256) kvgate_k_kernel(
    const float* __restrict__ kvp, __half* __restrict__ khg)
{
    __shared__ float t[64 * 65];
    const int n0 = blockIdx.x * 64;
    const int h = blockIdx.y, b = blockIdx.z;
    const int tid = threadIdx.x;

#pragma unroll
    for (int j = 0; j < 16; j++) {
        const int idx = tid + j * 256;
        const int d = idx >> 6, np = idx & 63;
        t[np * 65 + d] = kvp[((size_t)(b * 1024 + h * 64 + d)) * NKVP + n0 + np];
    }
    __syncthreads();

    __half* dst = khg + ((size_t)(b * HEADS + h) * NKV + n0) * DH;
#pragma unroll
    for (int j = 0; j < 16; j++) {
        const int idx = tid + j * 256;
        const int np = idx >> 6, d = idx & 63;
        const float v = t[np * 65 + d];
        dst[(size_t)np * DH + d] = __float2half_rn(1.f / (1.f + __expf(-v)));
    }
}

__global__ void __launch_bounds__(256) kvgate_v_kernel(
    const float* __restrict__ kvp, __half* __restrict__ vhg)
{
    const int c = blockIdx.x;
    const int b = blockIdx.y;
    const float* src = kvp + ((size_t)(b * 1024 + 512 + c)) * NKVP;
    __half* dst = vhg + ((size_t)((b * HEADS + (c >> 6)) * DH + (c & 63))) * NKV;
    for (int n = threadIdx.x; n < NKV; n += 256) {
        dst[n] = __float2half_rn(1.f / (1.f + __expf(-src[n])));
    }
}

// ---------------------------------------------------------------------------
// MMA attention v3: TQ=64, register softmax, P fp16 only, 2 CTAs/SM.
// smem: Q[dd][si] 9216 | K[n][d] 46080 (V[d][n] 41984 overlays) |
//       P fp16 64x656 | partial max/sum | inv
// ---------------------------------------------------------------------------
#define TQ       64
#define Q_ROW    144
#define K_ROW    144
#define V_ROW    656
#define P_ROW    656
#define A_Q      0
#define A_K      9216
#define A_V      9216
#define A_P      55296
#define A_MX     97280
#define A_SM2    97792
#define A_INV    98304
#define ATTN2_SMEM 98560

__global__ void __launch_bounds__(256, 2) attn_mma_kernel(
    const __half* __restrict__ qh,
    const __half* __restrict__ khg, const __half* __restrict__ vhg,
    const float* __restrict__ pos,
    __half* __restrict__ att)
{
    extern __shared__ char sm[];
    const uint32_t sb = smem_u32(sm);
    const int b = blockIdx.z, hd = blockIdx.y;
    const int s0 = blockIdx.x * TQ;
    const int tid = threadIdx.x, wid = tid >> 5, lane = tid & 31;

    // ---- K via cp.async: [n][d], 320 rows x 128B ----
    {
        const char* kh = (const char*)(khg + (size_t)(b * HEADS + hd) * NKV * DH);
#pragma unroll
        for (int i = 0; i < 10; i++) {
            const int c = tid + i * 256;
            cpasync16(sb + A_K + (c >> 3) * K_ROW + (c & 7) * 16,
                      kh + (size_t)c * 16);
        }
    }
    // ---- Q via cp.async: [dd][si], 64 rows x 128B, stride 144 ----
    {
        const __half* qg = qh + ((size_t)b * CIN + hd * DH) * S + s0;
#pragma unroll
        for (int i = 0; i < 2; i++) {
            const int c = tid + i * 256;
            const int row = c >> 3, ch = c & 7;
            cpasync16(sb + A_Q + row * Q_ROW + ch * 16,
                      qg + (size_t)row * S + ch * 8);
        }
    }
    CP_COMMIT();
    CP_WAIT(0);
    __syncthreads();

    const int mw = wid & 3;          // 4 m-tiles of 16 rows
    const int nw = wid >> 2;         // 2 n-halves of 160
    const int n0w = nw * 160;
    const int r0 = mw * 16 + (lane >> 2);

    float acc[20][4];
#pragma unroll
    for (int t = 0; t < 20; t++) {
        acc[t][0] = 0.f; acc[t][1] = 0.f; acc[t][2] = 0.f; acc[t][3] = 0.f;
    }

    // ---- QK^T into registers ----
    {
        const uint32_t qaddr0 = sb + A_Q
            + (uint32_t)(((lane & 7) + ((lane >> 4) << 3)) * Q_ROW
            + (mw * 16 + (((lane >> 3) & 1) << 3)) * 2);
#pragma unroll
        for (int k = 0; k < 4; k++) {
            uint32_t ah[4];
            LDSM_X4_T(ah, qaddr0 + k * 16 * Q_ROW);
#pragma unroll
            for (int jn = 0; jn < 10; jn++) {
                uint32_t bh[4];
                LDSM_X4(bh, sb + A_K + (n0w + jn * 16 + (lane & 15)) * K_ROW
                            + (lane >> 4) * 16 + k * 32);
                mma_f16(acc[2 * jn],     ah, bh[0], bh[2]);
                mma_f16(acc[2 * jn + 1], ah, bh[1], bh[3]);
            }
        }
    }
    __syncthreads();                 // everyone done reading K

    // ---- V into dead K region: [d][n], 64 rows x 640B ----
    {
        const char* vh = (const char*)(vhg + (size_t)(b * HEADS + hd) * DH * NKV);
#pragma unroll
        for (int i = 0; i < 10; i++) {
            const int c = tid + i * 256;
            const int d = c / 40, o = c % 40;
            cpasync16(sb + A_V + d * V_ROW + o * 16, vh + (size_t)c * 16);
        }
        CP_COMMIT();
    }

    // ---- pos add + row max (registers) ----
    float mx0 = -1e30f, mx1 = -1e30f;
    {
        const float* pr0 = pos + (size_t)(s0 + r0) * NKV;
        const float* pr1 = pr0 + (size_t)8 * NKV;
#pragma unroll
        for (int g = 0; g < 20; g++) {
            const int jn = g >> 1, t = g & 1;
            const int n = n0w + jn * 16 + t * 8 + (lane & 3) * 2;
            const float2 p0 = *(const float2*)(pr0 + n);
            const float2 p1 = *(const float2*)(pr1 + n);
            acc[g][0] += p0.x; acc[g][1] += p0.y;
            acc[g][2] += p1.x; acc[g][3] += p1.y;
            mx0 = fmaxf(mx0, fmaxf(acc[g][0], acc[g][1]));
            mx1 = fmaxf(mx1, fmaxf(acc[g][2], acc[g][3]));
        }
    }
    mx0 = fmaxf(mx0, __shfl_xor_sync(0xffffffffu, mx0, 1));
    mx0 = fmaxf(mx0, __shfl_xor_sync(0xffffffffu, mx0, 2));
    mx1 = fmaxf(mx1, __shfl_xor_sync(0xffffffffu, mx1, 1));
    mx1 = fmaxf(mx1, __shfl_xor_sync(0xffffffffu, mx1, 2));
    if ((lane & 3) == 0) {
        *(float*)(sm + A_MX + (nw * 64 + r0) * 4)     = mx0;
        *(float*)(sm + A_MX + (nw * 64 + r0 + 8) * 4) = mx1;
    }
    __syncthreads();
    const float gm0 = fmaxf(*(const float*)(sm + A_MX + r0 * 4),
                            *(const float*)(sm + A_MX + (64 + r0) * 4));
    const float gm1 = fmaxf(*(const float*)(sm + A_MX + (r0 + 8) * 4),
                            *(const float*)(sm + A_MX + (64 + r0 + 8) * 4));

    // ---- exp + row sum (registers) ----
    float sm0 = 0.f, sm1 = 0.f;
#pragma unroll
    for (int g = 0; g < 20; g++) {
        acc[g][0] = __expf(acc[g][0] - gm0);
        acc[g][1] = __expf(acc[g][1] - gm0);
        acc[g][2] = __expf(acc[g][2] - gm1);
        acc[g][3] = __expf(acc[g][3] - gm1);
        sm0 += acc[g][0] + acc[g][1];
        sm1 += acc[g][2] + acc[g][3];
    }
    sm0 += __shfl_xor_sync(0xffffffffu, sm0, 1);
    sm0 += __shfl_xor_sync(0xffffffffu, sm0, 2);
    sm1 += __shfl_xor_sync(0xffffffffu, sm1, 1);
    sm1 += __shfl_xor_sync(0xffffffffu, sm1, 2);
    if ((lane & 3) == 0) {
        *(float*)(sm + A_SM2 + (nw * 64 + r0) * 4)     = sm0;
        *(float*)(sm + A_SM2 + (nw * 64 + r0 + 8) * 4) = sm1;
    }
    __syncthreads();
    if (nw == 0 && (lane & 3) == 0) {
        const float i0 = 1.f / (*(const float*)(sm + A_SM2 + r0 * 4)
                              + *(const float*)(sm + A_SM2 + (64 + r0) * 4));
        const float i1 = 1.f / (*(const float*)(sm + A_SM2 + (r0 + 8) * 4)
                              + *(const float*)(sm + A_SM2 + (64 + r0 + 8) * 4));
        *(float*)(sm + A_INV + r0 * 4)       = i0;
        *(float*)(sm + A_INV + (r0 + 8) * 4) = i1;
    }

    // ---- write P fp16 (unnormalized) ----
#pragma unroll
    for (int g = 0; g < 20; g++) {
        const int jn = g >> 1, t = g & 1;
        const int n = n0w + jn * 16 + t * 8 + (lane & 3) * 2;
        *(__half2*)(sm + A_P + r0 * P_ROW + n * 2) =
            __floats2half2_rn(acc[g][0], acc[g][1]);
        *(__half2*)(sm + A_P + (r0 + 8) * P_ROW + n * 2) =
            __floats2half2_rn(acc[g][2], acc[g][3]);
    }
    CP_WAIT(0);
    __syncthreads();                 // P + V visible

    // ---- AV: warp = (m16, d32) ----
    {
        const int dw = nw;           // d half: dw*32
        float oa[4][4];
#pragma unroll
        for (int t = 0; t < 4; t++) {
            oa[t][0] = 0.f; oa[t][1] = 0.f; oa[t][2] = 0.f; oa[t][3] = 0.f;
        }
#pragma unroll
        for (int k = 0; k < 20; k++) {
            uint32_t pa[4], v0[4], v1[4];
            LDSM_X4(pa, sb + A_P + (mw * 16 + (lane & 15)) * P_ROW
                        + (lane >> 4) * 16 + k * 32);
            const uint32_t va = sb + A_V + (dw * 32 + (lane & 15)) * V_ROW
                              + (lane >> 4) * 16 + k * 32;
            LDSM_X4(v0, va);
            LDSM_X4(v1, va + 16 * V_ROW);
            mma_f16(oa[0], pa, v0[0], v0[2]);
            mma_f16(oa[1], pa, v0[1], v0[3]);
            mma_f16(oa[2], pa, v1[0], v1[2]);
            mma_f16(oa[3], pa, v1[1], v1[3]);
        }
        const float inv0 = *(const float*)(sm + A_INV + r0 * 4);
        const float inv1 = *(const float*)(sm + A_INV + (r0 + 8) * 4);
        const size_t ro0 = ((size_t)b * S + s0 + r0) * CIN + hd * DH;
        const size_t ro1 = ro0 + (size_t)8 * CIN;
#pragma unroll
        for (int jt = 0; jt < 4; jt++) {
            const int col = dw * 32 + jt * 8 + (lane & 3) * 2;
            __half2 h0 = __floats2half2_rn(oa[jt][0] * inv0, oa[jt][1] * inv0);
            __half2 h1 = __floats2half2_rn(oa[jt][2] * inv1, oa[jt][3] * inv1);
            *(__half2*)(att + ro0 + col) = h0;
            *(__half2*)(att + ro1 + col) = h1;
        }
    }
}

// ---------------------------------------------------------------------------
// Launch
// ---------------------------------------------------------------------------
extern "C" void kernel_launch(void* const* d_in, const int* in_sizes, int n_in,
                              void* d_out, int out_size)
{
    const float* x     = (const float*)d_in[0];
    const float* Wqkv  = (const float*)d_in[1];
    const float* Wout  = (const float*)d_in[2];
    const float* bout  = (const float*)d_in[3];
    const float* pos   = (const float*)d_in[4];
    float* out = (float*)d_out;

    float *p_kvp, *p_pool;
    __half *p_qh, *p_x, *p_xp, *p_kh, *p_vh, *p_at, *p_wq, *p_wo;
    cudaGetSymbolAddress((void**)&p_kvp,  g_kvp);
    cudaGetSymbolAddress((void**)&p_pool, g_pool);
    cudaGetSymbolAddress((void**)&p_qh,   g_qh);
    cudaGetSymbolAddress((void**)&p_x,    g_x);
    cudaGetSymbolAddress((void**)&p_xp,   g_xp);
    cudaGetSymbolAddress((void**)&p_kh,   g_kh);
    cudaGetSymbolAddress((void**)&p_vh,   g_vh);
    cudaGetSymbolAddress((void**)&p_at,   g_at);
    cudaGetSymbolAddress((void**)&p_wq,   g_wq);
    cudaGetSymbolAddress((void**)&p_wo,   g_wo);

    cudaFuncSetAttribute(gemm_mma_kernel,
                         cudaFuncAttributeMaxDynamicSharedMemorySize, GSMEM);
    cudaFuncSetAttribute(attn_mma_kernel,
                         cudaFuncAttributeMaxDynamicSharedMemorySize, ATTN2_SMEM);

    // 0) operand prep
    cvt_wqkv_kernel<<<(QKVC * KDIM + 255) / 256, 256>>>(Wqkv, p_wq);
    cvt_kernel<<<(COUT * KDIM + 255) / 256, 256>>>(Wout, p_wo, COUT * KDIM);
    tsplit_kernel<<<dim3(S / 32, KDIM / 32, BATCH), dim3(32, 8)>>>(x, p_x);
    pool_x_kernel<<<BATCH * CIN, 256>>>(x, p_pool);
    xpose_kernel<<<dim3(KDIM / 32, NKVP / 32, BATCH), dim3(32, 8)>>>(p_pool, p_xp);

    // 1) Q = (0.125*Wq) @ x^T -> fp16 [B,512,1024]
    gemm_mma_kernel<<<dim3(S / 128, CIN / 128, BATCH), 256, GSMEM>>>(
        p_wq, p_x, nullptr, p_qh, nullptr, S);

    // 2) kv_pre = Wkv @ xp^T   [B,1024,384]
    gemm_mma_kernel<<<dim3(NKVP / 128, 1024 / 128, BATCH), 256, GSMEM>>>(
        p_wq + (size_t)CIN * KDIM, p_xp, p_kvp, nullptr, nullptr, NKVP);

    // 3) sigmoid gates -> K (tiled transpose), V (elementwise)
    kvgate_k_kernel<<<dim3(NKV / 64, HEADS, BATCH), 256>>>(p_kvp, p_kh);
    kvgate_v_kernel<<<dim3(512, BATCH), 256>>>(p_kvp, p_vh);

    // 4) tensor-core attention -> att fp16 [B,S,C]
    attn_mma_kernel<<<dim3(S / TQ, HEADS, BATCH), 256, ATTN2_SMEM>>>(
        p_qh, p_kh, p_vh, pos, p_at);

    // 5) out = Wout @ att^T + bout   [B,512,1024]
    gemm_mma_kernel<<<dim3(S / 128, COUT / 128, BATCH), 256, GSMEM>>>(
        p_wo, p_at, out, nullptr, bout, S);
}